// round 2
// baseline (speedup 1.0000x reference)
#include <cuda_runtime.h>
#include <math.h>
#include <float.h>
#include <stdint.h>

#define NNODE 4096
#define NIN   28
#define NE    131072
#define NEP   (NE + NNODE)
#define NH    8
#define NC    256
#define NHC   2048
#define HID   256
#define NOUT  128
#define SHEAD ((size_t)NNODE * NNODE)

// ---------- scratch layout (floats) ----------
#define OFF_HT   ((size_t)0)
#define OFF_G    (OFF_HT   + (size_t)NNODE * NHC)
#define OFF_HC   (OFF_G    + (size_t)NNODE * 1024)
#define OFF_QKV  (OFF_HC   + (size_t)NNODE * 256)
#define OFF_ATTN (OFF_QKV  + (size_t)NNODE * 768)
#define OFF_HCAT (OFF_ATTN + (size_t)NNODE * 256)
#define OFF_HFUS (OFF_HCAT + (size_t)NNODE * 512)
#define OFF_PROJ (OFF_HFUS + (size_t)NNODE * 256)
#define OFF_BSUM (OFF_PROJ + (size_t)NNODE * 256)
#define OFF_S    (OFF_BSUM + 1024)
#define BIG_SZ   (OFF_S + 4 * SHEAD)

__device__ float g_big[BIG_SZ];
__device__ float g_xp[2][(size_t)NNODE * NHC];
__device__ float g_as[2][NNODE * NH];
__device__ float g_ad[2][NNODE * NH];
__device__ float g_w [2][(size_t)NEP * NH];
__device__ int   g_mx[2][NNODE * NH];
__device__ float g_den[2][NNODE * NH];
__device__ int   g_cnt[2][NNODE];
__device__ int   g_cur[2][NNODE];
__device__ int   g_start[2][NNODE];
__device__ int   g_sorted[2][NE];
__device__ float g_part[2][128];
__device__ float g_mean[2];
__device__ float g_ce[2][NH];

__device__ __forceinline__ int   f2ord(float f){ int i = __float_as_int(f); return i >= 0 ? i : i ^ 0x7fffffff; }
__device__ __forceinline__ float ord2f(int k){ return __int_as_float(k >= 0 ? k : k ^ 0x7fffffff); }
__device__ __forceinline__ float sigmf(float x){ return 1.f / (1.f + expf(-x)); }

// ================= setup =================
__global__ void k_init(){
    int idx = blockIdx.x * 256 + threadIdx.x, stride = gridDim.x * 256;
    int mi = f2ord(-FLT_MAX);
    for (int i = idx; i < NNODE * NH; i += stride){
        g_mx[0][i] = mi; g_mx[1][i] = mi;
        g_den[0][i] = 0.f; g_den[1][i] = 0.f;
    }
    for (int i = idx; i < NNODE; i += stride){
        g_cnt[0][i] = 0; g_cnt[1][i] = 0;
        g_cur[0][i] = 0; g_cur[1][i] = 0;
    }
}

__global__ void k_meanp(const float* __restrict__ ea_t, const float* __restrict__ ea_c){
    __shared__ float s0[256], s1[256];
    float a = 0.f, b = 0.f;
    for (int i = blockIdx.x * 256 + threadIdx.x; i < NE; i += 128 * 256){ a += ea_t[i]; b += ea_c[i]; }
    s0[threadIdx.x] = a; s1[threadIdx.x] = b; __syncthreads();
    for (int s = 128; s; s >>= 1){
        if (threadIdx.x < s){ s0[threadIdx.x] += s0[threadIdx.x+s]; s1[threadIdx.x] += s1[threadIdx.x+s]; }
        __syncthreads();
    }
    if (!threadIdx.x){ g_part[0][blockIdx.x] = s0[0]; g_part[1][blockIdx.x] = s1[0]; }
}

__global__ void k_setup(const float* __restrict__ We_t, const float* __restrict__ ae_t,
                        const float* __restrict__ We_c, const float* __restrict__ ae_c,
                        const float* __restrict__ bih,  const float* __restrict__ bhh){
    __shared__ float sh[256];
    int tid = threadIdx.x;
    for (int g = 0; g < 2; g++){
        sh[tid] = (tid < 128) ? g_part[g][tid] : 0.f;
        __syncthreads();
        for (int s = 128; s; s >>= 1){ if (tid < s) sh[tid] += sh[tid+s]; __syncthreads(); }
        if (!tid) g_mean[g] = sh[0] / (float)NE;
        __syncthreads();
    }
    int wid = tid >> 5, lane = tid & 31;
    for (int c = wid; c < 16; c += 8){
        int g = c >> 3, h = c & 7;
        const float* We = g ? We_c : We_t;
        const float* ae = g ? ae_c : ae_t;
        float s = 0.f;
        for (int i = lane; i < NC; i += 32) s = fmaf(We[h*NC + i], ae[h*NC + i], s);
        for (int o = 16; o; o >>= 1) s += __shfl_down_sync(0xffffffffu, s, o);
        if (!lane) g_ce[g][h] = s;
    }
    for (int j = tid; j < 1024; j += 256) g_big[OFF_BSUM + j] = bih[j] + bhh[j];
}

// ================= GAT =================
__global__ void __launch_bounds__(256) k_xp(const float* __restrict__ x, const float* __restrict__ W, int g){
    __shared__ float xs[NIN];
    int n = blockIdx.y;
    int col = blockIdx.x * 256 + threadIdx.x;
    if (threadIdx.x < NIN) xs[threadIdx.x] = x[n * NIN + threadIdx.x];
    __syncthreads();
    float a = 0.f;
#pragma unroll
    for (int k = 0; k < NIN; k++) a = fmaf(xs[k], W[k * NHC + col], a);
    g_xp[g][(size_t)n * NHC + col] = a;
}

__global__ void k_asd(const float* __restrict__ asrc, const float* __restrict__ adst, int g){
    int n = blockIdx.x, h = threadIdx.x >> 5, lane = threadIdx.x & 31;
    const float* xr = g_xp[g] + (size_t)n * NHC + h * NC;
    float s1 = 0.f, s2 = 0.f;
    for (int c = lane; c < NC; c += 32){
        float v = xr[c];
        s1 = fmaf(v, asrc[h*NC + c], s1);
        s2 = fmaf(v, adst[h*NC + c], s2);
    }
    for (int o = 16; o; o >>= 1){ s1 += __shfl_down_sync(~0u, s1, o); s2 += __shfl_down_sync(~0u, s2, o); }
    if (!lane){ g_as[g][n*NH + h] = s1; g_ad[g][n*NH + h] = s2; }
}

__global__ void k_count(const int* __restrict__ dst, int g){
    int e = blockIdx.x * 256 + threadIdx.x;
    if (e < NE) atomicAdd(&g_cnt[g][dst[e]], 1);
}

__global__ void k_scan(){   // grid=2 (one block per g), 1024 threads
    int g = blockIdx.x, tid = threadIdx.x;
    __shared__ int sh[1024];
    int base = tid * 4;
    int c0 = g_cnt[g][base], c1 = g_cnt[g][base+1], c2 = g_cnt[g][base+2], c3 = g_cnt[g][base+3];
    int s = c0 + c1 + c2 + c3;
    sh[tid] = s; __syncthreads();
    for (int off = 1; off < 1024; off <<= 1){
        int v = (tid >= off) ? sh[tid - off] : 0;
        __syncthreads();
        sh[tid] += v;
        __syncthreads();
    }
    int excl = sh[tid] - s;
    g_start[g][base]   = excl;
    g_start[g][base+1] = excl + c0;
    g_start[g][base+2] = excl + c0 + c1;
    g_start[g][base+3] = excl + c0 + c1 + c2;
}

__global__ void k_scatter(const int* __restrict__ dst, int g){
    int e = blockIdx.x * 256 + threadIdx.x;
    if (e < NE){
        int d = dst[e];
        int pos = g_start[g][d] + atomicAdd(&g_cur[g][d], 1);
        g_sorted[g][pos] = e;
    }
}

__global__ void k_alpha(const int* __restrict__ src, const int* __restrict__ dst,
                        const float* __restrict__ ea, int g){
    int e = blockIdx.x * 256 + threadIdx.x;
    if (e >= NEP) return;
    int s, d; float av;
    if (e < NE){ s = src[e]; d = dst[e]; av = ea[e]; }
    else { s = d = e - NE; av = g_mean[g]; }
#pragma unroll
    for (int h = 0; h < NH; h++){
        float al = g_as[g][s*NH + h] + g_ad[g][d*NH + h] + av * g_ce[g][h];
        al = al > 0.f ? al : 0.2f * al;
        g_w[g][(size_t)e * NH + h] = al;
        atomicMax(&g_mx[g][d*NH + h], f2ord(al));
    }
}

__global__ void k_ex(const int* __restrict__ dst, int g){
    int e = blockIdx.x * 256 + threadIdx.x;
    if (e >= NEP) return;
    int d = (e < NE) ? dst[e] : e - NE;
#pragma unroll
    for (int h = 0; h < NH; h++){
        float al = g_w[g][(size_t)e * NH + h];
        float ex = expf(al - ord2f(g_mx[g][d*NH + h]));
        g_w[g][(size_t)e * NH + h] = ex;
        atomicAdd(&g_den[g][d*NH + h], ex);
    }
}

__global__ void __launch_bounds__(256) k_agg(const int* __restrict__ src, int g,
                                             const float* __restrict__ bias,
                                             float* __restrict__ outp, int concat){
    int n = blockIdx.x, t = threadIdx.x;
    const float* xp = g_xp[g];
    const float* w  = g_w[g];
    float acc[NH];
    {   // self loop (src = dst = n)
        size_t e = (size_t)(NE + n) * NH;
        const float* xr = xp + (size_t)n * NHC + t;
#pragma unroll
        for (int h = 0; h < NH; h++) acc[h] = w[e + h] * xr[h * NC];
    }
    __shared__ int   ssrc[32];
    __shared__ float sw[32][NH];
    int st = g_start[g][n], c = g_cnt[g][n];
    for (int i0 = 0; i0 < c; i0 += 32){
        int m = min(32, c - i0);
        __syncthreads();
        if (t < m) ssrc[t] = src[g_sorted[g][st + i0 + t]];
        {
            int j = t >> 3, h = t & 7;
            if (j < m) sw[j][h] = w[(size_t)g_sorted[g][st + i0 + j] * NH + h];
        }
        __syncthreads();
        for (int jj = 0; jj < m; jj++){
            const float* xr = xp + (size_t)ssrc[jj] * NHC + t;
#pragma unroll
            for (int h = 0; h < NH; h++) acc[h] = fmaf(sw[jj][h], xr[h * NC], acc[h]);
        }
    }
    const float* den = g_den[g] + n * NH;
    if (concat){
#pragma unroll
        for (int h = 0; h < NH; h++)
            outp[(size_t)n * NHC + h * NC + t] = acc[h] / (den[h] + 1e-16f) + bias[h * NC + t];
    } else {
        float s = 0.f;
#pragma unroll
        for (int h = 0; h < NH; h++) s += acc[h] / (den[h] + 1e-16f);
        outp[(size_t)n * NC + t] = s * 0.125f + bias[t];
    }
}

// ================= GEMMs =================
// C[M,N] = act( alpha * A(M,K,lda) * B(N,K,ldb)^T + bias[col] )
__global__ void __launch_bounds__(256) gemm_nt(
    const float* __restrict__ A, int lda, size_t sA,
    const float* __restrict__ B, int ldb, size_t sB,
    float* __restrict__ C, int ldc, size_t sC,
    int K, const float* __restrict__ bias, float alpha, int act)
{
    A += (size_t)blockIdx.z * sA; B += (size_t)blockIdx.z * sB; C += (size_t)blockIdx.z * sC;
    int row0 = blockIdx.y * 64, col0 = blockIdx.x * 64;
    __shared__ float As[16][68], Bs[16][68];
    int tid = threadIdx.x;
    int lr = tid >> 2, lk = (tid & 3) * 4;
    const float* Ag = A + (size_t)(row0 + lr) * lda + lk;
    const float* Bg = B + (size_t)(col0 + lr) * ldb + lk;
    int tx = tid & 15, ty = tid >> 4;
    float acc[4][4] = {};
    for (int k0 = 0; k0 < K; k0 += 16){
        float4 av = *(const float4*)(Ag + k0);
        float4 bv = *(const float4*)(Bg + k0);
        As[lk+0][lr] = av.x; As[lk+1][lr] = av.y; As[lk+2][lr] = av.z; As[lk+3][lr] = av.w;
        Bs[lk+0][lr] = bv.x; Bs[lk+1][lr] = bv.y; Bs[lk+2][lr] = bv.z; Bs[lk+3][lr] = bv.w;
        __syncthreads();
#pragma unroll
        for (int kk = 0; kk < 16; kk++){
            float a[4], b[4];
            *(float4*)a = *(const float4*)&As[kk][ty*4];
            *(float4*)b = *(const float4*)&Bs[kk][tx*4];
#pragma unroll
            for (int i = 0; i < 4; i++)
#pragma unroll
                for (int j = 0; j < 4; j++) acc[i][j] = fmaf(a[i], b[j], acc[i][j]);
        }
        __syncthreads();
    }
#pragma unroll
    for (int i = 0; i < 4; i++){
        int r = row0 + ty*4 + i;
#pragma unroll
        for (int j = 0; j < 4; j++){
            int cc = col0 + tx*4 + j;
            float v = acc[i][j] * alpha;
            if (bias) v += bias[cc];
            if (act == 1) v = fmaxf(v, 0.f);
            C[(size_t)r * ldc + cc] = v;
        }
    }
}

// C[M,N] = A(M,K,lda) * B(K,N,ldb)
__global__ void __launch_bounds__(256) gemm_nn(
    const float* __restrict__ A, int lda, size_t sA,
    const float* __restrict__ B, int ldb, size_t sB,
    float* __restrict__ C, int ldc, size_t sC, int K)
{
    A += (size_t)blockIdx.z * sA; B += (size_t)blockIdx.z * sB; C += (size_t)blockIdx.z * sC;
    int row0 = blockIdx.y * 64, col0 = blockIdx.x * 64;
    __shared__ float As[16][68], Bs[16][68];
    int tid = threadIdx.x;
    int lr = tid >> 2, lk = (tid & 3) * 4;
    const float* Ag = A + (size_t)(row0 + lr) * lda + lk;
    int bn = tid & 63, bk = tid >> 6;
    const float* Bg = B + (size_t)bk * ldb + col0 + bn;
    int tx = tid & 15, ty = tid >> 4;
    float acc[4][4] = {};
    for (int k0 = 0; k0 < K; k0 += 16){
        float4 av = *(const float4*)(Ag + k0);
        As[lk+0][lr] = av.x; As[lk+1][lr] = av.y; As[lk+2][lr] = av.z; As[lk+3][lr] = av.w;
#pragma unroll
        for (int j = 0; j < 4; j++)
            Bs[bk + 4*j][bn] = Bg[(size_t)(k0 + 4*j) * ldb];
        __syncthreads();
#pragma unroll
        for (int kk = 0; kk < 16; kk++){
            float a[4], b[4];
            *(float4*)a = *(const float4*)&As[kk][ty*4];
            *(float4*)b = *(const float4*)&Bs[kk][tx*4];
#pragma unroll
            for (int i = 0; i < 4; i++)
#pragma unroll
                for (int j = 0; j < 4; j++) acc[i][j] = fmaf(a[i], b[j], acc[i][j]);
        }
        __syncthreads();
    }
#pragma unroll
    for (int i = 0; i < 4; i++){
        int r = row0 + ty*4 + i;
#pragma unroll
        for (int j = 0; j < 4; j++)
            C[(size_t)r * ldc + col0 + tx*4 + j] = acc[i][j];
    }
}

// ================= pointwise =================
__global__ void k_lstm(const float* __restrict__ G, float* __restrict__ ht_out, float* __restrict__ hcat){
    int idx = blockIdx.x * 256 + threadIdx.x;
    int n = idx >> 8, j = idx & 255;
    const float* gr = G + (size_t)n * 1024;
    float ig = gr[j], gg = gr[512 + j], og = gr[768 + j];
    float cc = sigmf(ig) * tanhf(gg);
    float hv = sigmf(og) * tanhf(cc);
    ht_out[idx] = hv;
    hcat[(size_t)n * 512 + j] = hv;
}

__global__ void __launch_bounds__(256) k_softmax(float* __restrict__ S){
    int row = blockIdx.x, head = blockIdx.y, t = threadIdx.x;
    float* p = S + (size_t)head * SHEAD + (size_t)row * NNODE;
    float v[16];
    float m = -FLT_MAX;
#pragma unroll
    for (int i = 0; i < 16; i++){ v[i] = p[i*256 + t]; m = fmaxf(m, v[i]); }
    __shared__ float sh[256];
    sh[t] = m; __syncthreads();
    for (int s = 128; s; s >>= 1){ if (t < s) sh[t] = fmaxf(sh[t], sh[t+s]); __syncthreads(); }
    m = sh[0]; __syncthreads();
    float sum = 0.f;
#pragma unroll
    for (int i = 0; i < 16; i++){ v[i] = expf(v[i] - m); sum += v[i]; }
    sh[t] = sum; __syncthreads();
    for (int s = 128; s; s >>= 1){ if (t < s) sh[t] += sh[t+s]; __syncthreads(); }
    float inv = 1.f / sh[0];
#pragma unroll
    for (int i = 0; i < 16; i++) p[i*256 + t] = v[i] * inv;
}

__global__ void k_copyhc(const float* __restrict__ proj, float* __restrict__ hc_out, float* __restrict__ hcat){
    int idx = blockIdx.x * 256 + threadIdx.x;
    int n = idx >> 8, j = idx & 255;
    float v = proj[idx];
    hc_out[idx] = v;
    hcat[(size_t)n * 512 + 256 + j] = v;
}

// ================= launch =================
extern "C" void kernel_launch(void* const* d_in, const int* in_sizes, int n_in,
                              void* d_out, int out_size) {
    const float* x     = (const float*)d_in[0];
    const int*   ei_t  = (const int*)d_in[1];
    const int*   ei_c  = (const int*)d_in[2];
    const float* ea_t  = (const float*)d_in[3];
    const float* ea_c  = (const float*)d_in[4];
    const float* W_t   = (const float*)d_in[5];
    const float* asrc_t= (const float*)d_in[6];
    const float* adst_t= (const float*)d_in[7];
    const float* We_t  = (const float*)d_in[8];
    const float* ae_t  = (const float*)d_in[9];
    const float* b_t   = (const float*)d_in[10];
    const float* W_c   = (const float*)d_in[11];
    const float* asrc_c= (const float*)d_in[12];
    const float* adst_c= (const float*)d_in[13];
    const float* We_c  = (const float*)d_in[14];
    const float* ae_c  = (const float*)d_in[15];
    const float* b_c   = (const float*)d_in[16];
    const float* lstm_Wih = (const float*)d_in[17];
    // d_in[18] lstm_Whh unused (h0 = 0)
    const float* lstm_bih = (const float*)d_in[19];
    const float* lstm_bhh = (const float*)d_in[20];
    const float* mha_in_w  = (const float*)d_in[21];
    const float* mha_in_b  = (const float*)d_in[22];
    const float* mha_out_w = (const float*)d_in[23];
    const float* mha_out_b = (const float*)d_in[24];
    const float* fus_w = (const float*)d_in[25];
    const float* fus_b = (const float*)d_in[26];
    const float* out_w = (const float*)d_in[27];
    const float* out_b = (const float*)d_in[28];

    float* big = nullptr;
    cudaGetSymbolAddress((void**)&big, g_big);

    float* out_main = (float*)d_out;                        // (4096,128)
    float* out_ht   = out_main + (size_t)NNODE * NOUT;      // (4096,256)
    float* out_hc   = out_ht   + (size_t)NNODE * HID;       // (4096,256)

    const int* src_t = ei_t;           const int* dst_t = ei_t + NE;
    const int* src_c = ei_c;           const int* dst_c = ei_c + NE;

    int nepb = (NEP + 255) / 256;
    int neb  = (NE + 255) / 256;

    k_init<<<64, 256>>>();
    k_meanp<<<128, 256>>>(ea_t, ea_c);
    k_setup<<<1, 256>>>(We_t, ae_t, We_c, ae_c, lstm_bih, lstm_bhh);

    // ---- GATs ----
    k_xp<<<dim3(8, NNODE), 256>>>(x, W_t, 0);
    k_xp<<<dim3(8, NNODE), 256>>>(x, W_c, 1);
    k_asd<<<NNODE, 256>>>(asrc_t, adst_t, 0);
    k_asd<<<NNODE, 256>>>(asrc_c, adst_c, 1);
    k_count<<<neb, 256>>>(dst_t, 0);
    k_count<<<neb, 256>>>(dst_c, 1);
    k_scan<<<2, 1024>>>();
    k_scatter<<<neb, 256>>>(dst_t, 0);
    k_scatter<<<neb, 256>>>(dst_c, 1);
    k_alpha<<<nepb, 256>>>(src_t, dst_t, ea_t, 0);
    k_alpha<<<nepb, 256>>>(src_c, dst_c, ea_c, 1);
    k_ex<<<nepb, 256>>>(dst_t, 0);
    k_ex<<<nepb, 256>>>(dst_c, 1);
    k_agg<<<NNODE, 256>>>(src_t, 0, b_t, big + OFF_HT, 1);
    k_agg<<<NNODE, 256>>>(src_c, 1, b_c, big + OFF_HC, 0);

    // ---- temporal branch: LSTM ----
    gemm_nt<<<dim3(1024/64, NNODE/64, 1), 256>>>(
        big + OFF_HT, NHC, 0, lstm_Wih, NHC, 0, big + OFF_G, 1024, 0,
        NHC, big + OFF_BSUM, 1.f, 0);
    k_lstm<<<NNODE, 256>>>(big + OFF_G, out_ht, big + OFF_HCAT);

    // ---- causal branch: MHA ----
    gemm_nt<<<dim3(768/64, NNODE/64, 1), 256>>>(
        big + OFF_HC, 256, 0, mha_in_w, 256, 0, big + OFF_QKV, 768, 0,
        256, mha_in_b, 1.f, 0);
    gemm_nt<<<dim3(NNODE/64, NNODE/64, 4), 256>>>(
        big + OFF_QKV, 768, 64, big + OFF_QKV + 256, 768, 64,
        big + OFF_S, NNODE, SHEAD, 64, nullptr, 0.125f, 0);
    k_softmax<<<dim3(NNODE, 4), 256>>>(big + OFF_S);
    gemm_nn<<<dim3(1, NNODE/64, 4), 256>>>(
        big + OFF_S, NNODE, SHEAD, big + OFF_QKV + 512, 768, 64,
        big + OFF_ATTN, 256, 64, NNODE);
    gemm_nt<<<dim3(256/64, NNODE/64, 1), 256>>>(
        big + OFF_ATTN, 256, 0, mha_out_w, 256, 0, big + OFF_PROJ, 256, 0,
        256, mha_out_b, 1.f, 0);
    k_copyhc<<<NNODE, 256>>>(big + OFF_PROJ, out_hc, big + OFF_HCAT);

    // ---- fusion head ----
    gemm_nt<<<dim3(256/64, NNODE/64, 1), 256>>>(
        big + OFF_HCAT, 512, 0, fus_w, 512, 0, big + OFF_HFUS, 256, 0,
        512, fus_b, 1.f, 1);
    gemm_nt<<<dim3(128/64, NNODE/64, 1), 256>>>(
        big + OFF_HFUS, 256, 0, out_w, 256, 0, out_main, NOUT, 0,
        256, out_b, 1.f, 0);
}

// round 4
// speedup vs baseline: 1.6650x; 1.6650x over previous
#include <cuda_runtime.h>
#include <cuda_bf16.h>
#include <math.h>
#include <float.h>
#include <stdint.h>

#define NNODE 4096
#define NIN   28
#define NE    131072
#define NEP   (NE + NNODE)
#define NH    8
#define NC    256
#define NHC   2048
#define HID   256
#define NOUT  128
#define SHEAD ((size_t)NNODE * NNODE)

// ---------------- fp32 scratch ----------------
#define OFF_G    ((size_t)0)
#define OFF_BSUM (OFF_G + (size_t)NNODE * 1024)
#define OFF_S    (OFF_BSUM + 1024)
#define BIG_SZ   (OFF_S + 4 * SHEAD)
__device__ float g_big[BIG_SZ];

__device__ float g_xp[2][(size_t)NNODE * NHC];
__device__ float g_as[2][NNODE * NH];
__device__ float g_ad[2][NNODE * NH];
__device__ float g_w [2][(size_t)NEP * NH];
__device__ int   g_mx[2][NNODE * NH];
__device__ float g_den[2][NNODE * NH];
__device__ int   g_cnt[2][NNODE];
__device__ int   g_cur[2][NNODE];
__device__ int   g_start[2][NNODE];
__device__ int   g_sorted[2][NE];
__device__ float g_part[2][128];
__device__ float g_mean[2];
__device__ float g_ce[2][NH];

// ---------------- bf16 hi/lo tensors ----------------
__device__ __nv_bfloat16 g_hth[(size_t)NNODE * NHC], g_htl[(size_t)NNODE * NHC];
__device__ __nv_bfloat16 g_hch[(size_t)NNODE * 256], g_hcl[(size_t)NNODE * 256];
__device__ __nv_bfloat16 g_qkvh[(size_t)NNODE * 768], g_qkvl[(size_t)NNODE * 768];
__device__ __nv_bfloat16 g_vth[(size_t)4 * 64 * NNODE], g_vtl[(size_t)4 * 64 * NNODE];
__device__ __nv_bfloat16 g_ph[4 * SHEAD], g_pl[4 * SHEAD];
__device__ __nv_bfloat16 g_attnh[(size_t)NNODE * 256], g_attnl[(size_t)NNODE * 256];
__device__ __nv_bfloat16 g_hcath[(size_t)NNODE * 512], g_hcatl[(size_t)NNODE * 512];
__device__ __nv_bfloat16 g_hfush[(size_t)NNODE * 256], g_hfusl[(size_t)NNODE * 256];
// weights
__device__ __nv_bfloat16 g_wihh[1024 * 2048], g_wihl[1024 * 2048];
__device__ __nv_bfloat16 g_inwh[768 * 256],   g_inwl[768 * 256];
__device__ __nv_bfloat16 g_mowh[256 * 256],   g_mowl[256 * 256];
__device__ __nv_bfloat16 g_fuwh[256 * 512],   g_fuwl[256 * 512];
__device__ __nv_bfloat16 g_owh[128 * 256],    g_owl[128 * 256];

// ---------------- helpers ----------------
__device__ __forceinline__ int   f2ord(float f){ int i = __float_as_int(f); return i >= 0 ? i : i ^ 0x7fffffff; }
__device__ __forceinline__ float ord2f(int k){ return __int_as_float(k >= 0 ? k : k ^ 0x7fffffff); }
__device__ __forceinline__ float sigmf(float x){ return 1.f / (1.f + expf(-x)); }
__device__ __forceinline__ void f2hl(float v, __nv_bfloat16* H, __nv_bfloat16* L, size_t i){
    __nv_bfloat16 h = __float2bfloat16(v);
    H[i] = h; L[i] = __float2bfloat16(v - __bfloat162float(h));
}
__device__ __forceinline__ uint32_t smem_u32(const void* p){
    uint32_t a;
    asm("{ .reg .u64 t; cvta.to.shared.u64 t, %1; cvt.u32.u64 %0, t; }" : "=r"(a) : "l"(p));
    return a;
}
__device__ __forceinline__ void ldm_x4(uint32_t* r, uint32_t addr){
    asm volatile("ldmatrix.sync.aligned.m8n8.x4.shared.b16 {%0,%1,%2,%3}, [%4];"
        : "=r"(r[0]), "=r"(r[1]), "=r"(r[2]), "=r"(r[3]) : "r"(addr));
}
__device__ __forceinline__ void ldm_x2(uint32_t* r, uint32_t addr){
    asm volatile("ldmatrix.sync.aligned.m8n8.x2.shared.b16 {%0,%1}, [%2];"
        : "=r"(r[0]), "=r"(r[1]) : "r"(addr));
}
__device__ __forceinline__ void mma_bf16(float* c, const uint32_t* a, const uint32_t* b){
    asm volatile("mma.sync.aligned.m16n8k16.row.col.f32.bf16.bf16.f32 "
        "{%0,%1,%2,%3}, {%4,%5,%6,%7}, {%8,%9}, {%0,%1,%2,%3};"
        : "+f"(c[0]), "+f"(c[1]), "+f"(c[2]), "+f"(c[3])
        : "r"(a[0]), "r"(a[1]), "r"(a[2]), "r"(a[3]), "r"(b[0]), "r"(b[1]));
}

// ================= setup =================
__global__ void k_init(){
    int idx = blockIdx.x * 256 + threadIdx.x, stride = gridDim.x * 256;
    int mi = f2ord(-FLT_MAX);
    for (int i = idx; i < NNODE * NH; i += stride){
        g_mx[0][i] = mi; g_mx[1][i] = mi;
        g_den[0][i] = 0.f; g_den[1][i] = 0.f;
    }
    for (int i = idx; i < NNODE; i += stride){
        g_cnt[0][i] = 0; g_cnt[1][i] = 0;
        g_cur[0][i] = 0; g_cur[1][i] = 0;
    }
}

__global__ void k_meanp(const float* __restrict__ ea_t, const float* __restrict__ ea_c){
    __shared__ float s0[256], s1[256];
    float a = 0.f, b = 0.f;
    for (int i = blockIdx.x * 256 + threadIdx.x; i < NE; i += 128 * 256){ a += ea_t[i]; b += ea_c[i]; }
    s0[threadIdx.x] = a; s1[threadIdx.x] = b; __syncthreads();
    for (int s = 128; s; s >>= 1){
        if (threadIdx.x < s){ s0[threadIdx.x] += s0[threadIdx.x+s]; s1[threadIdx.x] += s1[threadIdx.x+s]; }
        __syncthreads();
    }
    if (!threadIdx.x){ g_part[0][blockIdx.x] = s0[0]; g_part[1][blockIdx.x] = s1[0]; }
}

__global__ void k_setup(const float* __restrict__ We_t, const float* __restrict__ ae_t,
                        const float* __restrict__ We_c, const float* __restrict__ ae_c,
                        const float* __restrict__ bih,  const float* __restrict__ bhh){
    __shared__ float sh[256];
    int tid = threadIdx.x;
    for (int g = 0; g < 2; g++){
        sh[tid] = (tid < 128) ? g_part[g][tid] : 0.f;
        __syncthreads();
        for (int s = 128; s; s >>= 1){ if (tid < s) sh[tid] += sh[tid+s]; __syncthreads(); }
        if (!tid) g_mean[g] = sh[0] / (float)NE;
        __syncthreads();
    }
    int wid = tid >> 5, lane = tid & 31;
    for (int c = wid; c < 16; c += 8){
        int g = c >> 3, h = c & 7;
        const float* We = g ? We_c : We_t;
        const float* ae = g ? ae_c : ae_t;
        float s = 0.f;
        for (int i = lane; i < NC; i += 32) s = fmaf(We[h*NC + i], ae[h*NC + i], s);
        for (int o = 16; o; o >>= 1) s += __shfl_down_sync(0xffffffffu, s, o);
        if (!lane) g_ce[g][h] = s;
    }
    for (int j = tid; j < 1024; j += 256) g_big[OFF_BSUM + j] = bih[j] + bhh[j];
}

__global__ void k_conv(const float* __restrict__ in, __nv_bfloat16* __restrict__ H,
                       __nv_bfloat16* __restrict__ L, int n){
    int i = blockIdx.x * 256 + threadIdx.x;
    if (i < n) f2hl(in[i], H, L, i);
}

// ================= GAT =================
__global__ void __launch_bounds__(256) k_xp2(const float* __restrict__ x, const float* __restrict__ W, int g){
    __shared__ float Ws[NIN][256];
    __shared__ float xs[16][32];
    int tid = threadIdx.x;
    int col = blockIdx.x * 256 + tid;
    int n0 = blockIdx.y * 16;
#pragma unroll
    for (int k = 0; k < NIN; k++) Ws[k][tid] = W[k * NHC + col];
    for (int i = tid; i < 16 * NIN; i += 256){ int n = i / NIN, k = i % NIN; xs[n][k] = x[(size_t)(n0 + n) * NIN + k]; }
    for (int i = tid; i < 16 * 4; i += 256) xs[i >> 2][NIN + (i & 3)] = 0.f;
    __syncthreads();
    float acc[16] = {};
    for (int k0 = 0; k0 < 28; k0 += 4){
        float w0 = Ws[k0][tid], w1 = Ws[k0+1][tid], w2 = Ws[k0+2][tid], w3 = Ws[k0+3][tid];
#pragma unroll
        for (int n = 0; n < 16; n++){
            float4 xv = *(const float4*)&xs[n][k0];
            acc[n] = fmaf(xv.x, w0, fmaf(xv.y, w1, fmaf(xv.z, w2, fmaf(xv.w, w3, acc[n]))));
        }
    }
#pragma unroll
    for (int n = 0; n < 16; n++) g_xp[g][(size_t)(n0 + n) * NHC + col] = acc[n];
}

__global__ void k_asd(const float* __restrict__ asrc, const float* __restrict__ adst, int g){
    int n = blockIdx.x, h = threadIdx.x >> 5, lane = threadIdx.x & 31;
    const float* xr = g_xp[g] + (size_t)n * NHC + h * NC;
    float s1 = 0.f, s2 = 0.f;
    for (int c = lane; c < NC; c += 32){
        float v = xr[c];
        s1 = fmaf(v, asrc[h*NC + c], s1);
        s2 = fmaf(v, adst[h*NC + c], s2);
    }
    for (int o = 16; o; o >>= 1){ s1 += __shfl_down_sync(~0u, s1, o); s2 += __shfl_down_sync(~0u, s2, o); }
    if (!lane){ g_as[g][n*NH + h] = s1; g_ad[g][n*NH + h] = s2; }
}

__global__ void k_count(const int* __restrict__ dst, int g){
    int e = blockIdx.x * 256 + threadIdx.x;
    if (e < NE) atomicAdd(&g_cnt[g][dst[e]], 1);
}

__global__ void k_scan(){
    int g = blockIdx.x, tid = threadIdx.x;
    __shared__ int sh[1024];
    int base = tid * 4;
    int c0 = g_cnt[g][base], c1 = g_cnt[g][base+1], c2 = g_cnt[g][base+2], c3 = g_cnt[g][base+3];
    int s = c0 + c1 + c2 + c3;
    sh[tid] = s; __syncthreads();
    for (int off = 1; off < 1024; off <<= 1){
        int v = (tid >= off) ? sh[tid - off] : 0;
        __syncthreads();
        sh[tid] += v;
        __syncthreads();
    }
    int excl = sh[tid] - s;
    g_start[g][base]   = excl;
    g_start[g][base+1] = excl + c0;
    g_start[g][base+2] = excl + c0 + c1;
    g_start[g][base+3] = excl + c0 + c1 + c2;
}

__global__ void k_scatter(const int* __restrict__ dst, int g){
    int e = blockIdx.x * 256 + threadIdx.x;
    if (e < NE){
        int d = dst[e];
        int pos = g_start[g][d] + atomicAdd(&g_cur[g][d], 1);
        g_sorted[g][pos] = e;
    }
}

__global__ void k_alpha(const int* __restrict__ src, const int* __restrict__ dst,
                        const float* __restrict__ ea, int g){
    int e = blockIdx.x * 256 + threadIdx.x;
    if (e >= NEP) return;
    int s, d; float av;
    if (e < NE){ s = src[e]; d = dst[e]; av = ea[e]; }
    else { s = d = e - NE; av = g_mean[g]; }
#pragma unroll
    for (int h = 0; h < NH; h++){
        float al = g_as[g][s*NH + h] + g_ad[g][d*NH + h] + av * g_ce[g][h];
        al = al > 0.f ? al : 0.2f * al;
        g_w[g][(size_t)e * NH + h] = al;
        atomicMax(&g_mx[g][d*NH + h], f2ord(al));
    }
}

__global__ void k_ex(const int* __restrict__ dst, int g){
    int e = blockIdx.x * 256 + threadIdx.x;
    if (e >= NEP) return;
    int d = (e < NE) ? dst[e] : e - NE;
#pragma unroll
    for (int h = 0; h < NH; h++){
        float al = g_w[g][(size_t)e * NH + h];
        float ex = expf(al - ord2f(g_mx[g][d*NH + h]));
        g_w[g][(size_t)e * NH + h] = ex;
        atomicAdd(&g_den[g][d*NH + h], ex);
    }
}

__global__ void __launch_bounds__(256) k_agg(const int* __restrict__ src, int g,
                                             const float* __restrict__ bias,
                                             __nv_bfloat16* __restrict__ Oh,
                                             __nv_bfloat16* __restrict__ Ol, int concat){
    int n = blockIdx.x, t = threadIdx.x;
    const float* xp = g_xp[g];
    const float* w  = g_w[g];
    float acc[NH];
    {
        size_t e = (size_t)(NE + n) * NH;
        const float* xr = xp + (size_t)n * NHC + t;
#pragma unroll
        for (int h = 0; h < NH; h++) acc[h] = w[e + h] * xr[h * NC];
    }
    __shared__ int   ssrc[32];
    __shared__ float sw[32][NH];
    int st = g_start[g][n], c = g_cnt[g][n];
    for (int i0 = 0; i0 < c; i0 += 32){
        int m = min(32, c - i0);
        __syncthreads();
        if (t < m) ssrc[t] = src[g_sorted[g][st + i0 + t]];
        {
            int j = t >> 3, h = t & 7;
            if (j < m) sw[j][h] = w[(size_t)g_sorted[g][st + i0 + j] * NH + h];
        }
        __syncthreads();
        for (int jj = 0; jj < m; jj++){
            const float* xr = xp + (size_t)ssrc[jj] * NHC + t;
#pragma unroll
            for (int h = 0; h < NH; h++) acc[h] = fmaf(sw[jj][h], xr[h * NC], acc[h]);
        }
    }
    const float* den = g_den[g] + n * NH;
    if (concat){
#pragma unroll
        for (int h = 0; h < NH; h++){
            float v = acc[h] / (den[h] + 1e-16f) + bias[h * NC + t];
            f2hl(v, Oh, Ol, (size_t)n * NHC + h * NC + t);
        }
    } else {
        float s = 0.f;
#pragma unroll
        for (int h = 0; h < NH; h++) s += acc[h] / (den[h] + 1e-16f);
        f2hl(s * 0.125f + bias[t], Oh, Ol, (size_t)n * NC + t);
    }
}

// ================= HMMA bf16x3 GEMM =================
// C[M,N] = act(alpha * A·B^T + bias). A=[M,K] hi/lo, B=[N,K] hi/lo, K-major.
// CTA tile 128x64, BK=64, 8 warps (4 x 2), warp tile 32x32.
__global__ void __launch_bounds__(256) mma_gemm(
    const __nv_bfloat16* __restrict__ Ah, const __nv_bfloat16* __restrict__ Al, int lda, unsigned long long sA,
    const __nv_bfloat16* __restrict__ Bh, const __nv_bfloat16* __restrict__ Bl, int ldb, unsigned long long sB,
    float* __restrict__ C, int ldc, unsigned long long sC,
    __nv_bfloat16* __restrict__ Ch, __nv_bfloat16* __restrict__ Cl, int ldc2, unsigned long long sC2, int c2off,
    int K, const float* __restrict__ bias, float alpha, int act)
{
    extern __shared__ char sm[];   // [Ah 16K][Al 16K][Bh 8K][Bl 8K] = 48K
    int tid = threadIdx.x, lane = tid & 31, wid = tid >> 5;
    int wm = wid & 3, wn = wid >> 2;
    int z = blockIdx.z;
    Ah += (size_t)z * sA; Al += (size_t)z * sA;
    Bh += (size_t)z * sB; Bl += (size_t)z * sB;
    if (C) C += (size_t)z * sC;
    if (Ch){ Ch += (size_t)z * sC2; Cl += (size_t)z * sC2; }
    int row0 = blockIdx.y * 128, col0 = blockIdx.x * 64;
    Ah += (size_t)row0 * lda; Al += (size_t)row0 * lda;
    Bh += (size_t)col0 * ldb; Bl += (size_t)col0 * ldb;

    uint32_t sbase = smem_u32(sm);
    float acc[2][4][4] = {};
    int nkb = K >> 6;

    for (int kb = 0; kb < nkb; kb++){
        int k0 = kb << 6;
#pragma unroll
        for (int it = 0; it < 4; it++){
            int i = tid + it * 256;            // 1024 (row,seg) pairs for A
            int row = i >> 3, seg = i & 7;
            size_t goff = (size_t)row * lda + k0 + seg * 8;
            uint32_t so = row * 128 + ((seg ^ (row & 7)) << 4);
            *(uint4*)(sm + so)          = *(const uint4*)(Ah + goff);
            *(uint4*)(sm + 16384 + so)  = *(const uint4*)(Al + goff);
        }
#pragma unroll
        for (int it = 0; it < 2; it++){
            int i = tid + it * 256;            // 512 pairs for B
            int row = i >> 3, seg = i & 7;
            size_t goff = (size_t)row * ldb + k0 + seg * 8;
            uint32_t so = row * 128 + ((seg ^ (row & 7)) << 4);
            *(uint4*)(sm + 32768 + so)  = *(const uint4*)(Bh + goff);
            *(uint4*)(sm + 40960 + so)  = *(const uint4*)(Bl + goff);
        }
        __syncthreads();
#pragma unroll
        for (int ks = 0; ks < 4; ks++){
            uint32_t a_h[2][4], a_l[2][4], b_h[4][2], b_l[4][2];
#pragma unroll
            for (int mt = 0; mt < 2; mt++){
                int r = wm * 32 + mt * 16 + (lane & 15);
                int seg = ks * 2 + (lane >> 4);
                uint32_t ad = sbase + r * 128 + ((seg ^ (r & 7)) << 4);
                ldm_x4(a_h[mt], ad);
                ldm_x4(a_l[mt], ad + 16384);
            }
#pragma unroll
            for (int nt = 0; nt < 4; nt++){
                int r = wn * 32 + nt * 8 + (lane & 7);
                int seg = ks * 2 + ((lane >> 3) & 1);
                uint32_t bd = sbase + 32768 + r * 128 + ((seg ^ (r & 7)) << 4);
                ldm_x2(b_h[nt], bd);
                ldm_x2(b_l[nt], bd + 8192);
            }
#pragma unroll
            for (int mt = 0; mt < 2; mt++)
#pragma unroll
                for (int nt = 0; nt < 4; nt++){
                    mma_bf16(acc[mt][nt], a_h[mt], b_h[nt]);
                    mma_bf16(acc[mt][nt], a_h[mt], b_l[nt]);
                    mma_bf16(acc[mt][nt], a_l[mt], b_h[nt]);
                }
        }
        __syncthreads();
    }

    // epilogue
#pragma unroll
    for (int mt = 0; mt < 2; mt++){
#pragma unroll
        for (int nt = 0; nt < 4; nt++){
            int r0 = row0 + wm * 32 + mt * 16 + (lane >> 2);
            int c0 = col0 + wn * 32 + nt * 8 + ((lane & 3) << 1);
#pragma unroll
            for (int q = 0; q < 4; q++){
                int r = r0 + (q >> 1) * 8;
                int cc = c0 + (q & 1);
                float v = acc[mt][nt][q] * alpha;
                if (bias) v += bias[cc];
                if (act == 1) v = fmaxf(v, 0.f);
                if (C) C[(size_t)r * ldc + cc] = v;
                if (Ch) f2hl(v, Ch, Cl, (size_t)r * ldc2 + c2off + cc);
            }
        }
    }
}

// ================= pointwise =================
__global__ void k_lstm(const float* __restrict__ G, float* __restrict__ ht_out,
                       __nv_bfloat16* __restrict__ Hh, __nv_bfloat16* __restrict__ Hl){
    int idx = blockIdx.x * 256 + threadIdx.x;
    int n = idx >> 8, j = idx & 255;
    const float* gr = G + (size_t)n * 1024;
    float ig = gr[j], gg = gr[512 + j], og = gr[768 + j];
    float cc = sigmf(ig) * tanhf(gg);
    float hv = sigmf(og) * tanhf(cc);
    ht_out[idx] = hv;
    f2hl(hv, Hh, Hl, (size_t)n * 512 + j);
}

__global__ void __launch_bounds__(256) k_softmax(const float* __restrict__ S,
                                                 __nv_bfloat16* __restrict__ Ph,
                                                 __nv_bfloat16* __restrict__ Pl){
    int row = blockIdx.x, head = blockIdx.y, t = threadIdx.x;
    const float* p = S + (size_t)head * SHEAD + (size_t)row * NNODE;
    size_t ob = (size_t)head * SHEAD + (size_t)row * NNODE;
    float v[16];
    float m = -FLT_MAX;
#pragma unroll
    for (int i = 0; i < 16; i++){ v[i] = p[i*256 + t]; m = fmaxf(m, v[i]); }
    __shared__ float sh[256];
    sh[t] = m; __syncthreads();
    for (int s = 128; s; s >>= 1){ if (t < s) sh[t] = fmaxf(sh[t], sh[t+s]); __syncthreads(); }
    m = sh[0]; __syncthreads();
    float sum = 0.f;
#pragma unroll
    for (int i = 0; i < 16; i++){ v[i] = expf(v[i] - m); sum += v[i]; }
    sh[t] = sum; __syncthreads();
    for (int s = 128; s; s >>= 1){ if (t < s) sh[t] += sh[t+s]; __syncthreads(); }
    float inv = 1.f / sh[0];
#pragma unroll
    for (int i = 0; i < 16; i++) f2hl(v[i] * inv, Ph, Pl, ob + i*256 + t);
}

__global__ void k_vt(const __nv_bfloat16* __restrict__ qh, const __nv_bfloat16* __restrict__ ql,
                     __nv_bfloat16* __restrict__ vh, __nv_bfloat16* __restrict__ vl){
    int idx = blockIdx.x * 256 + threadIdx.x;
    int hd = idx >> 12, n = idx & 4095;
    size_t s = (size_t)n * 768 + 512 + hd;
    vh[idx] = qh[s]; vl[idx] = ql[s];
}

// ================= launch =================
#define SYMADDR(p, s) do { void* _t; cudaGetSymbolAddress(&_t, s); p = (decltype(p))_t; } while(0)

extern "C" void kernel_launch(void* const* d_in, const int* in_sizes, int n_in,
                              void* d_out, int out_size) {
    const float* x     = (const float*)d_in[0];
    const int*   ei_t  = (const int*)d_in[1];
    const int*   ei_c  = (const int*)d_in[2];
    const float* ea_t  = (const float*)d_in[3];
    const float* ea_c  = (const float*)d_in[4];
    const float* W_t   = (const float*)d_in[5];
    const float* asrc_t= (const float*)d_in[6];
    const float* adst_t= (const float*)d_in[7];
    const float* We_t  = (const float*)d_in[8];
    const float* ae_t  = (const float*)d_in[9];
    const float* b_t   = (const float*)d_in[10];
    const float* W_c   = (const float*)d_in[11];
    const float* asrc_c= (const float*)d_in[12];
    const float* adst_c= (const float*)d_in[13];
    const float* We_c  = (const float*)d_in[14];
    const float* ae_c  = (const float*)d_in[15];
    const float* b_c   = (const float*)d_in[16];
    const float* lstm_Wih = (const float*)d_in[17];
    const float* lstm_bih = (const float*)d_in[19];
    const float* lstm_bhh = (const float*)d_in[20];
    const float* mha_in_w  = (const float*)d_in[21];
    const float* mha_in_b  = (const float*)d_in[22];
    const float* mha_out_w = (const float*)d_in[23];
    const float* mha_out_b = (const float*)d_in[24];
    const float* fus_w = (const float*)d_in[25];
    const float* fus_b = (const float*)d_in[26];
    const float* out_w = (const float*)d_in[27];
    const float* out_b = (const float*)d_in[28];

    float* big; SYMADDR(big, g_big);
    __nv_bfloat16 *hth, *htl, *hch, *hcl, *qkvh, *qkvl, *vth, *vtl, *ph, *pl;
    __nv_bfloat16 *attnh, *attnl, *hcath, *hcatl, *hfush, *hfusl;
    __nv_bfloat16 *wihh, *wihl, *inwh, *inwl, *mowh, *mowl, *fuwh, *fuwl, *owh, *owl;
    SYMADDR(hth, g_hth); SYMADDR(htl, g_htl); SYMADDR(hch, g_hch); SYMADDR(hcl, g_hcl);
    SYMADDR(qkvh, g_qkvh); SYMADDR(qkvl, g_qkvl); SYMADDR(vth, g_vth); SYMADDR(vtl, g_vtl);
    SYMADDR(ph, g_ph); SYMADDR(pl, g_pl);
    SYMADDR(attnh, g_attnh); SYMADDR(attnl, g_attnl);
    SYMADDR(hcath, g_hcath); SYMADDR(hcatl, g_hcatl);
    SYMADDR(hfush, g_hfush); SYMADDR(hfusl, g_hfusl);
    SYMADDR(wihh, g_wihh); SYMADDR(wihl, g_wihl);
    SYMADDR(inwh, g_inwh); SYMADDR(inwl, g_inwl);
    SYMADDR(mowh, g_mowh); SYMADDR(mowl, g_mowl);
    SYMADDR(fuwh, g_fuwh); SYMADDR(fuwl, g_fuwl);
    SYMADDR(owh, g_owh); SYMADDR(owl, g_owl);

    const int DYN = 49152;

    float* out_main = (float*)d_out;
    float* out_ht   = out_main + (size_t)NNODE * NOUT;
    float* out_hc   = out_ht   + (size_t)NNODE * HID;

    const int* src_t = ei_t; const int* dst_t = ei_t + NE;
    const int* src_c = ei_c; const int* dst_c = ei_c + NE;
    int nepb = (NEP + 255) / 256, neb = (NE + 255) / 256;

    k_init<<<64, 256>>>();
    k_meanp<<<128, 256>>>(ea_t, ea_c);
    k_setup<<<1, 256>>>(We_t, ae_t, We_c, ae_c, lstm_bih, lstm_bhh);

    // weight conversions
    k_conv<<<(1024*2048+255)/256, 256>>>(lstm_Wih, wihh, wihl, 1024*2048);
    k_conv<<<(768*256+255)/256, 256>>>(mha_in_w, inwh, inwl, 768*256);
    k_conv<<<(256*256+255)/256, 256>>>(mha_out_w, mowh, mowl, 256*256);
    k_conv<<<(256*512+255)/256, 256>>>(fus_w, fuwh, fuwl, 256*512);
    k_conv<<<(128*256+255)/256, 256>>>(out_w, owh, owl, 128*256);

    // ---- GATs ----
    k_xp2<<<dim3(8, 256), 256>>>(x, W_t, 0);
    k_xp2<<<dim3(8, 256), 256>>>(x, W_c, 1);
    k_asd<<<NNODE, 256>>>(asrc_t, adst_t, 0);
    k_asd<<<NNODE, 256>>>(asrc_c, adst_c, 1);
    k_count<<<neb, 256>>>(dst_t, 0);
    k_count<<<neb, 256>>>(dst_c, 1);
    k_scan<<<2, 1024>>>();
    k_scatter<<<neb, 256>>>(dst_t, 0);
    k_scatter<<<neb, 256>>>(dst_c, 1);
    k_alpha<<<nepb, 256>>>(src_t, dst_t, ea_t, 0);
    k_alpha<<<nepb, 256>>>(src_c, dst_c, ea_c, 1);
    k_ex<<<nepb, 256>>>(dst_t, 0);
    k_ex<<<nepb, 256>>>(dst_c, 1);
    k_agg<<<NNODE, 256>>>(src_t, 0, b_t, hth, htl, 1);
    k_agg<<<NNODE, 256>>>(src_c, 1, b_c, hch, hcl, 0);

    // ---- temporal: LSTM gates (4096x1024x2048) ----
    mma_gemm<<<dim3(16, 32, 1), 256, DYN>>>(
        hth, htl, NHC, 0, wihh, wihl, NHC, 0,
        big + OFF_G, 1024, 0, nullptr, nullptr, 0, 0, 0,
        NHC, big + OFF_BSUM, 1.f, 0);
    k_lstm<<<NNODE, 256>>>(big + OFF_G, out_ht, hcath, hcatl);

    // ---- causal: qkv (4096x768x256) ----
    mma_gemm<<<dim3(12, 32, 1), 256, DYN>>>(
        hch, hcl, 256, 0, inwh, inwl, 256, 0,
        nullptr, 0, 0, qkvh, qkvl, 768, 0, 0,
        256, mha_in_b, 1.f, 0);
    k_vt<<<(4*64*NNODE)/256, 256>>>(qkvh, qkvl, vth, vtl);

    // ---- S = 0.125 * Q K^T (per head, 4096x4096x64) ----
    mma_gemm<<<dim3(64, 32, 4), 256, DYN>>>(
        qkvh, qkvl, 768, 64, qkvh + 256, qkvl + 256, 768, 64,
        big + OFF_S, NNODE, SHEAD, nullptr, nullptr, 0, 0, 0,
        64, nullptr, 0.125f, 0);
    k_softmax<<<dim3(NNODE, 4), 256>>>(big + OFF_S, ph, pl);

    // ---- ATTN = P V (per head, 4096x64x4096) ----
    mma_gemm<<<dim3(1, 32, 4), 256, DYN>>>(
        ph, pl, NNODE, SHEAD, vth, vtl, NNODE, (unsigned long long)64 * NNODE,
        nullptr, 0, 0, attnh, attnl, 256, 64, 0,
        NNODE, nullptr, 1.f, 0);

    // ---- proj (4096x256x256) ----
    mma_gemm<<<dim3(4, 32, 1), 256, DYN>>>(
        attnh, attnl, 256, 0, mowh, mowl, 256, 0,
        out_hc, 256, 0, hcath, hcatl, 512, 0, 256,
        256, mha_out_b, 1.f, 0);

    // ---- fusion relu (4096x256x512) ----
    mma_gemm<<<dim3(4, 32, 1), 256, DYN>>>(
        hcath, hcatl, 512, 0, fuwh, fuwl, 512, 0,
        nullptr, 0, 0, hfush, hfusl, 256, 0, 0,
        512, fus_b, 1.f, 1);

    // ---- out (4096x128x256) ----
    mma_gemm<<<dim3(2, 32, 1), 256, DYN>>>(
        hfush, hfusl, 256, 0, owh, owl, 256, 0,
        out_main, NOUT, 0, nullptr, nullptr, 0, 0, 0,
        256, out_b, 1.f, 0);
}

// round 5
// speedup vs baseline: 2.1049x; 1.2642x over previous
#include <cuda_runtime.h>
#include <cuda_bf16.h>
#include <math.h>
#include <float.h>
#include <stdint.h>

#define NNODE 4096
#define NIN   28
#define NE    131072
#define NEP   (NE + NNODE)
#define NH    8
#define NC    256
#define NHC   2048
#define HID   256
#define NOUT  128

// ---------------- fp32 scratch ----------------
#define OFF_G    ((size_t)0)
#define OFF_BSUM (OFF_G + (size_t)NNODE * 1024)
#define BIG_SZ   (OFF_BSUM + 1024)
__device__ float g_big[BIG_SZ];

__device__ float g_xp[2][(size_t)NNODE * NHC];
__device__ float g_as[2][NNODE * NH];
__device__ float g_ad[2][NNODE * NH];
__device__ float g_w [2][(size_t)NEP * NH];
__device__ int   g_mx[2][NNODE * NH];
__device__ float g_den[2][NNODE * NH];
__device__ int   g_cnt[2][NNODE];
__device__ int   g_cur[2][NNODE];
__device__ int   g_start[2][NNODE];
__device__ int   g_sorted[2][NE];
__device__ float g_part[2][128];
__device__ float g_mean[2];
__device__ float g_ce[2][NH];

// ---------------- bf16 hi/lo tensors ----------------
__device__ __nv_bfloat16 g_hth[(size_t)NNODE * NHC], g_htl[(size_t)NNODE * NHC];
__device__ __nv_bfloat16 g_hch[(size_t)NNODE * 256], g_hcl[(size_t)NNODE * 256];
__device__ __nv_bfloat16 g_qkvh[(size_t)NNODE * 768], g_qkvl[(size_t)NNODE * 768];
__device__ __nv_bfloat16 g_vth[(size_t)4 * 64 * NNODE], g_vtl[(size_t)4 * 64 * NNODE];
__device__ __nv_bfloat16 g_attnh[(size_t)NNODE * 256], g_attnl[(size_t)NNODE * 256];
__device__ __nv_bfloat16 g_hcath[(size_t)NNODE * 512], g_hcatl[(size_t)NNODE * 512];
__device__ __nv_bfloat16 g_hfush[(size_t)NNODE * 256], g_hfusl[(size_t)NNODE * 256];
// weights
__device__ __nv_bfloat16 g_wihh[1024 * 2048], g_wihl[1024 * 2048];
__device__ __nv_bfloat16 g_inwh[768 * 256],   g_inwl[768 * 256];
__device__ __nv_bfloat16 g_mowh[256 * 256],   g_mowl[256 * 256];
__device__ __nv_bfloat16 g_fuwh[256 * 512],   g_fuwl[256 * 512];
__device__ __nv_bfloat16 g_owh[128 * 256],    g_owl[128 * 256];

// ---------------- helpers ----------------
__device__ __forceinline__ int   f2ord(float f){ int i = __float_as_int(f); return i >= 0 ? i : i ^ 0x7fffffff; }
__device__ __forceinline__ float ord2f(int k){ return __int_as_float(k >= 0 ? k : k ^ 0x7fffffff); }
__device__ __forceinline__ float sigmf(float x){ return 1.f / (1.f + expf(-x)); }
__device__ __forceinline__ void f2hl(float v, __nv_bfloat16* H, __nv_bfloat16* L, size_t i){
    __nv_bfloat16 h = __float2bfloat16(v);
    H[i] = h; L[i] = __float2bfloat16(v - __bfloat162float(h));
}
__device__ __forceinline__ uint32_t smem_u32(const void* p){
    uint32_t a;
    asm("{ .reg .u64 t; cvta.to.shared.u64 t, %1; cvt.u32.u64 %0, t; }" : "=r"(a) : "l"(p));
    return a;
}
__device__ __forceinline__ void ldm_x4(uint32_t* r, uint32_t addr){
    asm volatile("ldmatrix.sync.aligned.m8n8.x4.shared.b16 {%0,%1,%2,%3}, [%4];"
        : "=r"(r[0]), "=r"(r[1]), "=r"(r[2]), "=r"(r[3]) : "r"(addr));
}
__device__ __forceinline__ void ldm_x2(uint32_t* r, uint32_t addr){
    asm volatile("ldmatrix.sync.aligned.m8n8.x2.shared.b16 {%0,%1}, [%2];"
        : "=r"(r[0]), "=r"(r[1]) : "r"(addr));
}
__device__ __forceinline__ void mma_bf16(float* c, const uint32_t* a, const uint32_t* b){
    asm volatile("mma.sync.aligned.m16n8k16.row.col.f32.bf16.bf16.f32 "
        "{%0,%1,%2,%3}, {%4,%5,%6,%7}, {%8,%9}, {%0,%1,%2,%3};"
        : "+f"(c[0]), "+f"(c[1]), "+f"(c[2]), "+f"(c[3])
        : "r"(a[0]), "r"(a[1]), "r"(a[2]), "r"(a[3]), "r"(b[0]), "r"(b[1]));
}
__device__ __forceinline__ void cpa16(uint32_t saddr, const void* g){
    asm volatile("cp.async.ca.shared.global [%0], [%1], 16;" :: "r"(saddr), "l"(g));
}
__device__ __forceinline__ void cpa_commit(){ asm volatile("cp.async.commit_group;" ::: "memory"); }
__device__ __forceinline__ void splitpack(float a, float b, uint32_t& hi, uint32_t& lo){
    __nv_bfloat16 ha = __float2bfloat16(a), hb = __float2bfloat16(b);
    __nv_bfloat16 la = __float2bfloat16(a - __bfloat162float(ha));
    __nv_bfloat16 lb = __float2bfloat16(b - __bfloat162float(hb));
    hi = ((uint32_t)__bfloat16_as_ushort(hb) << 16) | (uint32_t)__bfloat16_as_ushort(ha);
    lo = ((uint32_t)__bfloat16_as_ushort(lb) << 16) | (uint32_t)__bfloat16_as_ushort(la);
}

// ================= setup =================
__global__ void k_init(){
    int idx = blockIdx.x * 256 + threadIdx.x, stride = gridDim.x * 256;
    int mi = f2ord(-FLT_MAX);
    for (int i = idx; i < NNODE * NH; i += stride){
        g_mx[0][i] = mi; g_mx[1][i] = mi;
        g_den[0][i] = 0.f; g_den[1][i] = 0.f;
    }
    for (int i = idx; i < NNODE; i += stride){
        g_cnt[0][i] = 0; g_cnt[1][i] = 0;
        g_cur[0][i] = 0; g_cur[1][i] = 0;
    }
}

__global__ void k_meanp(const float* __restrict__ ea_t, const float* __restrict__ ea_c){
    __shared__ float s0[256], s1[256];
    float a = 0.f, b = 0.f;
    for (int i = blockIdx.x * 256 + threadIdx.x; i < NE; i += 128 * 256){ a += ea_t[i]; b += ea_c[i]; }
    s0[threadIdx.x] = a; s1[threadIdx.x] = b; __syncthreads();
    for (int s = 128; s; s >>= 1){
        if (threadIdx.x < s){ s0[threadIdx.x] += s0[threadIdx.x+s]; s1[threadIdx.x] += s1[threadIdx.x+s]; }
        __syncthreads();
    }
    if (!threadIdx.x){ g_part[0][blockIdx.x] = s0[0]; g_part[1][blockIdx.x] = s1[0]; }
}

__global__ void k_setup(const float* __restrict__ We_t, const float* __restrict__ ae_t,
                        const float* __restrict__ We_c, const float* __restrict__ ae_c,
                        const float* __restrict__ bih,  const float* __restrict__ bhh){
    __shared__ float sh[256];
    int tid = threadIdx.x;
    for (int g = 0; g < 2; g++){
        sh[tid] = (tid < 128) ? g_part[g][tid] : 0.f;
        __syncthreads();
        for (int s = 128; s; s >>= 1){ if (tid < s) sh[tid] += sh[tid+s]; __syncthreads(); }
        if (!tid) g_mean[g] = sh[0] / (float)NE;
        __syncthreads();
    }
    int wid = tid >> 5, lane = tid & 31;
    for (int c = wid; c < 16; c += 8){
        int g = c >> 3, h = c & 7;
        const float* We = g ? We_c : We_t;
        const float* ae = g ? ae_c : ae_t;
        float s = 0.f;
        for (int i = lane; i < NC; i += 32) s = fmaf(We[h*NC + i], ae[h*NC + i], s);
        for (int o = 16; o; o >>= 1) s += __shfl_down_sync(0xffffffffu, s, o);
        if (!lane) g_ce[g][h] = s;
    }
    for (int j = tid; j < 1024; j += 256) g_big[OFF_BSUM + j] = bih[j] + bhh[j];
}

__global__ void k_conv(const float* __restrict__ in, __nv_bfloat16* __restrict__ H,
                       __nv_bfloat16* __restrict__ L, int n){
    int i = blockIdx.x * 256 + threadIdx.x;
    if (i < n) f2hl(in[i], H, L, i);
}

// ================= GAT =================
__global__ void __launch_bounds__(256) k_xp2(const float* __restrict__ x, const float* __restrict__ W, int g){
    __shared__ float Ws[NIN][256];
    __shared__ float xs[16][32];
    int tid = threadIdx.x;
    int col = blockIdx.x * 256 + tid;
    int n0 = blockIdx.y * 16;
#pragma unroll
    for (int k = 0; k < NIN; k++) Ws[k][tid] = W[k * NHC + col];
    for (int i = tid; i < 16 * NIN; i += 256){ int n = i / NIN, k = i % NIN; xs[n][k] = x[(size_t)(n0 + n) * NIN + k]; }
    for (int i = tid; i < 16 * 4; i += 256) xs[i >> 2][NIN + (i & 3)] = 0.f;
    __syncthreads();
    float acc[16] = {};
    for (int k0 = 0; k0 < 28; k0 += 4){
        float w0 = Ws[k0][tid], w1 = Ws[k0+1][tid], w2 = Ws[k0+2][tid], w3 = Ws[k0+3][tid];
#pragma unroll
        for (int n = 0; n < 16; n++){
            float4 xv = *(const float4*)&xs[n][k0];
            acc[n] = fmaf(xv.x, w0, fmaf(xv.y, w1, fmaf(xv.z, w2, fmaf(xv.w, w3, acc[n]))));
        }
    }
#pragma unroll
    for (int n = 0; n < 16; n++) g_xp[g][(size_t)(n0 + n) * NHC + col] = acc[n];
}

__global__ void k_asd(const float* __restrict__ asrc, const float* __restrict__ adst, int g){
    int n = blockIdx.x, h = threadIdx.x >> 5, lane = threadIdx.x & 31;
    const float* xr = g_xp[g] + (size_t)n * NHC + h * NC;
    float s1 = 0.f, s2 = 0.f;
    for (int c = lane; c < NC; c += 32){
        float v = xr[c];
        s1 = fmaf(v, asrc[h*NC + c], s1);
        s2 = fmaf(v, adst[h*NC + c], s2);
    }
    for (int o = 16; o; o >>= 1){ s1 += __shfl_down_sync(~0u, s1, o); s2 += __shfl_down_sync(~0u, s2, o); }
    if (!lane){ g_as[g][n*NH + h] = s1; g_ad[g][n*NH + h] = s2; }
}

__global__ void k_count(const int* __restrict__ dst, int g){
    int e = blockIdx.x * 256 + threadIdx.x;
    if (e < NE) atomicAdd(&g_cnt[g][dst[e]], 1);
}

__global__ void k_scan(){
    int g = blockIdx.x, tid = threadIdx.x;
    __shared__ int sh[1024];
    int base = tid * 4;
    int c0 = g_cnt[g][base], c1 = g_cnt[g][base+1], c2 = g_cnt[g][base+2], c3 = g_cnt[g][base+3];
    int s = c0 + c1 + c2 + c3;
    sh[tid] = s; __syncthreads();
    for (int off = 1; off < 1024; off <<= 1){
        int v = (tid >= off) ? sh[tid - off] : 0;
        __syncthreads();
        sh[tid] += v;
        __syncthreads();
    }
    int excl = sh[tid] - s;
    g_start[g][base]   = excl;
    g_start[g][base+1] = excl + c0;
    g_start[g][base+2] = excl + c0 + c1;
    g_start[g][base+3] = excl + c0 + c1 + c2;
}

__global__ void k_scatter(const int* __restrict__ dst, int g){
    int e = blockIdx.x * 256 + threadIdx.x;
    if (e < NE){
        int d = dst[e];
        int pos = g_start[g][d] + atomicAdd(&g_cur[g][d], 1);
        g_sorted[g][pos] = e;
    }
}

__global__ void k_alpha(const int* __restrict__ src, const int* __restrict__ dst,
                        const float* __restrict__ ea, int g){
    int e = blockIdx.x * 256 + threadIdx.x;
    if (e >= NEP) return;
    int s, d; float av;
    if (e < NE){ s = src[e]; d = dst[e]; av = ea[e]; }
    else { s = d = e - NE; av = g_mean[g]; }
#pragma unroll
    for (int h = 0; h < NH; h++){
        float al = g_as[g][s*NH + h] + g_ad[g][d*NH + h] + av * g_ce[g][h];
        al = al > 0.f ? al : 0.2f * al;
        g_w[g][(size_t)e * NH + h] = al;
        atomicMax(&g_mx[g][d*NH + h], f2ord(al));
    }
}

__global__ void k_ex(const int* __restrict__ dst, int g){
    int e = blockIdx.x * 256 + threadIdx.x;
    if (e >= NEP) return;
    int d = (e < NE) ? dst[e] : e - NE;
#pragma unroll
    for (int h = 0; h < NH; h++){
        float al = g_w[g][(size_t)e * NH + h];
        float ex = expf(al - ord2f(g_mx[g][d*NH + h]));
        g_w[g][(size_t)e * NH + h] = ex;
        atomicAdd(&g_den[g][d*NH + h], ex);
    }
}

__global__ void __launch_bounds__(256) k_agg(const int* __restrict__ src, int g,
                                             const float* __restrict__ bias,
                                             __nv_bfloat16* __restrict__ Oh,
                                             __nv_bfloat16* __restrict__ Ol, int concat){
    int n = blockIdx.x, t = threadIdx.x;
    const float* xp = g_xp[g];
    const float* w  = g_w[g];
    float acc[NH];
    {
        size_t e = (size_t)(NE + n) * NH;
        const float* xr = xp + (size_t)n * NHC + t;
#pragma unroll
        for (int h = 0; h < NH; h++) acc[h] = w[e + h] * xr[h * NC];
    }
    __shared__ int   ssrc[32];
    __shared__ float sw[32][NH];
    int st = g_start[g][n], c = g_cnt[g][n];
    for (int i0 = 0; i0 < c; i0 += 32){
        int m = min(32, c - i0);
        __syncthreads();
        if (t < m) ssrc[t] = src[g_sorted[g][st + i0 + t]];
        {
            int j = t >> 3, h = t & 7;
            if (j < m) sw[j][h] = w[(size_t)g_sorted[g][st + i0 + j] * NH + h];
        }
        __syncthreads();
        for (int jj = 0; jj < m; jj++){
            const float* xr = xp + (size_t)ssrc[jj] * NHC + t;
#pragma unroll
            for (int h = 0; h < NH; h++) acc[h] = fmaf(sw[jj][h], xr[h * NC], acc[h]);
        }
    }
    const float* den = g_den[g] + n * NH;
    if (concat){
#pragma unroll
        for (int h = 0; h < NH; h++){
            float v = acc[h] / (den[h] + 1e-16f) + bias[h * NC + t];
            f2hl(v, Oh, Ol, (size_t)n * NHC + h * NC + t);
        }
    } else {
        float s = 0.f;
#pragma unroll
        for (int h = 0; h < NH; h++) s += acc[h] / (den[h] + 1e-16f);
        f2hl(s * 0.125f + bias[t], Oh, Ol, (size_t)n * NC + t);
    }
}

// ================= HMMA bf16x3 GEMM =================
__global__ void __launch_bounds__(256) mma_gemm(
    const __nv_bfloat16* __restrict__ Ah, const __nv_bfloat16* __restrict__ Al, int lda, unsigned long long sA,
    const __nv_bfloat16* __restrict__ Bh, const __nv_bfloat16* __restrict__ Bl, int ldb, unsigned long long sB,
    float* __restrict__ C, int ldc, unsigned long long sC,
    __nv_bfloat16* __restrict__ Ch, __nv_bfloat16* __restrict__ Cl, int ldc2, unsigned long long sC2, int c2off,
    int K, const float* __restrict__ bias, float alpha, int act)
{
    extern __shared__ char sm[];   // [Ah 16K][Al 16K][Bh 8K][Bl 8K] = 48K
    int tid = threadIdx.x, lane = tid & 31, wid = tid >> 5;
    int wm = wid & 3, wn = wid >> 2;
    int z = blockIdx.z;
    Ah += (size_t)z * sA; Al += (size_t)z * sA;
    Bh += (size_t)z * sB; Bl += (size_t)z * sB;
    if (C) C += (size_t)z * sC;
    if (Ch){ Ch += (size_t)z * sC2; Cl += (size_t)z * sC2; }
    int row0 = blockIdx.y * 128, col0 = blockIdx.x * 64;
    Ah += (size_t)row0 * lda; Al += (size_t)row0 * lda;
    Bh += (size_t)col0 * ldb; Bl += (size_t)col0 * ldb;

    uint32_t sbase = smem_u32(sm);
    float acc[2][4][4] = {};
    int nkb = K >> 6;

    for (int kb = 0; kb < nkb; kb++){
        int k0 = kb << 6;
#pragma unroll
        for (int it = 0; it < 4; it++){
            int i = tid + it * 256;
            int row = i >> 3, seg = i & 7;
            size_t goff = (size_t)row * lda + k0 + seg * 8;
            uint32_t so = row * 128 + ((seg ^ (row & 7)) << 4);
            *(uint4*)(sm + so)          = *(const uint4*)(Ah + goff);
            *(uint4*)(sm + 16384 + so)  = *(const uint4*)(Al + goff);
        }
#pragma unroll
        for (int it = 0; it < 2; it++){
            int i = tid + it * 256;
            int row = i >> 3, seg = i & 7;
            size_t goff = (size_t)row * ldb + k0 + seg * 8;
            uint32_t so = row * 128 + ((seg ^ (row & 7)) << 4);
            *(uint4*)(sm + 32768 + so)  = *(const uint4*)(Bh + goff);
            *(uint4*)(sm + 40960 + so)  = *(const uint4*)(Bl + goff);
        }
        __syncthreads();
#pragma unroll
        for (int ks = 0; ks < 4; ks++){
            uint32_t a_h[2][4], a_l[2][4], b_h[4][2], b_l[4][2];
#pragma unroll
            for (int mt = 0; mt < 2; mt++){
                int r = wm * 32 + mt * 16 + (lane & 15);
                int seg = ks * 2 + (lane >> 4);
                uint32_t ad = sbase + r * 128 + ((seg ^ (r & 7)) << 4);
                ldm_x4(a_h[mt], ad);
                ldm_x4(a_l[mt], ad + 16384);
            }
#pragma unroll
            for (int nt = 0; nt < 4; nt++){
                int r = wn * 32 + nt * 8 + (lane & 7);
                int seg = ks * 2 + ((lane >> 3) & 1);
                uint32_t bd = sbase + 32768 + r * 128 + ((seg ^ (r & 7)) << 4);
                ldm_x2(b_h[nt], bd);
                ldm_x2(b_l[nt], bd + 8192);
            }
#pragma unroll
            for (int mt = 0; mt < 2; mt++)
#pragma unroll
                for (int nt = 0; nt < 4; nt++){
                    mma_bf16(acc[mt][nt], a_h[mt], b_h[nt]);
                    mma_bf16(acc[mt][nt], a_h[mt], b_l[nt]);
                    mma_bf16(acc[mt][nt], a_l[mt], b_h[nt]);
                }
        }
        __syncthreads();
    }

#pragma unroll
    for (int mt = 0; mt < 2; mt++){
#pragma unroll
        for (int nt = 0; nt < 4; nt++){
            int r0 = row0 + wm * 32 + mt * 16 + (lane >> 2);
            int c0 = col0 + wn * 32 + nt * 8 + ((lane & 3) << 1);
#pragma unroll
            for (int q = 0; q < 4; q++){
                int r = r0 + (q >> 1) * 8;
                int cc = c0 + (q & 1);
                float v = acc[mt][nt][q] * alpha;
                if (bias) v += bias[cc];
                if (act == 1) v = fmaxf(v, 0.f);
                if (C) C[(size_t)r * ldc + cc] = v;
                if (Ch) f2hl(v, Ch, Cl, (size_t)r * ldc2 + c2off + cc);
            }
        }
    }
}

// ================= flash attention =================
// grid (32 row-tiles, 4 heads), 256 threads (8 warps x 16 rows).
// smem: QH 16K | QL 16K | buf0 {KH 8K, KL 8K, VH 8K, VL 8K} | buf1 {...} = 96KB
__global__ void __launch_bounds__(256) k_flash(
    const __nv_bfloat16* __restrict__ qkvh, const __nv_bfloat16* __restrict__ qkvl,
    const __nv_bfloat16* __restrict__ vth, const __nv_bfloat16* __restrict__ vtl,
    __nv_bfloat16* __restrict__ Oh, __nv_bfloat16* __restrict__ Ol)
{
    extern __shared__ char sm[];
    int tid = threadIdx.x, lane = tid & 31, wid = tid >> 5;
    int head = blockIdx.y;
    int row0 = blockIdx.x * 128;
    uint32_t sb = smem_u32(sm);

    const __nv_bfloat16* Qh = qkvh + (size_t)row0 * 768 + head * 64;
    const __nv_bfloat16* Ql = qkvl + (size_t)row0 * 768 + head * 64;
    const __nv_bfloat16* Kh = qkvh + 256 + head * 64;
    const __nv_bfloat16* Kl = qkvl + 256 + head * 64;
    const __nv_bfloat16* Vh = vth + (size_t)head * 64 * 4096;
    const __nv_bfloat16* Vl = vtl + (size_t)head * 64 * 4096;

    // ---- load Q tile (hi/lo) + first K/V buffer via cp.async ----
#pragma unroll
    for (int it = 0; it < 4; it++){
        int i = tid + it * 256;                  // 1024 pairs
        int r = i >> 3, seg = i & 7;
        uint32_t so = r * 128 + ((seg ^ (r & 7)) << 4);
        cpa16(sb + so,         Qh + (size_t)r * 768 + seg * 8);
        cpa16(sb + 16384 + so, Ql + (size_t)r * 768 + seg * 8);
    }
#pragma unroll
    for (int it = 0; it < 2; it++){
        int i = tid + it * 256;                  // 512 pairs
        int r = i >> 3, seg = i & 7;
        uint32_t so = r * 128 + ((seg ^ (r & 7)) << 4);
        cpa16(sb + 32768 + so,         Kh + (size_t)r * 768 + seg * 8);
        cpa16(sb + 32768 + 8192 + so,  Kl + (size_t)r * 768 + seg * 8);
        cpa16(sb + 32768 + 16384 + so, Vh + (size_t)r * 4096 + seg * 8);
        cpa16(sb + 32768 + 24576 + so, Vl + (size_t)r * 4096 + seg * 8);
    }
    cpa_commit();
    asm volatile("cp.async.wait_group 0;" ::: "memory");
    __syncthreads();

    // ---- Q register fragments (persist across all key tiles) ----
    uint32_t qf_h[4][4], qf_l[4][4];
#pragma unroll
    for (int ks = 0; ks < 4; ks++){
        int r = wid * 16 + (lane & 15);
        int seg = ks * 2 + (lane >> 4);
        uint32_t ad = sb + r * 128 + ((seg ^ (r & 7)) << 4);
        ldm_x4(qf_h[ks], ad);
        ldm_x4(qf_l[ks], ad + 16384);
    }

    float m0 = -1e30f, m1 = -1e30f, l0 = 0.f, l1 = 0.f;
    float acc_o[8][4] = {};
    int buf = 0;

    for (int kt = 0; kt < 64; kt++){
        if (kt < 63){
            uint32_t bo = sb + 32768 + (buf ^ 1) * 32768;
            int key0 = (kt + 1) * 64;
#pragma unroll
            for (int it = 0; it < 2; it++){
                int i = tid + it * 256;
                int r = i >> 3, seg = i & 7;
                uint32_t so = r * 128 + ((seg ^ (r & 7)) << 4);
                cpa16(bo + so,         Kh + (size_t)(key0 + r) * 768 + seg * 8);
                cpa16(bo + 8192 + so,  Kl + (size_t)(key0 + r) * 768 + seg * 8);
                cpa16(bo + 16384 + so, Vh + (size_t)r * 4096 + key0 + seg * 8);
                cpa16(bo + 24576 + so, Vl + (size_t)r * 4096 + key0 + seg * 8);
            }
            cpa_commit();
            asm volatile("cp.async.wait_group 1;" ::: "memory");
        } else {
            asm volatile("cp.async.wait_group 0;" ::: "memory");
        }
        __syncthreads();

        uint32_t kb = sb + 32768 + buf * 32768;

        // ---- S tile = Q K^T (bf16x3) ----
        float acc_s[8][4] = {};
#pragma unroll
        for (int ks = 0; ks < 4; ks++){
            uint32_t bh[8][2], bl[8][2];
#pragma unroll
            for (int nt = 0; nt < 8; nt++){
                int r = nt * 8 + (lane & 7);
                int seg = ks * 2 + ((lane >> 3) & 1);
                uint32_t bd = kb + r * 128 + ((seg ^ (r & 7)) << 4);
                ldm_x2(bh[nt], bd);
                ldm_x2(bl[nt], bd + 8192);
            }
#pragma unroll
            for (int nt = 0; nt < 8; nt++){
                mma_bf16(acc_s[nt], qf_h[ks], bh[nt]);
                mma_bf16(acc_s[nt], qf_h[ks], bl[nt]);
                mma_bf16(acc_s[nt], qf_l[ks], bh[nt]);
            }
        }
#pragma unroll
        for (int nt = 0; nt < 8; nt++){
            acc_s[nt][0] *= 0.125f; acc_s[nt][1] *= 0.125f;
            acc_s[nt][2] *= 0.125f; acc_s[nt][3] *= 0.125f;
        }

        // ---- online softmax ----
        float tm0 = -1e30f, tm1 = -1e30f;
#pragma unroll
        for (int nt = 0; nt < 8; nt++){
            tm0 = fmaxf(tm0, fmaxf(acc_s[nt][0], acc_s[nt][1]));
            tm1 = fmaxf(tm1, fmaxf(acc_s[nt][2], acc_s[nt][3]));
        }
        tm0 = fmaxf(tm0, __shfl_xor_sync(~0u, tm0, 1)); tm0 = fmaxf(tm0, __shfl_xor_sync(~0u, tm0, 2));
        tm1 = fmaxf(tm1, __shfl_xor_sync(~0u, tm1, 1)); tm1 = fmaxf(tm1, __shfl_xor_sync(~0u, tm1, 2));
        float mn0 = fmaxf(m0, tm0), mn1 = fmaxf(m1, tm1);
        float sc0 = __expf(m0 - mn0), sc1 = __expf(m1 - mn1);
        m0 = mn0; m1 = mn1;
        l0 *= sc0; l1 *= sc1;
#pragma unroll
        for (int nt = 0; nt < 8; nt++){
            acc_o[nt][0] *= sc0; acc_o[nt][1] *= sc0;
            acc_o[nt][2] *= sc1; acc_o[nt][3] *= sc1;
        }
        float rs0 = 0.f, rs1 = 0.f;
        uint32_t pa_h[4][4], pa_l[4][4];
#pragma unroll
        for (int nt = 0; nt < 8; nt++){
            float p0 = __expf(acc_s[nt][0] - mn0), p1 = __expf(acc_s[nt][1] - mn0);
            float p2 = __expf(acc_s[nt][2] - mn1), p3 = __expf(acc_s[nt][3] - mn1);
            rs0 += p0 + p1; rs1 += p2 + p3;
            int k2 = nt >> 1;
            if (!(nt & 1)){
                splitpack(p0, p1, pa_h[k2][0], pa_l[k2][0]);
                splitpack(p2, p3, pa_h[k2][1], pa_l[k2][1]);
            } else {
                splitpack(p0, p1, pa_h[k2][2], pa_l[k2][2]);
                splitpack(p2, p3, pa_h[k2][3], pa_l[k2][3]);
            }
        }
        rs0 += __shfl_xor_sync(~0u, rs0, 1); rs0 += __shfl_xor_sync(~0u, rs0, 2);
        rs1 += __shfl_xor_sync(~0u, rs1, 1); rs1 += __shfl_xor_sync(~0u, rs1, 2);
        l0 += rs0; l1 += rs1;

        // ---- O += P V (bf16x3, A from registers) ----
        uint32_t vb = kb + 16384;
#pragma unroll
        for (int k2 = 0; k2 < 4; k2++){
            uint32_t vh[8][2], vl[8][2];
#pragma unroll
            for (int nt = 0; nt < 8; nt++){
                int r = nt * 8 + (lane & 7);
                int seg = k2 * 2 + ((lane >> 3) & 1);
                uint32_t vd = vb + r * 128 + ((seg ^ (r & 7)) << 4);
                ldm_x2(vh[nt], vd);
                ldm_x2(vl[nt], vd + 8192);
            }
#pragma unroll
            for (int nt = 0; nt < 8; nt++){
                mma_bf16(acc_o[nt], pa_h[k2], vh[nt]);
                mma_bf16(acc_o[nt], pa_h[k2], vl[nt]);
                mma_bf16(acc_o[nt], pa_l[k2], vh[nt]);
            }
        }
        __syncthreads();
        buf ^= 1;
    }

    // ---- epilogue ----
    float inv0 = 1.f / l0, inv1 = 1.f / l1;
    int r = row0 + wid * 16 + (lane >> 2);
#pragma unroll
    for (int nt = 0; nt < 8; nt++){
        int cc = head * 64 + nt * 8 + ((lane & 3) << 1);
        f2hl(acc_o[nt][0] * inv0, Oh, Ol, (size_t)r * 256 + cc);
        f2hl(acc_o[nt][1] * inv0, Oh, Ol, (size_t)r * 256 + cc + 1);
        f2hl(acc_o[nt][2] * inv1, Oh, Ol, (size_t)(r + 8) * 256 + cc);
        f2hl(acc_o[nt][3] * inv1, Oh, Ol, (size_t)(r + 8) * 256 + cc + 1);
    }
}

// ================= pointwise =================
__global__ void k_lstm(const float* __restrict__ G, float* __restrict__ ht_out,
                       __nv_bfloat16* __restrict__ Hh, __nv_bfloat16* __restrict__ Hl){
    int idx = blockIdx.x * 256 + threadIdx.x;
    int n = idx >> 8, j = idx & 255;
    const float* gr = G + (size_t)n * 1024;
    float ig = gr[j], gg = gr[512 + j], og = gr[768 + j];
    float cc = sigmf(ig) * tanhf(gg);
    float hv = sigmf(og) * tanhf(cc);
    ht_out[idx] = hv;
    f2hl(hv, Hh, Hl, (size_t)n * 512 + j);
}

__global__ void k_vt(const __nv_bfloat16* __restrict__ qh, const __nv_bfloat16* __restrict__ ql,
                     __nv_bfloat16* __restrict__ vh, __nv_bfloat16* __restrict__ vl){
    int idx = blockIdx.x * 256 + threadIdx.x;
    int hd = idx >> 12, n = idx & 4095;
    size_t s = (size_t)n * 768 + 512 + hd;
    vh[idx] = qh[s]; vl[idx] = ql[s];
}

// ================= launch =================
#define SYMADDR(p, s) do { void* _t; cudaGetSymbolAddress(&_t, s); p = (decltype(p))_t; } while(0)

extern "C" void kernel_launch(void* const* d_in, const int* in_sizes, int n_in,
                              void* d_out, int out_size) {
    const float* x     = (const float*)d_in[0];
    const int*   ei_t  = (const int*)d_in[1];
    const int*   ei_c  = (const int*)d_in[2];
    const float* ea_t  = (const float*)d_in[3];
    const float* ea_c  = (const float*)d_in[4];
    const float* W_t   = (const float*)d_in[5];
    const float* asrc_t= (const float*)d_in[6];
    const float* adst_t= (const float*)d_in[7];
    const float* We_t  = (const float*)d_in[8];
    const float* ae_t  = (const float*)d_in[9];
    const float* b_t   = (const float*)d_in[10];
    const float* W_c   = (const float*)d_in[11];
    const float* asrc_c= (const float*)d_in[12];
    const float* adst_c= (const float*)d_in[13];
    const float* We_c  = (const float*)d_in[14];
    const float* ae_c  = (const float*)d_in[15];
    const float* b_c   = (const float*)d_in[16];
    const float* lstm_Wih = (const float*)d_in[17];
    const float* lstm_bih = (const float*)d_in[19];
    const float* lstm_bhh = (const float*)d_in[20];
    const float* mha_in_w  = (const float*)d_in[21];
    const float* mha_in_b  = (const float*)d_in[22];
    const float* mha_out_w = (const float*)d_in[23];
    const float* mha_out_b = (const float*)d_in[24];
    const float* fus_w = (const float*)d_in[25];
    const float* fus_b = (const float*)d_in[26];
    const float* out_w = (const float*)d_in[27];
    const float* out_b = (const float*)d_in[28];

    float* big; SYMADDR(big, g_big);
    __nv_bfloat16 *hth, *htl, *hch, *hcl, *qkvh, *qkvl, *vth, *vtl;
    __nv_bfloat16 *attnh, *attnl, *hcath, *hcatl, *hfush, *hfusl;
    __nv_bfloat16 *wihh, *wihl, *inwh, *inwl, *mowh, *mowl, *fuwh, *fuwl, *owh, *owl;
    SYMADDR(hth, g_hth); SYMADDR(htl, g_htl); SYMADDR(hch, g_hch); SYMADDR(hcl, g_hcl);
    SYMADDR(qkvh, g_qkvh); SYMADDR(qkvl, g_qkvl); SYMADDR(vth, g_vth); SYMADDR(vtl, g_vtl);
    SYMADDR(attnh, g_attnh); SYMADDR(attnl, g_attnl);
    SYMADDR(hcath, g_hcath); SYMADDR(hcatl, g_hcatl);
    SYMADDR(hfush, g_hfush); SYMADDR(hfusl, g_hfusl);
    SYMADDR(wihh, g_wihh); SYMADDR(wihl, g_wihl);
    SYMADDR(inwh, g_inwh); SYMADDR(inwl, g_inwl);
    SYMADDR(mowh, g_mowh); SYMADDR(mowl, g_mowl);
    SYMADDR(fuwh, g_fuwh); SYMADDR(fuwl, g_fuwl);
    SYMADDR(owh, g_owh); SYMADDR(owl, g_owl);

    cudaFuncSetAttribute(k_flash, cudaFuncAttributeMaxDynamicSharedMemorySize, 98304);
    const int DYN = 49152;
    const int DYN_FA = 98304;

    float* out_main = (float*)d_out;
    float* out_ht   = out_main + (size_t)NNODE * NOUT;
    float* out_hc   = out_ht   + (size_t)NNODE * HID;

    const int* src_t = ei_t; const int* dst_t = ei_t + NE;
    const int* src_c = ei_c; const int* dst_c = ei_c + NE;
    int nepb = (NEP + 255) / 256, neb = (NE + 255) / 256;

    k_init<<<64, 256>>>();
    k_meanp<<<128, 256>>>(ea_t, ea_c);
    k_setup<<<1, 256>>>(We_t, ae_t, We_c, ae_c, lstm_bih, lstm_bhh);

    k_conv<<<(1024*2048+255)/256, 256>>>(lstm_Wih, wihh, wihl, 1024*2048);
    k_conv<<<(768*256+255)/256, 256>>>(mha_in_w, inwh, inwl, 768*256);
    k_conv<<<(256*256+255)/256, 256>>>(mha_out_w, mowh, mowl, 256*256);
    k_conv<<<(256*512+255)/256, 256>>>(fus_w, fuwh, fuwl, 256*512);
    k_conv<<<(128*256+255)/256, 256>>>(out_w, owh, owl, 128*256);

    // ---- GATs ----
    k_xp2<<<dim3(8, 256), 256>>>(x, W_t, 0);
    k_xp2<<<dim3(8, 256), 256>>>(x, W_c, 1);
    k_asd<<<NNODE, 256>>>(asrc_t, adst_t, 0);
    k_asd<<<NNODE, 256>>>(asrc_c, adst_c, 1);
    k_count<<<neb, 256>>>(dst_t, 0);
    k_count<<<neb, 256>>>(dst_c, 1);
    k_scan<<<2, 1024>>>();
    k_scatter<<<neb, 256>>>(dst_t, 0);
    k_scatter<<<neb, 256>>>(dst_c, 1);
    k_alpha<<<nepb, 256>>>(src_t, dst_t, ea_t, 0);
    k_alpha<<<nepb, 256>>>(src_c, dst_c, ea_c, 1);
    k_ex<<<nepb, 256>>>(dst_t, 0);
    k_ex<<<nepb, 256>>>(dst_c, 1);
    k_agg<<<NNODE, 256>>>(src_t, 0, b_t, hth, htl, 1);
    k_agg<<<NNODE, 256>>>(src_c, 1, b_c, hch, hcl, 0);

    // ---- temporal: LSTM gates (4096x1024x2048) ----
    mma_gemm<<<dim3(16, 32, 1), 256, DYN>>>(
        hth, htl, NHC, 0, wihh, wihl, NHC, 0,
        big + OFF_G, 1024, 0, nullptr, nullptr, 0, 0, 0,
        NHC, big + OFF_BSUM, 1.f, 0);
    k_lstm<<<NNODE, 256>>>(big + OFF_G, out_ht, hcath, hcatl);

    // ---- causal: qkv (4096x768x256) ----
    mma_gemm<<<dim3(12, 32, 1), 256, DYN>>>(
        hch, hcl, 256, 0, inwh, inwl, 256, 0,
        nullptr, 0, 0, qkvh, qkvl, 768, 0, 0,
        256, mha_in_b, 1.f, 0);
    k_vt<<<(4*64*NNODE)/256, 256>>>(qkvh, qkvl, vth, vtl);

    // ---- fused attention (S -> softmax -> PV), never materializing S/P ----
    k_flash<<<dim3(32, 4), 256, DYN_FA>>>(qkvh, qkvl, vth, vtl, attnh, attnl);

    // ---- proj (4096x256x256) ----
    mma_gemm<<<dim3(4, 32, 1), 256, DYN>>>(
        attnh, attnl, 256, 0, mowh, mowl, 256, 0,
        out_hc, 256, 0, hcath, hcatl, 512, 0, 256,
        256, mha_out_b, 1.f, 0);

    // ---- fusion relu (4096x256x512) ----
    mma_gemm<<<dim3(4, 32, 1), 256, DYN>>>(
        hcath, hcatl, 512, 0, fuwh, fuwl, 512, 0,
        nullptr, 0, 0, hfush, hfusl, 256, 0, 0,
        512, fus_b, 1.f, 1);

    // ---- out (4096x128x256) ----
    mma_gemm<<<dim3(2, 32, 1), 256, DYN>>>(
        hfush, hfusl, 256, 0, owh, owl, 256, 0,
        out_main, NOUT, 0, nullptr, nullptr, 0, 0, 0,
        256, out_b, 1.f, 0);
}

// round 6
// speedup vs baseline: 2.2180x; 1.0538x over previous
#include <cuda_runtime.h>
#include <cuda_bf16.h>
#include <math.h>
#include <float.h>
#include <stdint.h>

#define NNODE 4096
#define NIN   28
#define NE    131072
#define NEP   (NE + NNODE)
#define NH    8
#define NC    256
#define NHC   2048
#define HID   256
#define NOUT  128

// ---------------- fp32 scratch ----------------
#define OFF_G    ((size_t)0)
#define OFF_BSUM (OFF_G + (size_t)NNODE * 1024)
#define BIG_SZ   (OFF_BSUM + 1024)
__device__ float g_big[BIG_SZ];

__device__ float g_xp[2][(size_t)NNODE * NHC];
__device__ float g_as[2][NNODE * NH];
__device__ float g_ad[2][NNODE * NH];
__device__ float g_w [2][(size_t)NEP * NH];
__device__ int   g_mx[2][NNODE * NH];
__device__ float g_den[2][NNODE * NH];
__device__ int   g_cnt[2][NNODE];
__device__ int   g_cur[2][NNODE];
__device__ int   g_start[2][NNODE];
__device__ int   g_sorted[2][NE];
__device__ float g_part[2][128];
__device__ float g_mean[2];
__device__ float g_ce[2][NH];

// ---------------- bf16 hi/lo tensors ----------------
__device__ __nv_bfloat16 g_hth[(size_t)NNODE * NHC], g_htl[(size_t)NNODE * NHC];
__device__ __nv_bfloat16 g_hch[(size_t)NNODE * 256], g_hcl[(size_t)NNODE * 256];
__device__ __nv_bfloat16 g_qkvh[(size_t)NNODE * 768], g_qkvl[(size_t)NNODE * 768];
__device__ __nv_bfloat16 g_vth[(size_t)4 * 64 * NNODE], g_vtl[(size_t)4 * 64 * NNODE];
__device__ __nv_bfloat16 g_attnh[(size_t)NNODE * 256], g_attnl[(size_t)NNODE * 256];
__device__ __nv_bfloat16 g_hcath[(size_t)NNODE * 512], g_hcatl[(size_t)NNODE * 512];
__device__ __nv_bfloat16 g_hfush[(size_t)NNODE * 256], g_hfusl[(size_t)NNODE * 256];
// weights
__device__ __nv_bfloat16 g_wihh[1024 * 2048], g_wihl[1024 * 2048];
__device__ __nv_bfloat16 g_inwh[768 * 256],   g_inwl[768 * 256];
__device__ __nv_bfloat16 g_mowh[256 * 256],   g_mowl[256 * 256];
__device__ __nv_bfloat16 g_fuwh[256 * 512],   g_fuwl[256 * 512];
__device__ __nv_bfloat16 g_owh[128 * 256],    g_owl[128 * 256];

// ---------------- helpers ----------------
__device__ __forceinline__ int   f2ord(float f){ int i = __float_as_int(f); return i >= 0 ? i : i ^ 0x7fffffff; }
__device__ __forceinline__ float ord2f(int k){ return __int_as_float(k >= 0 ? k : k ^ 0x7fffffff); }
__device__ __forceinline__ float sigmf(float x){ return 1.f / (1.f + expf(-x)); }
__device__ __forceinline__ void f2hl(float v, __nv_bfloat16* H, __nv_bfloat16* L, size_t i){
    __nv_bfloat16 h = __float2bfloat16(v);
    H[i] = h; L[i] = __float2bfloat16(v - __bfloat162float(h));
}
__device__ __forceinline__ uint32_t smem_u32(const void* p){
    uint32_t a;
    asm("{ .reg .u64 t; cvta.to.shared.u64 t, %1; cvt.u32.u64 %0, t; }" : "=r"(a) : "l"(p));
    return a;
}
__device__ __forceinline__ void ldm_x4(uint32_t* r, uint32_t addr){
    asm volatile("ldmatrix.sync.aligned.m8n8.x4.shared.b16 {%0,%1,%2,%3}, [%4];"
        : "=r"(r[0]), "=r"(r[1]), "=r"(r[2]), "=r"(r[3]) : "r"(addr));
}
__device__ __forceinline__ void ldm_x2(uint32_t* r, uint32_t addr){
    asm volatile("ldmatrix.sync.aligned.m8n8.x2.shared.b16 {%0,%1}, [%2];"
        : "=r"(r[0]), "=r"(r[1]) : "r"(addr));
}
__device__ __forceinline__ void mma_bf16(float* c, const uint32_t* a, const uint32_t* b){
    asm volatile("mma.sync.aligned.m16n8k16.row.col.f32.bf16.bf16.f32 "
        "{%0,%1,%2,%3}, {%4,%5,%6,%7}, {%8,%9}, {%0,%1,%2,%3};"
        : "+f"(c[0]), "+f"(c[1]), "+f"(c[2]), "+f"(c[3])
        : "r"(a[0]), "r"(a[1]), "r"(a[2]), "r"(a[3]), "r"(b[0]), "r"(b[1]));
}
__device__ __forceinline__ void cpa16(uint32_t saddr, const void* g){
    asm volatile("cp.async.ca.shared.global [%0], [%1], 16;" :: "r"(saddr), "l"(g));
}
__device__ __forceinline__ void cpa_commit(){ asm volatile("cp.async.commit_group;" ::: "memory"); }
__device__ __forceinline__ void splitpack(float a, float b, uint32_t& hi, uint32_t& lo){
    __nv_bfloat16 ha = __float2bfloat16(a), hb = __float2bfloat16(b);
    __nv_bfloat16 la = __float2bfloat16(a - __bfloat162float(ha));
    __nv_bfloat16 lb = __float2bfloat16(b - __bfloat162float(hb));
    hi = ((uint32_t)__bfloat16_as_ushort(hb) << 16) | (uint32_t)__bfloat16_as_ushort(ha);
    lo = ((uint32_t)__bfloat16_as_ushort(lb) << 16) | (uint32_t)__bfloat16_as_ushort(la);
}

// ================= setup =================
// 128 blocks: grid-stride init of GAT scratch + edge-attr partial sums
__global__ void k_initmean(const float* __restrict__ ea_t, const float* __restrict__ ea_c){
    int idx = blockIdx.x * 256 + threadIdx.x, stride = gridDim.x * 256;
    int mi = f2ord(-FLT_MAX);
    for (int i = idx; i < NNODE * NH; i += stride){
        g_mx[0][i] = mi; g_mx[1][i] = mi;
        g_den[0][i] = 0.f; g_den[1][i] = 0.f;
    }
    for (int i = idx; i < NNODE; i += stride){
        g_cnt[0][i] = 0; g_cnt[1][i] = 0;
        g_cur[0][i] = 0; g_cur[1][i] = 0;
    }
    __shared__ float s0[256], s1[256];
    float a = 0.f, b = 0.f;
    for (int i = blockIdx.x * 256 + threadIdx.x; i < NE; i += 128 * 256){ a += ea_t[i]; b += ea_c[i]; }
    s0[threadIdx.x] = a; s1[threadIdx.x] = b; __syncthreads();
    for (int s = 128; s; s >>= 1){
        if (threadIdx.x < s){ s0[threadIdx.x] += s0[threadIdx.x+s]; s1[threadIdx.x] += s1[threadIdx.x+s]; }
        __syncthreads();
    }
    if (!threadIdx.x){ g_part[0][blockIdx.x] = s0[0]; g_part[1][blockIdx.x] = s1[0]; }
}

__global__ void k_setup(const float* __restrict__ We_t, const float* __restrict__ ae_t,
                        const float* __restrict__ We_c, const float* __restrict__ ae_c,
                        const float* __restrict__ bih,  const float* __restrict__ bhh){
    __shared__ float sh[256];
    int tid = threadIdx.x;
    for (int g = 0; g < 2; g++){
        sh[tid] = (tid < 128) ? g_part[g][tid] : 0.f;
        __syncthreads();
        for (int s = 128; s; s >>= 1){ if (tid < s) sh[tid] += sh[tid+s]; __syncthreads(); }
        if (!tid) g_mean[g] = sh[0] / (float)NE;
        __syncthreads();
    }
    int wid = tid >> 5, lane = tid & 31;
    for (int c = wid; c < 16; c += 8){
        int g = c >> 3, h = c & 7;
        const float* We = g ? We_c : We_t;
        const float* ae = g ? ae_c : ae_t;
        float s = 0.f;
        for (int i = lane; i < NC; i += 32) s = fmaf(We[h*NC + i], ae[h*NC + i], s);
        for (int o = 16; o; o >>= 1) s += __shfl_down_sync(0xffffffffu, s, o);
        if (!lane) g_ce[g][h] = s;
    }
    for (int j = tid; j < 1024; j += 256) g_big[OFF_BSUM + j] = bih[j] + bhh[j];
}

// all 5 weight hi/lo conversions in one launch (9856 blocks x 256)
#define CW0 2097152
#define CW1 (CW0 + 196608)
#define CW2 (CW1 + 65536)
#define CW3 (CW2 + 131072)
#define CW4 (CW3 + 32768)
__global__ void k_convall(const float* __restrict__ w0, const float* __restrict__ w1,
                          const float* __restrict__ w2, const float* __restrict__ w3,
                          const float* __restrict__ w4){
    int i = blockIdx.x * 256 + threadIdx.x;
    if (i < CW0)      f2hl(w0[i], g_wihh, g_wihl, i);
    else if (i < CW1) f2hl(w1[i - CW0], g_inwh, g_inwl, i - CW0);
    else if (i < CW2) f2hl(w2[i - CW1], g_mowh, g_mowl, i - CW1);
    else if (i < CW3) f2hl(w3[i - CW2], g_fuwh, g_fuwl, i - CW2);
    else if (i < CW4) f2hl(w4[i - CW3], g_owh, g_owl, i - CW3);
}

// ================= GAT =================
__global__ void __launch_bounds__(256) k_xp2(const float* __restrict__ x, const float* __restrict__ W, int g){
    __shared__ float Ws[NIN][256];
    __shared__ float xs[16][32];
    int tid = threadIdx.x;
    int col = blockIdx.x * 256 + tid;
    int n0 = blockIdx.y * 16;
#pragma unroll
    for (int k = 0; k < NIN; k++) Ws[k][tid] = W[k * NHC + col];
    for (int i = tid; i < 16 * NIN; i += 256){ int n = i / NIN, k = i % NIN; xs[n][k] = x[(size_t)(n0 + n) * NIN + k]; }
    for (int i = tid; i < 16 * 4; i += 256) xs[i >> 2][NIN + (i & 3)] = 0.f;
    __syncthreads();
    float acc[16] = {};
    for (int k0 = 0; k0 < 28; k0 += 4){
        float w0 = Ws[k0][tid], w1 = Ws[k0+1][tid], w2 = Ws[k0+2][tid], w3 = Ws[k0+3][tid];
#pragma unroll
        for (int n = 0; n < 16; n++){
            float4 xv = *(const float4*)&xs[n][k0];
            acc[n] = fmaf(xv.x, w0, fmaf(xv.y, w1, fmaf(xv.z, w2, fmaf(xv.w, w3, acc[n]))));
        }
    }
#pragma unroll
    for (int n = 0; n < 16; n++) g_xp[g][(size_t)(n0 + n) * NHC + col] = acc[n];
}

__global__ void k_asd(const float* __restrict__ asrc, const float* __restrict__ adst, int g){
    int n = blockIdx.x, h = threadIdx.x >> 5, lane = threadIdx.x & 31;
    const float* xr = g_xp[g] + (size_t)n * NHC + h * NC;
    float s1 = 0.f, s2 = 0.f;
    for (int c = lane; c < NC; c += 32){
        float v = xr[c];
        s1 = fmaf(v, asrc[h*NC + c], s1);
        s2 = fmaf(v, adst[h*NC + c], s2);
    }
    for (int o = 16; o; o >>= 1){ s1 += __shfl_down_sync(~0u, s1, o); s2 += __shfl_down_sync(~0u, s2, o); }
    if (!lane){ g_as[g][n*NH + h] = s1; g_ad[g][n*NH + h] = s2; }
}

__global__ void k_count(const int* __restrict__ dst, int g){
    int e = blockIdx.x * 256 + threadIdx.x;
    if (e < NE) atomicAdd(&g_cnt[g][dst[e]], 1);
}

__global__ void k_scan(){
    int g = blockIdx.x, tid = threadIdx.x;
    __shared__ int sh[1024];
    int base = tid * 4;
    int c0 = g_cnt[g][base], c1 = g_cnt[g][base+1], c2 = g_cnt[g][base+2], c3 = g_cnt[g][base+3];
    int s = c0 + c1 + c2 + c3;
    sh[tid] = s; __syncthreads();
    for (int off = 1; off < 1024; off <<= 1){
        int v = (tid >= off) ? sh[tid - off] : 0;
        __syncthreads();
        sh[tid] += v;
        __syncthreads();
    }
    int excl = sh[tid] - s;
    g_start[g][base]   = excl;
    g_start[g][base+1] = excl + c0;
    g_start[g][base+2] = excl + c0 + c1;
    g_start[g][base+3] = excl + c0 + c1 + c2;
}

__global__ void k_scatter(const int* __restrict__ dst, int g){
    int e = blockIdx.x * 256 + threadIdx.x;
    if (e < NE){
        int d = dst[e];
        int pos = g_start[g][d] + atomicAdd(&g_cur[g][d], 1);
        g_sorted[g][pos] = e;
    }
}

__global__ void k_alpha(const int* __restrict__ src, const int* __restrict__ dst,
                        const float* __restrict__ ea, int g){
    int e = blockIdx.x * 256 + threadIdx.x;
    if (e >= NEP) return;
    int s, d; float av;
    if (e < NE){ s = src[e]; d = dst[e]; av = ea[e]; }
    else { s = d = e - NE; av = g_mean[g]; }
#pragma unroll
    for (int h = 0; h < NH; h++){
        float al = g_as[g][s*NH + h] + g_ad[g][d*NH + h] + av * g_ce[g][h];
        al = al > 0.f ? al : 0.2f * al;
        g_w[g][(size_t)e * NH + h] = al;
        atomicMax(&g_mx[g][d*NH + h], f2ord(al));
    }
}

__global__ void k_ex(const int* __restrict__ dst, int g){
    int e = blockIdx.x * 256 + threadIdx.x;
    if (e >= NEP) return;
    int d = (e < NE) ? dst[e] : e - NE;
#pragma unroll
    for (int h = 0; h < NH; h++){
        float al = g_w[g][(size_t)e * NH + h];
        float ex = expf(al - ord2f(g_mx[g][d*NH + h]));
        g_w[g][(size_t)e * NH + h] = ex;
        atomicAdd(&g_den[g][d*NH + h], ex);
    }
}

__global__ void __launch_bounds__(256) k_agg(const int* __restrict__ src, int g,
                                             const float* __restrict__ bias,
                                             __nv_bfloat16* __restrict__ Oh,
                                             __nv_bfloat16* __restrict__ Ol, int concat){
    int n = blockIdx.x, t = threadIdx.x;
    const float* xp = g_xp[g];
    const float* w  = g_w[g];
    float acc[NH];
    {
        size_t e = (size_t)(NE + n) * NH;
        const float* xr = xp + (size_t)n * NHC + t;
#pragma unroll
        for (int h = 0; h < NH; h++) acc[h] = w[e + h] * xr[h * NC];
    }
    __shared__ int   ssrc[32];
    __shared__ float sw[32][NH];
    int st = g_start[g][n], c = g_cnt[g][n];
    for (int i0 = 0; i0 < c; i0 += 32){
        int m = min(32, c - i0);
        __syncthreads();
        if (t < m) ssrc[t] = src[g_sorted[g][st + i0 + t]];
        {
            int j = t >> 3, h = t & 7;
            if (j < m) sw[j][h] = w[(size_t)g_sorted[g][st + i0 + j] * NH + h];
        }
        __syncthreads();
        for (int jj = 0; jj < m; jj++){
            const float* xr = xp + (size_t)ssrc[jj] * NHC + t;
#pragma unroll
            for (int h = 0; h < NH; h++) acc[h] = fmaf(sw[jj][h], xr[h * NC], acc[h]);
        }
    }
    const float* den = g_den[g] + n * NH;
    if (concat){
#pragma unroll
        for (int h = 0; h < NH; h++){
            float v = acc[h] / (den[h] + 1e-16f) + bias[h * NC + t];
            f2hl(v, Oh, Ol, (size_t)n * NHC + h * NC + t);
        }
    } else {
        float s = 0.f;
#pragma unroll
        for (int h = 0; h < NH; h++) s += acc[h] / (den[h] + 1e-16f);
        f2hl(s * 0.125f + bias[t], Oh, Ol, (size_t)n * NC + t);
    }
}

// ================= HMMA bf16x3 GEMM (cp.async 2-stage pipelined) =================
// C[M,N] = act(alpha * A·B^T + bias). A=[M,K] hi/lo, B=[N,K] hi/lo, K-major.
// CTA tile 128x64, BK=64, 8 warps (4x2), warp tile 32x32.
// smem: 2 stages x [Ah 16K | Al 16K | Bh 8K | Bl 8K] = 96KB
__global__ void __launch_bounds__(256) mma_gemm(
    const __nv_bfloat16* __restrict__ Ah, const __nv_bfloat16* __restrict__ Al, int lda,
    const __nv_bfloat16* __restrict__ Bh, const __nv_bfloat16* __restrict__ Bl, int ldb,
    float* __restrict__ C, int ldc,
    __nv_bfloat16* __restrict__ Ch, __nv_bfloat16* __restrict__ Cl, int ldc2, int c2off,
    int K, const float* __restrict__ bias, float alpha, int act)
{
    extern __shared__ char sm[];
    int tid = threadIdx.x, lane = tid & 31, wid = tid >> 5;
    int wm = wid & 3, wn = wid >> 2;
    int row0 = blockIdx.y * 128, col0 = blockIdx.x * 64;
    Ah += (size_t)row0 * lda; Al += (size_t)row0 * lda;
    Bh += (size_t)col0 * ldb; Bl += (size_t)col0 * ldb;

    uint32_t sbase = smem_u32(sm);
    int nkb = K >> 6;

    auto issue = [&](int kb, int st){
        uint32_t su = sbase + st * 49152;
        int k0 = kb << 6;
#pragma unroll
        for (int it = 0; it < 4; it++){
            int i = tid + it * 256;
            int row = i >> 3, seg = i & 7;
            size_t goff = (size_t)row * lda + k0 + seg * 8;
            uint32_t so = row * 128 + ((seg ^ (row & 7)) << 4);
            cpa16(su + so,         Ah + goff);
            cpa16(su + 16384 + so, Al + goff);
        }
#pragma unroll
        for (int it = 0; it < 2; it++){
            int i = tid + it * 256;
            int row = i >> 3, seg = i & 7;
            size_t goff = (size_t)row * ldb + k0 + seg * 8;
            uint32_t so = row * 128 + ((seg ^ (row & 7)) << 4);
            cpa16(su + 32768 + so, Bh + goff);
            cpa16(su + 40960 + so, Bl + goff);
        }
        cpa_commit();
    };

    issue(0, 0);
    if (nkb > 1) issue(1, 1);

    float acc[2][4][4] = {};
    for (int kb = 0; kb < nkb; kb++){
        if (kb + 1 < nkb) asm volatile("cp.async.wait_group 1;" ::: "memory");
        else              asm volatile("cp.async.wait_group 0;" ::: "memory");
        __syncthreads();
        uint32_t sb2 = sbase + (kb & 1) * 49152;
#pragma unroll
        for (int ks = 0; ks < 4; ks++){
            uint32_t a_h[2][4], a_l[2][4], b_h[4][2], b_l[4][2];
#pragma unroll
            for (int mt = 0; mt < 2; mt++){
                int r = wm * 32 + mt * 16 + (lane & 15);
                int seg = ks * 2 + (lane >> 4);
                uint32_t ad = sb2 + r * 128 + ((seg ^ (r & 7)) << 4);
                ldm_x4(a_h[mt], ad);
                ldm_x4(a_l[mt], ad + 16384);
            }
#pragma unroll
            for (int nt = 0; nt < 4; nt++){
                int r = wn * 32 + nt * 8 + (lane & 7);
                int seg = ks * 2 + ((lane >> 3) & 1);
                uint32_t bd = sb2 + 32768 + r * 128 + ((seg ^ (r & 7)) << 4);
                ldm_x2(b_h[nt], bd);
                ldm_x2(b_l[nt], bd + 8192);
            }
#pragma unroll
            for (int mt = 0; mt < 2; mt++)
#pragma unroll
                for (int nt = 0; nt < 4; nt++){
                    mma_bf16(acc[mt][nt], a_h[mt], b_h[nt]);
                    mma_bf16(acc[mt][nt], a_h[mt], b_l[nt]);
                    mma_bf16(acc[mt][nt], a_l[mt], b_h[nt]);
                }
        }
        __syncthreads();
        if (kb + 2 < nkb) issue(kb + 2, kb & 1);
    }

#pragma unroll
    for (int mt = 0; mt < 2; mt++){
#pragma unroll
        for (int nt = 0; nt < 4; nt++){
            int r0 = row0 + wm * 32 + mt * 16 + (lane >> 2);
            int c0 = col0 + wn * 32 + nt * 8 + ((lane & 3) << 1);
#pragma unroll
            for (int q = 0; q < 4; q++){
                int r = r0 + (q >> 1) * 8;
                int cc = c0 + (q & 1);
                float v = acc[mt][nt][q] * alpha;
                if (bias) v += bias[cc];
                if (act == 1) v = fmaxf(v, 0.f);
                if (C) C[(size_t)r * ldc + cc] = v;
                if (Ch) f2hl(v, Ch, Cl, (size_t)r * ldc2 + c2off + cc);
            }
        }
    }
}

// ================= flash attention =================
__global__ void __launch_bounds__(256) k_flash(
    const __nv_bfloat16* __restrict__ qkvh, const __nv_bfloat16* __restrict__ qkvl,
    const __nv_bfloat16* __restrict__ vth, const __nv_bfloat16* __restrict__ vtl,
    __nv_bfloat16* __restrict__ Oh, __nv_bfloat16* __restrict__ Ol)
{
    extern __shared__ char sm[];
    int tid = threadIdx.x, lane = tid & 31, wid = tid >> 5;
    int head = blockIdx.y;
    int row0 = blockIdx.x * 128;
    uint32_t sb = smem_u32(sm);

    const __nv_bfloat16* Qh = qkvh + (size_t)row0 * 768 + head * 64;
    const __nv_bfloat16* Ql = qkvl + (size_t)row0 * 768 + head * 64;
    const __nv_bfloat16* Kh = qkvh + 256 + head * 64;
    const __nv_bfloat16* Kl = qkvl + 256 + head * 64;
    const __nv_bfloat16* Vh = vth + (size_t)head * 64 * 4096;
    const __nv_bfloat16* Vl = vtl + (size_t)head * 64 * 4096;

#pragma unroll
    for (int it = 0; it < 4; it++){
        int i = tid + it * 256;
        int r = i >> 3, seg = i & 7;
        uint32_t so = r * 128 + ((seg ^ (r & 7)) << 4);
        cpa16(sb + so,         Qh + (size_t)r * 768 + seg * 8);
        cpa16(sb + 16384 + so, Ql + (size_t)r * 768 + seg * 8);
    }
#pragma unroll
    for (int it = 0; it < 2; it++){
        int i = tid + it * 256;
        int r = i >> 3, seg = i & 7;
        uint32_t so = r * 128 + ((seg ^ (r & 7)) << 4);
        cpa16(sb + 32768 + so,         Kh + (size_t)r * 768 + seg * 8);
        cpa16(sb + 32768 + 8192 + so,  Kl + (size_t)r * 768 + seg * 8);
        cpa16(sb + 32768 + 16384 + so, Vh + (size_t)r * 4096 + seg * 8);
        cpa16(sb + 32768 + 24576 + so, Vl + (size_t)r * 4096 + seg * 8);
    }
    cpa_commit();
    asm volatile("cp.async.wait_group 0;" ::: "memory");
    __syncthreads();

    uint32_t qf_h[4][4], qf_l[4][4];
#pragma unroll
    for (int ks = 0; ks < 4; ks++){
        int r = wid * 16 + (lane & 15);
        int seg = ks * 2 + (lane >> 4);
        uint32_t ad = sb + r * 128 + ((seg ^ (r & 7)) << 4);
        ldm_x4(qf_h[ks], ad);
        ldm_x4(qf_l[ks], ad + 16384);
    }

    float m0 = -1e30f, m1 = -1e30f, l0 = 0.f, l1 = 0.f;
    float acc_o[8][4] = {};
    int buf = 0;

    for (int kt = 0; kt < 64; kt++){
        if (kt < 63){
            uint32_t bo = sb + 32768 + (buf ^ 1) * 32768;
            int key0 = (kt + 1) * 64;
#pragma unroll
            for (int it = 0; it < 2; it++){
                int i = tid + it * 256;
                int r = i >> 3, seg = i & 7;
                uint32_t so = r * 128 + ((seg ^ (r & 7)) << 4);
                cpa16(bo + so,         Kh + (size_t)(key0 + r) * 768 + seg * 8);
                cpa16(bo + 8192 + so,  Kl + (size_t)(key0 + r) * 768 + seg * 8);
                cpa16(bo + 16384 + so, Vh + (size_t)r * 4096 + key0 + seg * 8);
                cpa16(bo + 24576 + so, Vl + (size_t)r * 4096 + key0 + seg * 8);
            }
            cpa_commit();
            asm volatile("cp.async.wait_group 1;" ::: "memory");
        } else {
            asm volatile("cp.async.wait_group 0;" ::: "memory");
        }
        __syncthreads();

        uint32_t kb = sb + 32768 + buf * 32768;

        float acc_s[8][4] = {};
#pragma unroll
        for (int ks = 0; ks < 4; ks++){
            uint32_t bh[8][2], bl[8][2];
#pragma unroll
            for (int nt = 0; nt < 8; nt++){
                int r = nt * 8 + (lane & 7);
                int seg = ks * 2 + ((lane >> 3) & 1);
                uint32_t bd = kb + r * 128 + ((seg ^ (r & 7)) << 4);
                ldm_x2(bh[nt], bd);
                ldm_x2(bl[nt], bd + 8192);
            }
#pragma unroll
            for (int nt = 0; nt < 8; nt++){
                mma_bf16(acc_s[nt], qf_h[ks], bh[nt]);
                mma_bf16(acc_s[nt], qf_h[ks], bl[nt]);
                mma_bf16(acc_s[nt], qf_l[ks], bh[nt]);
            }
        }
#pragma unroll
        for (int nt = 0; nt < 8; nt++){
            acc_s[nt][0] *= 0.125f; acc_s[nt][1] *= 0.125f;
            acc_s[nt][2] *= 0.125f; acc_s[nt][3] *= 0.125f;
        }

        float tm0 = -1e30f, tm1 = -1e30f;
#pragma unroll
        for (int nt = 0; nt < 8; nt++){
            tm0 = fmaxf(tm0, fmaxf(acc_s[nt][0], acc_s[nt][1]));
            tm1 = fmaxf(tm1, fmaxf(acc_s[nt][2], acc_s[nt][3]));
        }
        tm0 = fmaxf(tm0, __shfl_xor_sync(~0u, tm0, 1)); tm0 = fmaxf(tm0, __shfl_xor_sync(~0u, tm0, 2));
        tm1 = fmaxf(tm1, __shfl_xor_sync(~0u, tm1, 1)); tm1 = fmaxf(tm1, __shfl_xor_sync(~0u, tm1, 2));
        float mn0 = fmaxf(m0, tm0), mn1 = fmaxf(m1, tm1);
        float sc0 = __expf(m0 - mn0), sc1 = __expf(m1 - mn1);
        m0 = mn0; m1 = mn1;
        l0 *= sc0; l1 *= sc1;
#pragma unroll
        for (int nt = 0; nt < 8; nt++){
            acc_o[nt][0] *= sc0; acc_o[nt][1] *= sc0;
            acc_o[nt][2] *= sc1; acc_o[nt][3] *= sc1;
        }
        float rs0 = 0.f, rs1 = 0.f;
        uint32_t pa_h[4][4], pa_l[4][4];
#pragma unroll
        for (int nt = 0; nt < 8; nt++){
            float p0 = __expf(acc_s[nt][0] - mn0), p1 = __expf(acc_s[nt][1] - mn0);
            float p2 = __expf(acc_s[nt][2] - mn1), p3 = __expf(acc_s[nt][3] - mn1);
            rs0 += p0 + p1; rs1 += p2 + p3;
            int k2 = nt >> 1;
            if (!(nt & 1)){
                splitpack(p0, p1, pa_h[k2][0], pa_l[k2][0]);
                splitpack(p2, p3, pa_h[k2][1], pa_l[k2][1]);
            } else {
                splitpack(p0, p1, pa_h[k2][2], pa_l[k2][2]);
                splitpack(p2, p3, pa_h[k2][3], pa_l[k2][3]);
            }
        }
        rs0 += __shfl_xor_sync(~0u, rs0, 1); rs0 += __shfl_xor_sync(~0u, rs0, 2);
        rs1 += __shfl_xor_sync(~0u, rs1, 1); rs1 += __shfl_xor_sync(~0u, rs1, 2);
        l0 += rs0; l1 += rs1;

        uint32_t vb = kb + 16384;
#pragma unroll
        for (int k2 = 0; k2 < 4; k2++){
            uint32_t vh[8][2], vl[8][2];
#pragma unroll
            for (int nt = 0; nt < 8; nt++){
                int r = nt * 8 + (lane & 7);
                int seg = k2 * 2 + ((lane >> 3) & 1);
                uint32_t vd = vb + r * 128 + ((seg ^ (r & 7)) << 4);
                ldm_x2(vh[nt], vd);
                ldm_x2(vl[nt], vd + 8192);
            }
#pragma unroll
            for (int nt = 0; nt < 8; nt++){
                mma_bf16(acc_o[nt], pa_h[k2], vh[nt]);
                mma_bf16(acc_o[nt], pa_h[k2], vl[nt]);
                mma_bf16(acc_o[nt], pa_l[k2], vh[nt]);
            }
        }
        __syncthreads();
        buf ^= 1;
    }

    float inv0 = 1.f / l0, inv1 = 1.f / l1;
    int r = row0 + wid * 16 + (lane >> 2);
#pragma unroll
    for (int nt = 0; nt < 8; nt++){
        int cc = head * 64 + nt * 8 + ((lane & 3) << 1);
        f2hl(acc_o[nt][0] * inv0, Oh, Ol, (size_t)r * 256 + cc);
        f2hl(acc_o[nt][1] * inv0, Oh, Ol, (size_t)r * 256 + cc + 1);
        f2hl(acc_o[nt][2] * inv1, Oh, Ol, (size_t)(r + 8) * 256 + cc);
        f2hl(acc_o[nt][3] * inv1, Oh, Ol, (size_t)(r + 8) * 256 + cc + 1);
    }
}

// ================= pointwise =================
__global__ void k_lstm(const float* __restrict__ G, float* __restrict__ ht_out,
                       __nv_bfloat16* __restrict__ Hh, __nv_bfloat16* __restrict__ Hl){
    int idx = blockIdx.x * 256 + threadIdx.x;
    int n = idx >> 8, j = idx & 255;
    const float* gr = G + (size_t)n * 1024;
    float ig = gr[j], gg = gr[512 + j], og = gr[768 + j];
    float cc = sigmf(ig) * tanhf(gg);
    float hv = sigmf(og) * tanhf(cc);
    ht_out[idx] = hv;
    f2hl(hv, Hh, Hl, (size_t)n * 512 + j);
}

__global__ void k_vt(const __nv_bfloat16* __restrict__ qh, const __nv_bfloat16* __restrict__ ql,
                     __nv_bfloat16* __restrict__ vh, __nv_bfloat16* __restrict__ vl){
    int idx = blockIdx.x * 256 + threadIdx.x;
    int hd = idx >> 12, n = idx & 4095;
    size_t s = (size_t)n * 768 + 512 + hd;
    vh[idx] = qh[s]; vl[idx] = ql[s];
}

// ================= launch =================
#define SYMADDR(p, s) do { void* _t; cudaGetSymbolAddress(&_t, s); p = (decltype(p))_t; } while(0)

extern "C" void kernel_launch(void* const* d_in, const int* in_sizes, int n_in,
                              void* d_out, int out_size) {
    const float* x     = (const float*)d_in[0];
    const int*   ei_t  = (const int*)d_in[1];
    const int*   ei_c  = (const int*)d_in[2];
    const float* ea_t  = (const float*)d_in[3];
    const float* ea_c  = (const float*)d_in[4];
    const float* W_t   = (const float*)d_in[5];
    const float* asrc_t= (const float*)d_in[6];
    const float* adst_t= (const float*)d_in[7];
    const float* We_t  = (const float*)d_in[8];
    const float* ae_t  = (const float*)d_in[9];
    const float* b_t   = (const float*)d_in[10];
    const float* W_c   = (const float*)d_in[11];
    const float* asrc_c= (const float*)d_in[12];
    const float* adst_c= (const float*)d_in[13];
    const float* We_c  = (const float*)d_in[14];
    const float* ae_c  = (const float*)d_in[15];
    const float* b_c   = (const float*)d_in[16];
    const float* lstm_Wih = (const float*)d_in[17];
    const float* lstm_bih = (const float*)d_in[19];
    const float* lstm_bhh = (const float*)d_in[20];
    const float* mha_in_w  = (const float*)d_in[21];
    const float* mha_in_b  = (const float*)d_in[22];
    const float* mha_out_w = (const float*)d_in[23];
    const float* mha_out_b = (const float*)d_in[24];
    const float* fus_w = (const float*)d_in[25];
    const float* fus_b = (const float*)d_in[26];
    const float* out_w = (const float*)d_in[27];
    const float* out_b = (const float*)d_in[28];

    float* big; SYMADDR(big, g_big);
    __nv_bfloat16 *hth, *htl, *hch, *hcl, *qkvh, *qkvl, *vth, *vtl;
    __nv_bfloat16 *attnh, *attnl, *hcath, *hcatl, *hfush, *hfusl;
    __nv_bfloat16 *wihh, *wihl, *inwh, *inwl, *mowh, *mowl, *fuwh, *fuwl, *owh, *owl;
    SYMADDR(hth, g_hth); SYMADDR(htl, g_htl); SYMADDR(hch, g_hch); SYMADDR(hcl, g_hcl);
    SYMADDR(qkvh, g_qkvh); SYMADDR(qkvl, g_qkvl); SYMADDR(vth, g_vth); SYMADDR(vtl, g_vtl);
    SYMADDR(attnh, g_attnh); SYMADDR(attnl, g_attnl);
    SYMADDR(hcath, g_hcath); SYMADDR(hcatl, g_hcatl);
    SYMADDR(hfush, g_hfush); SYMADDR(hfusl, g_hfusl);
    SYMADDR(wihh, g_wihh); SYMADDR(wihl, g_wihl);
    SYMADDR(inwh, g_inwh); SYMADDR(inwl, g_inwl);
    SYMADDR(mowh, g_mowh); SYMADDR(mowl, g_mowl);
    SYMADDR(fuwh, g_fuwh); SYMADDR(fuwl, g_fuwl);
    SYMADDR(owh, g_owh); SYMADDR(owl, g_owl);

    cudaFuncSetAttribute(k_flash, cudaFuncAttributeMaxDynamicSharedMemorySize, 98304);
    cudaFuncSetAttribute(mma_gemm, cudaFuncAttributeMaxDynamicSharedMemorySize, 98304);
    const int DYN = 98304;
    const int DYN_FA = 98304;

    float* out_main = (float*)d_out;
    float* out_ht   = out_main + (size_t)NNODE * NOUT;
    float* out_hc   = out_ht   + (size_t)NNODE * HID;

    const int* src_t = ei_t; const int* dst_t = ei_t + NE;
    const int* src_c = ei_c; const int* dst_c = ei_c + NE;
    int nepb = (NEP + 255) / 256, neb = (NE + 255) / 256;

    k_initmean<<<128, 256>>>(ea_t, ea_c);
    k_setup<<<1, 256>>>(We_t, ae_t, We_c, ae_c, lstm_bih, lstm_bhh);
    k_convall<<<CW4 / 256, 256>>>(lstm_Wih, mha_in_w, mha_out_w, fus_w, out_w);

    // ---- GATs ----
    k_xp2<<<dim3(8, 256), 256>>>(x, W_t, 0);
    k_xp2<<<dim3(8, 256), 256>>>(x, W_c, 1);
    k_asd<<<NNODE, 256>>>(asrc_t, adst_t, 0);
    k_asd<<<NNODE, 256>>>(asrc_c, adst_c, 1);
    k_count<<<neb, 256>>>(dst_t, 0);
    k_count<<<neb, 256>>>(dst_c, 1);
    k_scan<<<2, 1024>>>();
    k_scatter<<<neb, 256>>>(dst_t, 0);
    k_scatter<<<neb, 256>>>(dst_c, 1);
    k_alpha<<<nepb, 256>>>(src_t, dst_t, ea_t, 0);
    k_alpha<<<nepb, 256>>>(src_c, dst_c, ea_c, 1);
    k_ex<<<nepb, 256>>>(dst_t, 0);
    k_ex<<<nepb, 256>>>(dst_c, 1);
    k_agg<<<NNODE, 256>>>(src_t, 0, b_t, hth, htl, 1);
    k_agg<<<NNODE, 256>>>(src_c, 1, b_c, hch, hcl, 0);

    // ---- temporal: LSTM gates (4096x1024x2048) ----
    mma_gemm<<<dim3(16, 32), 256, DYN>>>(
        hth, htl, NHC, wihh, wihl, NHC,
        big + OFF_G, 1024, nullptr, nullptr, 0, 0,
        NHC, big + OFF_BSUM, 1.f, 0);
    k_lstm<<<NNODE, 256>>>(big + OFF_G, out_ht, hcath, hcatl);

    // ---- causal: qkv (4096x768x256) ----
    mma_gemm<<<dim3(12, 32), 256, DYN>>>(
        hch, hcl, 256, inwh, inwl, 256,
        nullptr, 0, qkvh, qkvl, 768, 0,
        256, mha_in_b, 1.f, 0);
    k_vt<<<(4*64*NNODE)/256, 256>>>(qkvh, qkvl, vth, vtl);

    // ---- fused attention ----
    k_flash<<<dim3(32, 4), 256, DYN_FA>>>(qkvh, qkvl, vth, vtl, attnh, attnl);

    // ---- proj (4096x256x256) ----
    mma_gemm<<<dim3(4, 32), 256, DYN>>>(
        attnh, attnl, 256, mowh, mowl, 256,
        out_hc, 256, hcath, hcatl, 512, 256,
        256, mha_out_b, 1.f, 0);

    // ---- fusion relu (4096x256x512) ----
    mma_gemm<<<dim3(4, 32), 256, DYN>>>(
        hcath, hcatl, 512, fuwh, fuwl, 512,
        nullptr, 0, hfush, hfusl, 256, 0,
        512, fus_b, 1.f, 1);

    // ---- out (4096x128x256) ----
    mma_gemm<<<dim3(2, 32), 256, DYN>>>(
        hfush, hfusl, 256, owh, owl, 256,
        out_main, NOUT, nullptr, nullptr, 0, 0,
        256, out_b, 1.f, 0);
}

// round 7
// speedup vs baseline: 2.3117x; 1.0422x over previous
#include <cuda_runtime.h>
#include <cuda_bf16.h>
#include <math.h>
#include <float.h>
#include <stdint.h>

#define NNODE 4096
#define NIN   28
#define NE    131072
#define NEP   (NE + NNODE)
#define NH    8
#define NC    256
#define NHC   2048
#define HID   256
#define NOUT  128

// ---------------- fp32 scratch ----------------
#define OFF_G    ((size_t)0)
#define OFF_BSUM (OFF_G + (size_t)NNODE * 1024)
#define BIG_SZ   (OFF_BSUM + 1024)
__device__ float g_big[BIG_SZ];

__device__ float g_xp[2][(size_t)NNODE * NHC];
__device__ float g_as[2][NNODE * NH];
__device__ float g_ad[2][NNODE * NH];
__device__ float g_w [2][(size_t)NEP * NH];
__device__ int   g_mx[2][NNODE * NH];
__device__ float g_den[2][NNODE * NH];
__device__ int   g_cnt[2][NNODE];
__device__ int   g_cur[2][NNODE];
__device__ int   g_start[2][NNODE];
__device__ int   g_sorted[2][NE];
__device__ float g_part[2][128];
__device__ float g_mean[2];
__device__ float g_ce[2][NH];

// flash split-K partials
__device__ float g_po[(size_t)2 * NNODE * 256];
__device__ float g_pml[(size_t)2 * NNODE * 8];

// ---------------- bf16 hi/lo tensors ----------------
__device__ __nv_bfloat16 g_hth[(size_t)NNODE * NHC], g_htl[(size_t)NNODE * NHC];
__device__ __nv_bfloat16 g_hch[(size_t)NNODE * 256], g_hcl[(size_t)NNODE * 256];
__device__ __nv_bfloat16 g_qkvh[(size_t)NNODE * 768], g_qkvl[(size_t)NNODE * 768];
__device__ __nv_bfloat16 g_vth[(size_t)4 * 64 * NNODE], g_vtl[(size_t)4 * 64 * NNODE];
__device__ __nv_bfloat16 g_attnh[(size_t)NNODE * 256], g_attnl[(size_t)NNODE * 256];
__device__ __nv_bfloat16 g_hcath[(size_t)NNODE * 512], g_hcatl[(size_t)NNODE * 512];
__device__ __nv_bfloat16 g_hfush[(size_t)NNODE * 256], g_hfusl[(size_t)NNODE * 256];
// weights
__device__ __nv_bfloat16 g_wihh[1024 * 2048], g_wihl[1024 * 2048];
__device__ __nv_bfloat16 g_inwh[768 * 256],   g_inwl[768 * 256];
__device__ __nv_bfloat16 g_mowh[256 * 256],   g_mowl[256 * 256];
__device__ __nv_bfloat16 g_fuwh[256 * 512],   g_fuwl[256 * 512];
__device__ __nv_bfloat16 g_owh[128 * 256],    g_owl[128 * 256];

// ---------------- helpers ----------------
__device__ __forceinline__ int   f2ord(float f){ int i = __float_as_int(f); return i >= 0 ? i : i ^ 0x7fffffff; }
__device__ __forceinline__ float ord2f(int k){ return __int_as_float(k >= 0 ? k : k ^ 0x7fffffff); }
__device__ __forceinline__ float sigmf(float x){ return 1.f / (1.f + expf(-x)); }
__device__ __forceinline__ void f2hl(float v, __nv_bfloat16* H, __nv_bfloat16* L, size_t i){
    __nv_bfloat16 h = __float2bfloat16(v);
    H[i] = h; L[i] = __float2bfloat16(v - __bfloat162float(h));
}
__device__ __forceinline__ uint32_t smem_u32(const void* p){
    uint32_t a;
    asm("{ .reg .u64 t; cvta.to.shared.u64 t, %1; cvt.u32.u64 %0, t; }" : "=r"(a) : "l"(p));
    return a;
}
__device__ __forceinline__ void ldm_x4(uint32_t* r, uint32_t addr){
    asm volatile("ldmatrix.sync.aligned.m8n8.x4.shared.b16 {%0,%1,%2,%3}, [%4];"
        : "=r"(r[0]), "=r"(r[1]), "=r"(r[2]), "=r"(r[3]) : "r"(addr));
}
__device__ __forceinline__ void ldm_x2(uint32_t* r, uint32_t addr){
    asm volatile("ldmatrix.sync.aligned.m8n8.x2.shared.b16 {%0,%1}, [%2];"
        : "=r"(r[0]), "=r"(r[1]) : "r"(addr));
}
__device__ __forceinline__ void mma_bf16(float* c, const uint32_t* a, const uint32_t* b){
    asm volatile("mma.sync.aligned.m16n8k16.row.col.f32.bf16.bf16.f32 "
        "{%0,%1,%2,%3}, {%4,%5,%6,%7}, {%8,%9}, {%0,%1,%2,%3};"
        : "+f"(c[0]), "+f"(c[1]), "+f"(c[2]), "+f"(c[3])
        : "r"(a[0]), "r"(a[1]), "r"(a[2]), "r"(a[3]), "r"(b[0]), "r"(b[1]));
}
__device__ __forceinline__ void cpa16(uint32_t saddr, const void* g){
    asm volatile("cp.async.ca.shared.global [%0], [%1], 16;" :: "r"(saddr), "l"(g));
}
__device__ __forceinline__ void cpa_commit(){ asm volatile("cp.async.commit_group;" ::: "memory"); }
__device__ __forceinline__ void splitpack(float a, float b, uint32_t& hi, uint32_t& lo){
    __nv_bfloat16 ha = __float2bfloat16(a), hb = __float2bfloat16(b);
    __nv_bfloat16 la = __float2bfloat16(a - __bfloat162float(ha));
    __nv_bfloat16 lb = __float2bfloat16(b - __bfloat162float(hb));
    hi = ((uint32_t)__bfloat16_as_ushort(hb) << 16) | (uint32_t)__bfloat16_as_ushort(ha);
    lo = ((uint32_t)__bfloat16_as_ushort(lb) << 16) | (uint32_t)__bfloat16_as_ushort(la);
}

// ================= setup =================
__global__ void k_initmean(const float* __restrict__ ea_t, const float* __restrict__ ea_c){
    int idx = blockIdx.x * 256 + threadIdx.x, stride = gridDim.x * 256;
    int mi = f2ord(-FLT_MAX);
    for (int i = idx; i < NNODE * NH; i += stride){
        g_mx[0][i] = mi; g_mx[1][i] = mi;
        g_den[0][i] = 0.f; g_den[1][i] = 0.f;
    }
    for (int i = idx; i < NNODE; i += stride){
        g_cnt[0][i] = 0; g_cnt[1][i] = 0;
        g_cur[0][i] = 0; g_cur[1][i] = 0;
    }
    __shared__ float s0[256], s1[256];
    float a = 0.f, b = 0.f;
    for (int i = blockIdx.x * 256 + threadIdx.x; i < NE; i += 128 * 256){ a += ea_t[i]; b += ea_c[i]; }
    s0[threadIdx.x] = a; s1[threadIdx.x] = b; __syncthreads();
    for (int s = 128; s; s >>= 1){
        if (threadIdx.x < s){ s0[threadIdx.x] += s0[threadIdx.x+s]; s1[threadIdx.x] += s1[threadIdx.x+s]; }
        __syncthreads();
    }
    if (!threadIdx.x){ g_part[0][blockIdx.x] = s0[0]; g_part[1][blockIdx.x] = s1[0]; }
}

__global__ void k_setup(const float* __restrict__ We_t, const float* __restrict__ ae_t,
                        const float* __restrict__ We_c, const float* __restrict__ ae_c,
                        const float* __restrict__ bih,  const float* __restrict__ bhh){
    __shared__ float sh[256];
    int tid = threadIdx.x;
    for (int g = 0; g < 2; g++){
        sh[tid] = (tid < 128) ? g_part[g][tid] : 0.f;
        __syncthreads();
        for (int s = 128; s; s >>= 1){ if (tid < s) sh[tid] += sh[tid+s]; __syncthreads(); }
        if (!tid) g_mean[g] = sh[0] / (float)NE;
        __syncthreads();
    }
    int wid = tid >> 5, lane = tid & 31;
    for (int c = wid; c < 16; c += 8){
        int g = c >> 3, h = c & 7;
        const float* We = g ? We_c : We_t;
        const float* ae = g ? ae_c : ae_t;
        float s = 0.f;
        for (int i = lane; i < NC; i += 32) s = fmaf(We[h*NC + i], ae[h*NC + i], s);
        for (int o = 16; o; o >>= 1) s += __shfl_down_sync(0xffffffffu, s, o);
        if (!lane) g_ce[g][h] = s;
    }
    for (int j = tid; j < 1024; j += 256) g_big[OFF_BSUM + j] = bih[j] + bhh[j];
}

#define CW0 2097152
#define CW1 (CW0 + 196608)
#define CW2 (CW1 + 65536)
#define CW3 (CW2 + 131072)
#define CW4 (CW3 + 32768)
__global__ void k_convall(const float* __restrict__ w0, const float* __restrict__ w1,
                          const float* __restrict__ w2, const float* __restrict__ w3,
                          const float* __restrict__ w4){
    int i = blockIdx.x * 256 + threadIdx.x;
    if (i < CW0)      f2hl(w0[i], g_wihh, g_wihl, i);
    else if (i < CW1) f2hl(w1[i - CW0], g_inwh, g_inwl, i - CW0);
    else if (i < CW2) f2hl(w2[i - CW1], g_mowh, g_mowl, i - CW1);
    else if (i < CW3) f2hl(w3[i - CW2], g_fuwh, g_fuwl, i - CW2);
    else if (i < CW4) f2hl(w4[i - CW3], g_owh, g_owl, i - CW3);
}

// ================= GAT (both graphs per launch) =================
__global__ void __launch_bounds__(256) k_xp2(const float* __restrict__ x,
                                             const float* __restrict__ W_t,
                                             const float* __restrict__ W_c){
    __shared__ float Ws[NIN][256];
    __shared__ float xs[16][32];
    int g = blockIdx.z;
    const float* W = g ? W_c : W_t;
    int tid = threadIdx.x;
    int col = blockIdx.x * 256 + tid;
    int n0 = blockIdx.y * 16;
#pragma unroll
    for (int k = 0; k < NIN; k++) Ws[k][tid] = W[k * NHC + col];
    for (int i = tid; i < 16 * NIN; i += 256){ int n = i / NIN, k = i % NIN; xs[n][k] = x[(size_t)(n0 + n) * NIN + k]; }
    for (int i = tid; i < 16 * 4; i += 256) xs[i >> 2][NIN + (i & 3)] = 0.f;
    __syncthreads();
    float acc[16] = {};
    for (int k0 = 0; k0 < 28; k0 += 4){
        float w0 = Ws[k0][tid], w1 = Ws[k0+1][tid], w2 = Ws[k0+2][tid], w3 = Ws[k0+3][tid];
#pragma unroll
        for (int n = 0; n < 16; n++){
            float4 xv = *(const float4*)&xs[n][k0];
            acc[n] = fmaf(xv.x, w0, fmaf(xv.y, w1, fmaf(xv.z, w2, fmaf(xv.w, w3, acc[n]))));
        }
    }
#pragma unroll
    for (int n = 0; n < 16; n++) g_xp[g][(size_t)(n0 + n) * NHC + col] = acc[n];
}

__global__ void k_asd(const float* __restrict__ asrc_t, const float* __restrict__ adst_t,
                      const float* __restrict__ asrc_c, const float* __restrict__ adst_c){
    int g = blockIdx.y;
    const float* asrc = g ? asrc_c : asrc_t;
    const float* adst = g ? adst_c : adst_t;
    int n = blockIdx.x, h = threadIdx.x >> 5, lane = threadIdx.x & 31;
    const float* xr = g_xp[g] + (size_t)n * NHC + h * NC;
    float s1 = 0.f, s2 = 0.f;
    for (int c = lane; c < NC; c += 32){
        float v = xr[c];
        s1 = fmaf(v, asrc[h*NC + c], s1);
        s2 = fmaf(v, adst[h*NC + c], s2);
    }
    for (int o = 16; o; o >>= 1){ s1 += __shfl_down_sync(~0u, s1, o); s2 += __shfl_down_sync(~0u, s2, o); }
    if (!lane){ g_as[g][n*NH + h] = s1; g_ad[g][n*NH + h] = s2; }
}

__global__ void k_count(const int* __restrict__ dst_t, const int* __restrict__ dst_c){
    int g = blockIdx.y;
    const int* dst = g ? dst_c : dst_t;
    int e = blockIdx.x * 256 + threadIdx.x;
    if (e < NE) atomicAdd(&g_cnt[g][dst[e]], 1);
}

__global__ void k_scan(){
    int g = blockIdx.x, tid = threadIdx.x;
    __shared__ int sh[1024];
    int base = tid * 4;
    int c0 = g_cnt[g][base], c1 = g_cnt[g][base+1], c2 = g_cnt[g][base+2], c3 = g_cnt[g][base+3];
    int s = c0 + c1 + c2 + c3;
    sh[tid] = s; __syncthreads();
    for (int off = 1; off < 1024; off <<= 1){
        int v = (tid >= off) ? sh[tid - off] : 0;
        __syncthreads();
        sh[tid] += v;
        __syncthreads();
    }
    int excl = sh[tid] - s;
    g_start[g][base]   = excl;
    g_start[g][base+1] = excl + c0;
    g_start[g][base+2] = excl + c0 + c1;
    g_start[g][base+3] = excl + c0 + c1 + c2;
}

__global__ void k_scatter(const int* __restrict__ dst_t, const int* __restrict__ dst_c){
    int g = blockIdx.y;
    const int* dst = g ? dst_c : dst_t;
    int e = blockIdx.x * 256 + threadIdx.x;
    if (e < NE){
        int d = dst[e];
        int pos = g_start[g][d] + atomicAdd(&g_cur[g][d], 1);
        g_sorted[g][pos] = e;
    }
}

__global__ void k_alpha(const int* __restrict__ src_t, const int* __restrict__ dst_t, const float* __restrict__ ea_t,
                        const int* __restrict__ src_c, const int* __restrict__ dst_c, const float* __restrict__ ea_c){
    int g = blockIdx.y;
    const int* src = g ? src_c : src_t;
    const int* dst = g ? dst_c : dst_t;
    const float* ea = g ? ea_c : ea_t;
    int e = blockIdx.x * 256 + threadIdx.x;
    if (e >= NEP) return;
    int s, d; float av;
    if (e < NE){ s = src[e]; d = dst[e]; av = ea[e]; }
    else { s = d = e - NE; av = g_mean[g]; }
#pragma unroll
    for (int h = 0; h < NH; h++){
        float al = g_as[g][s*NH + h] + g_ad[g][d*NH + h] + av * g_ce[g][h];
        al = al > 0.f ? al : 0.2f * al;
        g_w[g][(size_t)e * NH + h] = al;
        atomicMax(&g_mx[g][d*NH + h], f2ord(al));
    }
}

__global__ void k_ex(const int* __restrict__ dst_t, const int* __restrict__ dst_c){
    int g = blockIdx.y;
    const int* dst = g ? dst_c : dst_t;
    int e = blockIdx.x * 256 + threadIdx.x;
    if (e >= NEP) return;
    int d = (e < NE) ? dst[e] : e - NE;
#pragma unroll
    for (int h = 0; h < NH; h++){
        float al = g_w[g][(size_t)e * NH + h];
        float ex = expf(al - ord2f(g_mx[g][d*NH + h]));
        g_w[g][(size_t)e * NH + h] = ex;
        atomicAdd(&g_den[g][d*NH + h], ex);
    }
}

__global__ void __launch_bounds__(256) k_agg(const int* __restrict__ src_t, const int* __restrict__ src_c,
                                             const float* __restrict__ b_t, const float* __restrict__ b_c){
    int g = blockIdx.y;
    const int* src = g ? src_c : src_t;
    const float* bias = g ? b_c : b_t;
    int n = blockIdx.x, t = threadIdx.x;
    const float* xp = g_xp[g];
    const float* w  = g_w[g];
    float acc[NH];
    {
        size_t e = (size_t)(NE + n) * NH;
        const float* xr = xp + (size_t)n * NHC + t;
#pragma unroll
        for (int h = 0; h < NH; h++) acc[h] = w[e + h] * xr[h * NC];
    }
    __shared__ int   ssrc[32];
    __shared__ float sw[32][NH];
    int st = g_start[g][n], c = g_cnt[g][n];
    for (int i0 = 0; i0 < c; i0 += 32){
        int m = min(32, c - i0);
        __syncthreads();
        if (t < m) ssrc[t] = src[g_sorted[g][st + i0 + t]];
        {
            int j = t >> 3, h = t & 7;
            if (j < m) sw[j][h] = w[(size_t)g_sorted[g][st + i0 + j] * NH + h];
        }
        __syncthreads();
        for (int jj = 0; jj < m; jj++){
            const float* xr = xp + (size_t)ssrc[jj] * NHC + t;
#pragma unroll
            for (int h = 0; h < NH; h++) acc[h] = fmaf(sw[jj][h], xr[h * NC], acc[h]);
        }
    }
    const float* den = g_den[g] + n * NH;
    if (g == 0){
#pragma unroll
        for (int h = 0; h < NH; h++){
            float v = acc[h] / (den[h] + 1e-16f) + bias[h * NC + t];
            f2hl(v, g_hth, g_htl, (size_t)n * NHC + h * NC + t);
        }
    } else {
        float s = 0.f;
#pragma unroll
        for (int h = 0; h < NH; h++) s += acc[h] / (den[h] + 1e-16f);
        f2hl(s * 0.125f + bias[t], g_hch, g_hcl, (size_t)n * NC + t);
    }
}

// ================= HMMA bf16x3 GEMM (cp.async 2-stage pipelined) =================
__global__ void __launch_bounds__(256) mma_gemm(
    const __nv_bfloat16* __restrict__ Ah, const __nv_bfloat16* __restrict__ Al, int lda,
    const __nv_bfloat16* __restrict__ Bh, const __nv_bfloat16* __restrict__ Bl, int ldb,
    float* __restrict__ C, int ldc,
    __nv_bfloat16* __restrict__ Ch, __nv_bfloat16* __restrict__ Cl, int ldc2, int c2off,
    int K, const float* __restrict__ bias, float alpha, int act)
{
    extern __shared__ char sm[];
    int tid = threadIdx.x, lane = tid & 31, wid = tid >> 5;
    int wm = wid & 3, wn = wid >> 2;
    int row0 = blockIdx.y * 128, col0 = blockIdx.x * 64;
    Ah += (size_t)row0 * lda; Al += (size_t)row0 * lda;
    Bh += (size_t)col0 * ldb; Bl += (size_t)col0 * ldb;

    uint32_t sbase = smem_u32(sm);
    int nkb = K >> 6;

    auto issue = [&](int kb, int st){
        uint32_t su = sbase + st * 49152;
        int k0 = kb << 6;
#pragma unroll
        for (int it = 0; it < 4; it++){
            int i = tid + it * 256;
            int row = i >> 3, seg = i & 7;
            size_t goff = (size_t)row * lda + k0 + seg * 8;
            uint32_t so = row * 128 + ((seg ^ (row & 7)) << 4);
            cpa16(su + so,         Ah + goff);
            cpa16(su + 16384 + so, Al + goff);
        }
#pragma unroll
        for (int it = 0; it < 2; it++){
            int i = tid + it * 256;
            int row = i >> 3, seg = i & 7;
            size_t goff = (size_t)row * ldb + k0 + seg * 8;
            uint32_t so = row * 128 + ((seg ^ (row & 7)) << 4);
            cpa16(su + 32768 + so, Bh + goff);
            cpa16(su + 40960 + so, Bl + goff);
        }
        cpa_commit();
    };

    issue(0, 0);
    if (nkb > 1) issue(1, 1);

    float acc[2][4][4] = {};
    for (int kb = 0; kb < nkb; kb++){
        if (kb + 1 < nkb) asm volatile("cp.async.wait_group 1;" ::: "memory");
        else              asm volatile("cp.async.wait_group 0;" ::: "memory");
        __syncthreads();
        uint32_t sb2 = sbase + (kb & 1) * 49152;
#pragma unroll
        for (int ks = 0; ks < 4; ks++){
            uint32_t a_h[2][4], a_l[2][4], b_h[4][2], b_l[4][2];
#pragma unroll
            for (int mt = 0; mt < 2; mt++){
                int r = wm * 32 + mt * 16 + (lane & 15);
                int seg = ks * 2 + (lane >> 4);
                uint32_t ad = sb2 + r * 128 + ((seg ^ (r & 7)) << 4);
                ldm_x4(a_h[mt], ad);
                ldm_x4(a_l[mt], ad + 16384);
            }
#pragma unroll
            for (int nt = 0; nt < 4; nt++){
                int r = wn * 32 + nt * 8 + (lane & 7);
                int seg = ks * 2 + ((lane >> 3) & 1);
                uint32_t bd = sb2 + 32768 + r * 128 + ((seg ^ (r & 7)) << 4);
                ldm_x2(b_h[nt], bd);
                ldm_x2(b_l[nt], bd + 8192);
            }
#pragma unroll
            for (int mt = 0; mt < 2; mt++)
#pragma unroll
                for (int nt = 0; nt < 4; nt++){
                    mma_bf16(acc[mt][nt], a_h[mt], b_h[nt]);
                    mma_bf16(acc[mt][nt], a_h[mt], b_l[nt]);
                    mma_bf16(acc[mt][nt], a_l[mt], b_h[nt]);
                }
        }
        __syncthreads();
        if (kb + 2 < nkb) issue(kb + 2, kb & 1);
    }

#pragma unroll
    for (int mt = 0; mt < 2; mt++){
#pragma unroll
        for (int nt = 0; nt < 4; nt++){
            int r0 = row0 + wm * 32 + mt * 16 + (lane >> 2);
            int c0 = col0 + wn * 32 + nt * 8 + ((lane & 3) << 1);
#pragma unroll
            for (int q = 0; q < 4; q++){
                int r = r0 + (q >> 1) * 8;
                int cc = c0 + (q & 1);
                float v = acc[mt][nt][q] * alpha;
                if (bias) v += bias[cc];
                if (act == 1) v = fmaxf(v, 0.f);
                if (C) C[(size_t)r * ldc + cc] = v;
                if (Ch) f2hl(v, Ch, Cl, (size_t)r * ldc2 + c2off + cc);
            }
        }
    }
}

// ================= flash attention (split-KV, 2 partials) =================
// grid (32 row-tiles, 4 heads, 2 kv-splits), 256 threads.
__global__ void __launch_bounds__(256) k_flash(
    const __nv_bfloat16* __restrict__ qkvh, const __nv_bfloat16* __restrict__ qkvl,
    const __nv_bfloat16* __restrict__ vth, const __nv_bfloat16* __restrict__ vtl,
    float* __restrict__ pO, float* __restrict__ pML)
{
    extern __shared__ char sm[];
    int tid = threadIdx.x, lane = tid & 31, wid = tid >> 5;
    int head = blockIdx.y;
    int row0 = blockIdx.x * 128;
    int z = blockIdx.z;
    int kv0 = z * 2048;
    uint32_t sb = smem_u32(sm);

    const __nv_bfloat16* Qh = qkvh + (size_t)row0 * 768 + head * 64;
    const __nv_bfloat16* Ql = qkvl + (size_t)row0 * 768 + head * 64;
    const __nv_bfloat16* Kh = qkvh + 256 + head * 64;
    const __nv_bfloat16* Kl = qkvl + 256 + head * 64;
    const __nv_bfloat16* Vh = vth + (size_t)head * 64 * 4096;
    const __nv_bfloat16* Vl = vtl + (size_t)head * 64 * 4096;

#pragma unroll
    for (int it = 0; it < 4; it++){
        int i = tid + it * 256;
        int r = i >> 3, seg = i & 7;
        uint32_t so = r * 128 + ((seg ^ (r & 7)) << 4);
        cpa16(sb + so,         Qh + (size_t)r * 768 + seg * 8);
        cpa16(sb + 16384 + so, Ql + (size_t)r * 768 + seg * 8);
    }
#pragma unroll
    for (int it = 0; it < 2; it++){
        int i = tid + it * 256;
        int r = i >> 3, seg = i & 7;
        uint32_t so = r * 128 + ((seg ^ (r & 7)) << 4);
        cpa16(sb + 32768 + so,         Kh + (size_t)(kv0 + r) * 768 + seg * 8);
        cpa16(sb + 32768 + 8192 + so,  Kl + (size_t)(kv0 + r) * 768 + seg * 8);
        cpa16(sb + 32768 + 16384 + so, Vh + (size_t)r * 4096 + kv0 + seg * 8);
        cpa16(sb + 32768 + 24576 + so, Vl + (size_t)r * 4096 + kv0 + seg * 8);
    }
    cpa_commit();
    asm volatile("cp.async.wait_group 0;" ::: "memory");
    __syncthreads();

    uint32_t qf_h[4][4], qf_l[4][4];
#pragma unroll
    for (int ks = 0; ks < 4; ks++){
        int r = wid * 16 + (lane & 15);
        int seg = ks * 2 + (lane >> 4);
        uint32_t ad = sb + r * 128 + ((seg ^ (r & 7)) << 4);
        ldm_x4(qf_h[ks], ad);
        ldm_x4(qf_l[ks], ad + 16384);
    }

    float m0 = -1e30f, m1 = -1e30f, l0 = 0.f, l1 = 0.f;
    float acc_o[8][4] = {};
    int buf = 0;

    for (int kt = 0; kt < 32; kt++){
        if (kt < 31){
            uint32_t bo = sb + 32768 + (buf ^ 1) * 32768;
            int key0 = kv0 + (kt + 1) * 64;
#pragma unroll
            for (int it = 0; it < 2; it++){
                int i = tid + it * 256;
                int r = i >> 3, seg = i & 7;
                uint32_t so = r * 128 + ((seg ^ (r & 7)) << 4);
                cpa16(bo + so,         Kh + (size_t)(key0 + r) * 768 + seg * 8);
                cpa16(bo + 8192 + so,  Kl + (size_t)(key0 + r) * 768 + seg * 8);
                cpa16(bo + 16384 + so, Vh + (size_t)r * 4096 + key0 + seg * 8);
                cpa16(bo + 24576 + so, Vl + (size_t)r * 4096 + key0 + seg * 8);
            }
            cpa_commit();
            asm volatile("cp.async.wait_group 1;" ::: "memory");
        } else {
            asm volatile("cp.async.wait_group 0;" ::: "memory");
        }
        __syncthreads();

        uint32_t kb = sb + 32768 + buf * 32768;

        float acc_s[8][4] = {};
#pragma unroll
        for (int ks = 0; ks < 4; ks++){
            uint32_t bh[8][2], bl[8][2];
#pragma unroll
            for (int nt = 0; nt < 8; nt++){
                int r = nt * 8 + (lane & 7);
                int seg = ks * 2 + ((lane >> 3) & 1);
                uint32_t bd = kb + r * 128 + ((seg ^ (r & 7)) << 4);
                ldm_x2(bh[nt], bd);
                ldm_x2(bl[nt], bd + 8192);
            }
#pragma unroll
            for (int nt = 0; nt < 8; nt++){
                mma_bf16(acc_s[nt], qf_h[ks], bh[nt]);
                mma_bf16(acc_s[nt], qf_h[ks], bl[nt]);
                mma_bf16(acc_s[nt], qf_l[ks], bh[nt]);
            }
        }
#pragma unroll
        for (int nt = 0; nt < 8; nt++){
            acc_s[nt][0] *= 0.125f; acc_s[nt][1] *= 0.125f;
            acc_s[nt][2] *= 0.125f; acc_s[nt][3] *= 0.125f;
        }

        float tm0 = -1e30f, tm1 = -1e30f;
#pragma unroll
        for (int nt = 0; nt < 8; nt++){
            tm0 = fmaxf(tm0, fmaxf(acc_s[nt][0], acc_s[nt][1]));
            tm1 = fmaxf(tm1, fmaxf(acc_s[nt][2], acc_s[nt][3]));
        }
        tm0 = fmaxf(tm0, __shfl_xor_sync(~0u, tm0, 1)); tm0 = fmaxf(tm0, __shfl_xor_sync(~0u, tm0, 2));
        tm1 = fmaxf(tm1, __shfl_xor_sync(~0u, tm1, 1)); tm1 = fmaxf(tm1, __shfl_xor_sync(~0u, tm1, 2));
        float mn0 = fmaxf(m0, tm0), mn1 = fmaxf(m1, tm1);
        float sc0 = __expf(m0 - mn0), sc1 = __expf(m1 - mn1);
        m0 = mn0; m1 = mn1;
        l0 *= sc0; l1 *= sc1;
#pragma unroll
        for (int nt = 0; nt < 8; nt++){
            acc_o[nt][0] *= sc0; acc_o[nt][1] *= sc0;
            acc_o[nt][2] *= sc1; acc_o[nt][3] *= sc1;
        }
        float rs0 = 0.f, rs1 = 0.f;
        uint32_t pa_h[4][4], pa_l[4][4];
#pragma unroll
        for (int nt = 0; nt < 8; nt++){
            float p0 = __expf(acc_s[nt][0] - mn0), p1 = __expf(acc_s[nt][1] - mn0);
            float p2 = __expf(acc_s[nt][2] - mn1), p3 = __expf(acc_s[nt][3] - mn1);
            rs0 += p0 + p1; rs1 += p2 + p3;
            int k2 = nt >> 1;
            if (!(nt & 1)){
                splitpack(p0, p1, pa_h[k2][0], pa_l[k2][0]);
                splitpack(p2, p3, pa_h[k2][1], pa_l[k2][1]);
            } else {
                splitpack(p0, p1, pa_h[k2][2], pa_l[k2][2]);
                splitpack(p2, p3, pa_h[k2][3], pa_l[k2][3]);
            }
        }
        rs0 += __shfl_xor_sync(~0u, rs0, 1); rs0 += __shfl_xor_sync(~0u, rs0, 2);
        rs1 += __shfl_xor_sync(~0u, rs1, 1); rs1 += __shfl_xor_sync(~0u, rs1, 2);
        l0 += rs0; l1 += rs1;

        uint32_t vb = kb + 16384;
#pragma unroll
        for (int k2 = 0; k2 < 4; k2++){
            uint32_t vh[8][2], vl[8][2];
#pragma unroll
            for (int nt = 0; nt < 8; nt++){
                int r = nt * 8 + (lane & 7);
                int seg = k2 * 2 + ((lane >> 3) & 1);
                uint32_t vd = vb + r * 128 + ((seg ^ (r & 7)) << 4);
                ldm_x2(vh[nt], vd);
                ldm_x2(vl[nt], vd + 8192);
            }
#pragma unroll
            for (int nt = 0; nt < 8; nt++){
                mma_bf16(acc_o[nt], pa_h[k2], vh[nt]);
                mma_bf16(acc_o[nt], pa_h[k2], vl[nt]);
                mma_bf16(acc_o[nt], pa_l[k2], vh[nt]);
            }
        }
        __syncthreads();
        buf ^= 1;
    }

    // ---- write un-normalized partials ----
    int r = row0 + wid * 16 + (lane >> 2);
    size_t ro0 = ((size_t)z * NNODE + r) * 256;
    size_t ro1 = ((size_t)z * NNODE + r + 8) * 256;
#pragma unroll
    for (int nt = 0; nt < 8; nt++){
        int cc = head * 64 + nt * 8 + ((lane & 3) << 1);
        pO[ro0 + cc]     = acc_o[nt][0];
        pO[ro0 + cc + 1] = acc_o[nt][1];
        pO[ro1 + cc]     = acc_o[nt][2];
        pO[ro1 + cc + 1] = acc_o[nt][3];
    }
    if ((lane & 3) == 0){
        pML[((size_t)z * NNODE + r) * 8 + head * 2]     = m0;
        pML[((size_t)z * NNODE + r) * 8 + head * 2 + 1] = l0;
        pML[((size_t)z * NNODE + r + 8) * 8 + head * 2]     = m1;
        pML[((size_t)z * NNODE + r + 8) * 8 + head * 2 + 1] = l1;
    }
}

// combine the two KV-split partials -> attn hi/lo
__global__ void k_fmerge(const float* __restrict__ pO, const float* __restrict__ pML,
                         __nv_bfloat16* __restrict__ Oh, __nv_bfloat16* __restrict__ Ol){
    int row = blockIdx.x, col = threadIdx.x;
    int head = col >> 6;
    float m0 = pML[(size_t)row * 8 + head * 2],            l0 = pML[(size_t)row * 8 + head * 2 + 1];
    float m1 = pML[((size_t)NNODE + row) * 8 + head * 2],  l1 = pML[((size_t)NNODE + row) * 8 + head * 2 + 1];
    float mx = fmaxf(m0, m1);
    float w0 = __expf(m0 - mx), w1 = __expf(m1 - mx);
    float num = pO[(size_t)row * 256 + col] * w0 + pO[((size_t)NNODE + row) * 256 + col] * w1;
    float den = l0 * w0 + l1 * w1;
    f2hl(num / den, Oh, Ol, (size_t)row * 256 + col);
}

// ================= pointwise =================
__global__ void k_lstm(const float* __restrict__ G, float* __restrict__ ht_out,
                       __nv_bfloat16* __restrict__ Hh, __nv_bfloat16* __restrict__ Hl){
    int idx = blockIdx.x * 256 + threadIdx.x;
    int n = idx >> 8, j = idx & 255;
    const float* gr = G + (size_t)n * 1024;
    float ig = gr[j], gg = gr[512 + j], og = gr[768 + j];
    float cc = sigmf(ig) * tanhf(gg);
    float hv = sigmf(og) * tanhf(cc);
    ht_out[idx] = hv;
    f2hl(hv, Hh, Hl, (size_t)n * 512 + j);
}

__global__ void k_vt(const __nv_bfloat16* __restrict__ qh, const __nv_bfloat16* __restrict__ ql,
                     __nv_bfloat16* __restrict__ vh, __nv_bfloat16* __restrict__ vl){
    int idx = blockIdx.x * 256 + threadIdx.x;
    int hd = idx >> 12, n = idx & 4095;
    size_t s = (size_t)n * 768 + 512 + hd;
    vh[idx] = qh[s]; vl[idx] = ql[s];
}

// ================= launch =================
#define SYMADDR(p, s) do { void* _t; cudaGetSymbolAddress(&_t, s); p = (decltype(p))_t; } while(0)

extern "C" void kernel_launch(void* const* d_in, const int* in_sizes, int n_in,
                              void* d_out, int out_size) {
    const float* x     = (const float*)d_in[0];
    const int*   ei_t  = (const int*)d_in[1];
    const int*   ei_c  = (const int*)d_in[2];
    const float* ea_t  = (const float*)d_in[3];
    const float* ea_c  = (const float*)d_in[4];
    const float* W_t   = (const float*)d_in[5];
    const float* asrc_t= (const float*)d_in[6];
    const float* adst_t= (const float*)d_in[7];
    const float* We_t  = (const float*)d_in[8];
    const float* ae_t  = (const float*)d_in[9];
    const float* b_t   = (const float*)d_in[10];
    const float* W_c   = (const float*)d_in[11];
    const float* asrc_c= (const float*)d_in[12];
    const float* adst_c= (const float*)d_in[13];
    const float* We_c  = (const float*)d_in[14];
    const float* ae_c  = (const float*)d_in[15];
    const float* b_c   = (const float*)d_in[16];
    const float* lstm_Wih = (const float*)d_in[17];
    const float* lstm_bih = (const float*)d_in[19];
    const float* lstm_bhh = (const float*)d_in[20];
    const float* mha_in_w  = (const float*)d_in[21];
    const float* mha_in_b  = (const float*)d_in[22];
    const float* mha_out_w = (const float*)d_in[23];
    const float* mha_out_b = (const float*)d_in[24];
    const float* fus_w = (const float*)d_in[25];
    const float* fus_b = (const float*)d_in[26];
    const float* out_w = (const float*)d_in[27];
    const float* out_b = (const float*)d_in[28];

    float* big; SYMADDR(big, g_big);
    float* po;  SYMADDR(po, g_po);
    float* pml; SYMADDR(pml, g_pml);
    __nv_bfloat16 *hth, *htl, *hch, *hcl, *qkvh, *qkvl, *vth, *vtl;
    __nv_bfloat16 *attnh, *attnl, *hcath, *hcatl, *hfush, *hfusl;
    __nv_bfloat16 *wihh, *wihl, *inwh, *inwl, *mowh, *mowl, *fuwh, *fuwl, *owh, *owl;
    SYMADDR(hth, g_hth); SYMADDR(htl, g_htl); SYMADDR(hch, g_hch); SYMADDR(hcl, g_hcl);
    SYMADDR(qkvh, g_qkvh); SYMADDR(qkvl, g_qkvl); SYMADDR(vth, g_vth); SYMADDR(vtl, g_vtl);
    SYMADDR(attnh, g_attnh); SYMADDR(attnl, g_attnl);
    SYMADDR(hcath, g_hcath); SYMADDR(hcatl, g_hcatl);
    SYMADDR(hfush, g_hfush); SYMADDR(hfusl, g_hfusl);
    SYMADDR(wihh, g_wihh); SYMADDR(wihl, g_wihl);
    SYMADDR(inwh, g_inwh); SYMADDR(inwl, g_inwl);
    SYMADDR(mowh, g_mowh); SYMADDR(mowl, g_mowl);
    SYMADDR(fuwh, g_fuwh); SYMADDR(fuwl, g_fuwl);
    SYMADDR(owh, g_owh); SYMADDR(owl, g_owl);

    cudaFuncSetAttribute(k_flash, cudaFuncAttributeMaxDynamicSharedMemorySize, 98304);
    cudaFuncSetAttribute(mma_gemm, cudaFuncAttributeMaxDynamicSharedMemorySize, 98304);
    const int DYN = 98304;
    const int DYN_FA = 98304;

    float* out_main = (float*)d_out;
    float* out_ht   = out_main + (size_t)NNODE * NOUT;
    float* out_hc   = out_ht   + (size_t)NNODE * HID;

    const int* src_t = ei_t; const int* dst_t = ei_t + NE;
    const int* src_c = ei_c; const int* dst_c = ei_c + NE;
    int nepb = (NEP + 255) / 256, neb = (NE + 255) / 256;

    k_initmean<<<128, 256>>>(ea_t, ea_c);
    k_setup<<<1, 256>>>(We_t, ae_t, We_c, ae_c, lstm_bih, lstm_bhh);
    k_convall<<<CW4 / 256, 256>>>(lstm_Wih, mha_in_w, mha_out_w, fus_w, out_w);

    // ---- GATs (both graphs per launch) ----
    k_xp2<<<dim3(8, 256, 2), 256>>>(x, W_t, W_c);
    k_asd<<<dim3(NNODE, 2), 256>>>(asrc_t, adst_t, asrc_c, adst_c);
    k_count<<<dim3(neb, 2), 256>>>(dst_t, dst_c);
    k_scan<<<2, 1024>>>();
    k_scatter<<<dim3(neb, 2), 256>>>(dst_t, dst_c);
    k_alpha<<<dim3(nepb, 2), 256>>>(src_t, dst_t, ea_t, src_c, dst_c, ea_c);
    k_ex<<<dim3(nepb, 2), 256>>>(dst_t, dst_c);
    k_agg<<<dim3(NNODE, 2), 256>>>(src_t, src_c, b_t, b_c);

    // ---- temporal: LSTM gates (4096x1024x2048) ----
    mma_gemm<<<dim3(16, 32), 256, DYN>>>(
        hth, htl, NHC, wihh, wihl, NHC,
        big + OFF_G, 1024, nullptr, nullptr, 0, 0,
        NHC, big + OFF_BSUM, 1.f, 0);
    k_lstm<<<NNODE, 256>>>(big + OFF_G, out_ht, hcath, hcatl);

    // ---- causal: qkv (4096x768x256) ----
    mma_gemm<<<dim3(12, 32), 256, DYN>>>(
        hch, hcl, 256, inwh, inwl, 256,
        nullptr, 0, qkvh, qkvl, 768, 0,
        256, mha_in_b, 1.f, 0);
    k_vt<<<(4*64*NNODE)/256, 256>>>(qkvh, qkvl, vth, vtl);

    // ---- fused attention, split-KV x2 + merge ----
    k_flash<<<dim3(32, 4, 2), 256, DYN_FA>>>(qkvh, qkvl, vth, vtl, po, pml);
    k_fmerge<<<NNODE, 256>>>(po, pml, attnh, attnl);

    // ---- proj (4096x256x256) ----
    mma_gemm<<<dim3(4, 32), 256, DYN>>>(
        attnh, attnl, 256, mowh, mowl, 256,
        out_hc, 256, hcath, hcatl, 512, 256,
        256, mha_out_b, 1.f, 0);

    // ---- fusion relu (4096x256x512) ----
    mma_gemm<<<dim3(4, 32), 256, DYN>>>(
        hcath, hcatl, 512, fuwh, fuwl, 512,
        nullptr, 0, hfush, hfusl, 256, 0,
        512, fus_b, 1.f, 1);

    // ---- out (4096x128x256) ----
    mma_gemm<<<dim3(2, 32), 256, DYN>>>(
        hfush, hfusl, 256, owh, owl, 256,
        out_main, NOUT, nullptr, nullptr, 0, 0,
        256, out_b, 1.f, 0);
}

// round 8
// speedup vs baseline: 2.3286x; 1.0073x over previous
#include <cuda_runtime.h>
#include <cuda_bf16.h>
#include <math.h>
#include <float.h>
#include <stdint.h>

#define NNODE 4096
#define NIN   28
#define NE    131072
#define NEP   (NE + NNODE)
#define NH    8
#define NC    256
#define NHC   2048
#define HID   256
#define NOUT  128

// ---------------- fp32 scratch ----------------
#define OFF_G    ((size_t)0)
#define OFF_BSUM (OFF_G + (size_t)NNODE * 1024)
#define BIG_SZ   (OFF_BSUM + 1024)
__device__ float g_big[BIG_SZ];

__device__ float g_xp[2][(size_t)NNODE * NHC];
__device__ float g_as[2][NNODE * NH];
__device__ float g_ad[2][NNODE * NH];
__device__ float g_w [2][(size_t)NEP * NH];
__device__ int   g_mx[2][NNODE * NH];
__device__ float g_den[2][NNODE * NH];
__device__ int   g_cnt[2][NNODE];
__device__ int   g_cur[2][NNODE];
__device__ int   g_start[2][NNODE];
__device__ int   g_sorted[2][NE];
__device__ float g_part[2][128];
__device__ float g_mean[2];
__device__ float g_ce[2][NH];

// flash split-K partials
__device__ float g_po[(size_t)2 * NNODE * 256];
__device__ float g_pml[(size_t)2 * NNODE * 8];

// ---------------- bf16 hi/lo tensors ----------------
__device__ __nv_bfloat16 g_hth[(size_t)NNODE * NHC], g_htl[(size_t)NNODE * NHC];
__device__ __nv_bfloat16 g_hch[(size_t)NNODE * 256], g_hcl[(size_t)NNODE * 256];
__device__ __nv_bfloat16 g_qkvh[(size_t)NNODE * 768], g_qkvl[(size_t)NNODE * 768];
__device__ __nv_bfloat16 g_vth[(size_t)4 * 64 * NNODE], g_vtl[(size_t)4 * 64 * NNODE];
__device__ __nv_bfloat16 g_attnh[(size_t)NNODE * 256], g_attnl[(size_t)NNODE * 256];
__device__ __nv_bfloat16 g_hcath[(size_t)NNODE * 512], g_hcatl[(size_t)NNODE * 512];
__device__ __nv_bfloat16 g_hfush[(size_t)NNODE * 256], g_hfusl[(size_t)NNODE * 256];
// weights
__device__ __nv_bfloat16 g_wihh[1024 * 2048], g_wihl[1024 * 2048];
__device__ __nv_bfloat16 g_inwh[768 * 256],   g_inwl[768 * 256];
__device__ __nv_bfloat16 g_mowh[256 * 256],   g_mowl[256 * 256];
__device__ __nv_bfloat16 g_fuwh[256 * 512],   g_fuwl[256 * 512];
__device__ __nv_bfloat16 g_owh[128 * 256],    g_owl[128 * 256];
// padded x / W for tensor-core xp GEMM (K padded 28 -> 64)
__device__ __nv_bfloat16 g_xpadh[(size_t)NNODE * 64], g_xpadl[(size_t)NNODE * 64];
__device__ __nv_bfloat16 g_wpadh[(size_t)2 * NHC * 64], g_wpadl[(size_t)2 * NHC * 64];

// ---------------- helpers ----------------
__device__ __forceinline__ int   f2ord(float f){ int i = __float_as_int(f); return i >= 0 ? i : i ^ 0x7fffffff; }
__device__ __forceinline__ float ord2f(int k){ return __int_as_float(k >= 0 ? k : k ^ 0x7fffffff); }
__device__ __forceinline__ float sigmf(float x){ return 1.f / (1.f + expf(-x)); }
__device__ __forceinline__ void f2hl(float v, __nv_bfloat16* H, __nv_bfloat16* L, size_t i){
    __nv_bfloat16 h = __float2bfloat16(v);
    H[i] = h; L[i] = __float2bfloat16(v - __bfloat162float(h));
}
__device__ __forceinline__ uint32_t smem_u32(const void* p){
    uint32_t a;
    asm("{ .reg .u64 t; cvta.to.shared.u64 t, %1; cvt.u32.u64 %0, t; }" : "=r"(a) : "l"(p));
    return a;
}
__device__ __forceinline__ void ldm_x4(uint32_t* r, uint32_t addr){
    asm volatile("ldmatrix.sync.aligned.m8n8.x4.shared.b16 {%0,%1,%2,%3}, [%4];"
        : "=r"(r[0]), "=r"(r[1]), "=r"(r[2]), "=r"(r[3]) : "r"(addr));
}
__device__ __forceinline__ void ldm_x2(uint32_t* r, uint32_t addr){
    asm volatile("ldmatrix.sync.aligned.m8n8.x2.shared.b16 {%0,%1}, [%2];"
        : "=r"(r[0]), "=r"(r[1]) : "r"(addr));
}
__device__ __forceinline__ void mma_bf16(float* c, const uint32_t* a, const uint32_t* b){
    asm volatile("mma.sync.aligned.m16n8k16.row.col.f32.bf16.bf16.f32 "
        "{%0,%1,%2,%3}, {%4,%5,%6,%7}, {%8,%9}, {%0,%1,%2,%3};"
        : "+f"(c[0]), "+f"(c[1]), "+f"(c[2]), "+f"(c[3])
        : "r"(a[0]), "r"(a[1]), "r"(a[2]), "r"(a[3]), "r"(b[0]), "r"(b[1]));
}
__device__ __forceinline__ void cpa16(uint32_t saddr, const void* g){
    asm volatile("cp.async.ca.shared.global [%0], [%1], 16;" :: "r"(saddr), "l"(g));
}
__device__ __forceinline__ void cpa_commit(){ asm volatile("cp.async.commit_group;" ::: "memory"); }
__device__ __forceinline__ void splitpack(float a, float b, uint32_t& hi, uint32_t& lo){
    __nv_bfloat16 ha = __float2bfloat16(a), hb = __float2bfloat16(b);
    __nv_bfloat16 la = __float2bfloat16(a - __bfloat162float(ha));
    __nv_bfloat16 lb = __float2bfloat16(b - __bfloat162float(hb));
    hi = ((uint32_t)__bfloat16_as_ushort(hb) << 16) | (uint32_t)__bfloat16_as_ushort(ha);
    lo = ((uint32_t)__bfloat16_as_ushort(lb) << 16) | (uint32_t)__bfloat16_as_ushort(la);
}

// ================= setup =================
__global__ void k_initmean(const float* __restrict__ ea_t, const float* __restrict__ ea_c){
    int idx = blockIdx.x * 256 + threadIdx.x, stride = gridDim.x * 256;
    int mi = f2ord(-FLT_MAX);
    for (int i = idx; i < NNODE * NH; i += stride){
        g_mx[0][i] = mi; g_mx[1][i] = mi;
        g_den[0][i] = 0.f; g_den[1][i] = 0.f;
    }
    for (int i = idx; i < NNODE; i += stride){
        g_cnt[0][i] = 0; g_cnt[1][i] = 0;
        g_cur[0][i] = 0; g_cur[1][i] = 0;
    }
    __shared__ float s0[256], s1[256];
    float a = 0.f, b = 0.f;
    for (int i = blockIdx.x * 256 + threadIdx.x; i < NE; i += 128 * 256){ a += ea_t[i]; b += ea_c[i]; }
    s0[threadIdx.x] = a; s1[threadIdx.x] = b; __syncthreads();
    for (int s = 128; s; s >>= 1){
        if (threadIdx.x < s){ s0[threadIdx.x] += s0[threadIdx.x+s]; s1[threadIdx.x] += s1[threadIdx.x+s]; }
        __syncthreads();
    }
    if (!threadIdx.x){ g_part[0][blockIdx.x] = s0[0]; g_part[1][blockIdx.x] = s1[0]; }
}

__global__ void k_setup(const float* __restrict__ We_t, const float* __restrict__ ae_t,
                        const float* __restrict__ We_c, const float* __restrict__ ae_c,
                        const float* __restrict__ bih,  const float* __restrict__ bhh){
    __shared__ float sh[256];
    int tid = threadIdx.x;
    for (int g = 0; g < 2; g++){
        sh[tid] = (tid < 128) ? g_part[g][tid] : 0.f;
        __syncthreads();
        for (int s = 128; s; s >>= 1){ if (tid < s) sh[tid] += sh[tid+s]; __syncthreads(); }
        if (!tid) g_mean[g] = sh[0] / (float)NE;
        __syncthreads();
    }
    int wid = tid >> 5, lane = tid & 31;
    for (int c = wid; c < 16; c += 8){
        int g = c >> 3, h = c & 7;
        const float* We = g ? We_c : We_t;
        const float* ae = g ? ae_c : ae_t;
        float s = 0.f;
        for (int i = lane; i < NC; i += 32) s = fmaf(We[h*NC + i], ae[h*NC + i], s);
        for (int o = 16; o; o >>= 1) s += __shfl_down_sync(0xffffffffu, s, o);
        if (!lane) g_ce[g][h] = s;
    }
    for (int j = tid; j < 1024; j += 256) g_big[OFF_BSUM + j] = bih[j] + bhh[j];
}

#define CW0 2097152
#define CW1 (CW0 + 196608)
#define CW2 (CW1 + 65536)
#define CW3 (CW2 + 131072)
#define CW4 (CW3 + 32768)
#define CW5 (CW4 + NNODE * 64)
#define CW6 (CW5 + 2 * NHC * 64)
__global__ void k_convall(const float* __restrict__ w0, const float* __restrict__ w1,
                          const float* __restrict__ w2, const float* __restrict__ w3,
                          const float* __restrict__ w4, const float* __restrict__ x,
                          const float* __restrict__ W_t, const float* __restrict__ W_c){
    int i = blockIdx.x * 256 + threadIdx.x;
    if (i < CW0)      f2hl(w0[i], g_wihh, g_wihl, i);
    else if (i < CW1) f2hl(w1[i - CW0], g_inwh, g_inwl, i - CW0);
    else if (i < CW2) f2hl(w2[i - CW1], g_mowh, g_mowl, i - CW1);
    else if (i < CW3) f2hl(w3[i - CW2], g_fuwh, g_fuwl, i - CW2);
    else if (i < CW4) f2hl(w4[i - CW3], g_owh, g_owl, i - CW3);
    else if (i < CW5){
        int j = i - CW4; int n = j >> 6, k = j & 63;
        float v = (k < NIN) ? x[n * NIN + k] : 0.f;
        f2hl(v, g_xpadh, g_xpadl, j);
    } else if (i < CW6){
        int j = i - CW5; int g = j >> 17; int r = j & 131071;
        int n = r >> 6, k = r & 63;
        const float* W = g ? W_c : W_t;
        float v = (k < NIN) ? W[k * NHC + n] : 0.f;
        f2hl(v, g_wpadh, g_wpadl, j);
    }
}

// ================= GAT =================
__global__ void k_asd(const float* __restrict__ asrc_t, const float* __restrict__ adst_t,
                      const float* __restrict__ asrc_c, const float* __restrict__ adst_c){
    int g = blockIdx.y;
    const float* asrc = g ? asrc_c : asrc_t;
    const float* adst = g ? adst_c : adst_t;
    int n = blockIdx.x, h = threadIdx.x >> 5, lane = threadIdx.x & 31;
    const float* xr = g_xp[g] + (size_t)n * NHC + h * NC;
    float s1 = 0.f, s2 = 0.f;
    for (int c = lane; c < NC; c += 32){
        float v = xr[c];
        s1 = fmaf(v, asrc[h*NC + c], s1);
        s2 = fmaf(v, adst[h*NC + c], s2);
    }
    for (int o = 16; o; o >>= 1){ s1 += __shfl_down_sync(~0u, s1, o); s2 += __shfl_down_sync(~0u, s2, o); }
    if (!lane){ g_as[g][n*NH + h] = s1; g_ad[g][n*NH + h] = s2; }
}

__global__ void k_count(const int* __restrict__ dst_t, const int* __restrict__ dst_c){
    int g = blockIdx.y;
    const int* dst = g ? dst_c : dst_t;
    int e = blockIdx.x * 256 + threadIdx.x;
    if (e < NE) atomicAdd(&g_cnt[g][dst[e]], 1);
}

__global__ void k_scan(){
    int g = blockIdx.x, tid = threadIdx.x;
    __shared__ int sh[1024];
    int base = tid * 4;
    int c0 = g_cnt[g][base], c1 = g_cnt[g][base+1], c2 = g_cnt[g][base+2], c3 = g_cnt[g][base+3];
    int s = c0 + c1 + c2 + c3;
    sh[tid] = s; __syncthreads();
    for (int off = 1; off < 1024; off <<= 1){
        int v = (tid >= off) ? sh[tid - off] : 0;
        __syncthreads();
        sh[tid] += v;
        __syncthreads();
    }
    int excl = sh[tid] - s;
    g_start[g][base]   = excl;
    g_start[g][base+1] = excl + c0;
    g_start[g][base+2] = excl + c0 + c1;
    g_start[g][base+3] = excl + c0 + c1 + c2;
}

__global__ void k_scatter(const int* __restrict__ dst_t, const int* __restrict__ dst_c){
    int g = blockIdx.y;
    const int* dst = g ? dst_c : dst_t;
    int e = blockIdx.x * 256 + threadIdx.x;
    if (e < NE){
        int d = dst[e];
        int pos = g_start[g][d] + atomicAdd(&g_cur[g][d], 1);
        g_sorted[g][pos] = e;
    }
}

__global__ void k_alpha(const int* __restrict__ src_t, const int* __restrict__ dst_t, const float* __restrict__ ea_t,
                        const int* __restrict__ src_c, const int* __restrict__ dst_c, const float* __restrict__ ea_c){
    int g = blockIdx.y;
    const int* src = g ? src_c : src_t;
    const int* dst = g ? dst_c : dst_t;
    const float* ea = g ? ea_c : ea_t;
    int e = blockIdx.x * 256 + threadIdx.x;
    if (e >= NEP) return;
    int s, d; float av;
    if (e < NE){ s = src[e]; d = dst[e]; av = ea[e]; }
    else { s = d = e - NE; av = g_mean[g]; }
#pragma unroll
    for (int h = 0; h < NH; h++){
        float al = g_as[g][s*NH + h] + g_ad[g][d*NH + h] + av * g_ce[g][h];
        al = al > 0.f ? al : 0.2f * al;
        g_w[g][(size_t)e * NH + h] = al;
        atomicMax(&g_mx[g][d*NH + h], f2ord(al));
    }
}

__global__ void k_ex(const int* __restrict__ dst_t, const int* __restrict__ dst_c){
    int g = blockIdx.y;
    const int* dst = g ? dst_c : dst_t;
    int e = blockIdx.x * 256 + threadIdx.x;
    if (e >= NEP) return;
    int d = (e < NE) ? dst[e] : e - NE;
#pragma unroll
    for (int h = 0; h < NH; h++){
        float al = g_w[g][(size_t)e * NH + h];
        float ex = expf(al - ord2f(g_mx[g][d*NH + h]));
        g_w[g][(size_t)e * NH + h] = ex;
        atomicAdd(&g_den[g][d*NH + h], ex);
    }
}

__global__ void __launch_bounds__(256) k_agg(const int* __restrict__ src_t, const int* __restrict__ src_c,
                                             const float* __restrict__ b_t, const float* __restrict__ b_c){
    int g = blockIdx.y;
    const int* src = g ? src_c : src_t;
    const float* bias = g ? b_c : b_t;
    int n = blockIdx.x, t = threadIdx.x;
    const float* xp = g_xp[g];
    const float* w  = g_w[g];
    float acc[NH];
    {
        size_t e = (size_t)(NE + n) * NH;
        const float* xr = xp + (size_t)n * NHC + t;
#pragma unroll
        for (int h = 0; h < NH; h++) acc[h] = w[e + h] * xr[h * NC];
    }
    __shared__ int   ssrc[32];
    __shared__ float sw[32][NH];
    int st = g_start[g][n], c = g_cnt[g][n];
    for (int i0 = 0; i0 < c; i0 += 32){
        int m = min(32, c - i0);
        __syncthreads();
        if (t < m) ssrc[t] = src[g_sorted[g][st + i0 + t]];
        {
            int j = t >> 3, h = t & 7;
            if (j < m) sw[j][h] = w[(size_t)g_sorted[g][st + i0 + j] * NH + h];
        }
        __syncthreads();
        int jj = 0;
        for (; jj + 4 <= m; jj += 4){
            const float* x0 = xp + (size_t)ssrc[jj+0] * NHC + t;
            const float* x1 = xp + (size_t)ssrc[jj+1] * NHC + t;
            const float* x2 = xp + (size_t)ssrc[jj+2] * NHC + t;
            const float* x3 = xp + (size_t)ssrc[jj+3] * NHC + t;
            float v0[NH], v1[NH], v2[NH], v3[NH];
#pragma unroll
            for (int h = 0; h < NH; h++){ v0[h] = x0[h*NC]; v1[h] = x1[h*NC]; v2[h] = x2[h*NC]; v3[h] = x3[h*NC]; }
#pragma unroll
            for (int h = 0; h < NH; h++){
                acc[h] = fmaf(sw[jj+0][h], v0[h], acc[h]);
                acc[h] = fmaf(sw[jj+1][h], v1[h], acc[h]);
                acc[h] = fmaf(sw[jj+2][h], v2[h], acc[h]);
                acc[h] = fmaf(sw[jj+3][h], v3[h], acc[h]);
            }
        }
        for (; jj < m; jj++){
            const float* xr = xp + (size_t)ssrc[jj] * NHC + t;
#pragma unroll
            for (int h = 0; h < NH; h++) acc[h] = fmaf(sw[jj][h], xr[h * NC], acc[h]);
        }
    }
    const float* den = g_den[g] + n * NH;
    if (g == 0){
#pragma unroll
        for (int h = 0; h < NH; h++){
            float v = acc[h] / (den[h] + 1e-16f) + bias[h * NC + t];
            f2hl(v, g_hth, g_htl, (size_t)n * NHC + h * NC + t);
        }
    } else {
        float s = 0.f;
#pragma unroll
        for (int h = 0; h < NH; h++) s += acc[h] / (den[h] + 1e-16f);
        f2hl(s * 0.125f + bias[t], g_hch, g_hcl, (size_t)n * NC + t);
    }
}

// ================= HMMA bf16x3 GEMM core (cp.async 2-stage pipelined) =================
struct GA {
    const __nv_bfloat16 *Ah, *Al, *Bh, *Bl;
    float* C;
    __nv_bfloat16 *Ch, *Cl;
    const float* bias;
    int lda, ldb, ldc, ldc2, c2off, K, act, gx;
    float alpha;
};

__device__ __forceinline__ void gemm_core(const GA a){
    extern __shared__ char sm[];
    int tid = threadIdx.x, lane = tid & 31, wid = tid >> 5;
    int wm = wid & 3, wn = wid >> 2;
    int row0 = blockIdx.y * 128, col0 = blockIdx.x * 64;
    const __nv_bfloat16* Ah = a.Ah + (size_t)row0 * a.lda;
    const __nv_bfloat16* Al = a.Al + (size_t)row0 * a.lda;
    const __nv_bfloat16* Bh = a.Bh + (size_t)col0 * a.ldb;
    const __nv_bfloat16* Bl = a.Bl + (size_t)col0 * a.ldb;

    uint32_t sbase = smem_u32(sm);
    int nkb = a.K >> 6;

    auto issue = [&](int kb, int st){
        uint32_t su = sbase + st * 49152;
        int k0 = kb << 6;
#pragma unroll
        for (int it = 0; it < 4; it++){
            int i = tid + it * 256;
            int row = i >> 3, seg = i & 7;
            size_t goff = (size_t)row * a.lda + k0 + seg * 8;
            uint32_t so = row * 128 + ((seg ^ (row & 7)) << 4);
            cpa16(su + so,         Ah + goff);
            cpa16(su + 16384 + so, Al + goff);
        }
#pragma unroll
        for (int it = 0; it < 2; it++){
            int i = tid + it * 256;
            int row = i >> 3, seg = i & 7;
            size_t goff = (size_t)row * a.ldb + k0 + seg * 8;
            uint32_t so = row * 128 + ((seg ^ (row & 7)) << 4);
            cpa16(su + 32768 + so, Bh + goff);
            cpa16(su + 40960 + so, Bl + goff);
        }
        cpa_commit();
    };

    issue(0, 0);
    if (nkb > 1) issue(1, 1);

    float acc[2][4][4] = {};
    for (int kb = 0; kb < nkb; kb++){
        if (kb + 1 < nkb) asm volatile("cp.async.wait_group 1;" ::: "memory");
        else              asm volatile("cp.async.wait_group 0;" ::: "memory");
        __syncthreads();
        uint32_t sb2 = sbase + (kb & 1) * 49152;
#pragma unroll
        for (int ks = 0; ks < 4; ks++){
            uint32_t a_h[2][4], a_l[2][4], b_h[4][2], b_l[4][2];
#pragma unroll
            for (int mt = 0; mt < 2; mt++){
                int r = wm * 32 + mt * 16 + (lane & 15);
                int seg = ks * 2 + (lane >> 4);
                uint32_t ad = sb2 + r * 128 + ((seg ^ (r & 7)) << 4);
                ldm_x4(a_h[mt], ad);
                ldm_x4(a_l[mt], ad + 16384);
            }
#pragma unroll
            for (int nt = 0; nt < 4; nt++){
                int r = wn * 32 + nt * 8 + (lane & 7);
                int seg = ks * 2 + ((lane >> 3) & 1);
                uint32_t bd = sb2 + 32768 + r * 128 + ((seg ^ (r & 7)) << 4);
                ldm_x2(b_h[nt], bd);
                ldm_x2(b_l[nt], bd + 8192);
            }
#pragma unroll
            for (int mt = 0; mt < 2; mt++)
#pragma unroll
                for (int nt = 0; nt < 4; nt++){
                    mma_bf16(acc[mt][nt], a_h[mt], b_h[nt]);
                    mma_bf16(acc[mt][nt], a_h[mt], b_l[nt]);
                    mma_bf16(acc[mt][nt], a_l[mt], b_h[nt]);
                }
        }
        __syncthreads();
        if (kb + 2 < nkb) issue(kb + 2, kb & 1);
    }

#pragma unroll
    for (int mt = 0; mt < 2; mt++){
#pragma unroll
        for (int nt = 0; nt < 4; nt++){
            int r0 = row0 + wm * 32 + mt * 16 + (lane >> 2);
            int c0 = col0 + wn * 32 + nt * 8 + ((lane & 3) << 1);
#pragma unroll
            for (int q = 0; q < 4; q++){
                int r = r0 + (q >> 1) * 8;
                int cc = c0 + (q & 1);
                float v = acc[mt][nt][q] * a.alpha;
                if (a.bias) v += a.bias[cc];
                if (a.act == 1) v = fmaxf(v, 0.f);
                if (a.C) a.C[(size_t)r * a.ldc + cc] = v;
                if (a.Ch) f2hl(v, a.Ch, a.Cl, (size_t)r * a.ldc2 + a.c2off + cc);
            }
        }
    }
}

__global__ void __launch_bounds__(256) mma_single(GA a){
    if ((int)blockIdx.x >= a.gx) return;
    gemm_core(a);
}
__global__ void __launch_bounds__(256) mma_dual(GA a0, GA a1){
    GA a = blockIdx.z ? a1 : a0;
    if ((int)blockIdx.x >= a.gx) return;
    gemm_core(a);
}

// ================= flash attention (split-KV, 2 partials) =================
__global__ void __launch_bounds__(256) k_flash(
    const __nv_bfloat16* __restrict__ qkvh, const __nv_bfloat16* __restrict__ qkvl,
    const __nv_bfloat16* __restrict__ vth, const __nv_bfloat16* __restrict__ vtl,
    float* __restrict__ pO, float* __restrict__ pML)
{
    extern __shared__ char sm[];
    int tid = threadIdx.x, lane = tid & 31, wid = tid >> 5;
    int head = blockIdx.y;
    int row0 = blockIdx.x * 128;
    int z = blockIdx.z;
    int kv0 = z * 2048;
    uint32_t sb = smem_u32(sm);

    const __nv_bfloat16* Qh = qkvh + (size_t)row0 * 768 + head * 64;
    const __nv_bfloat16* Ql = qkvl + (size_t)row0 * 768 + head * 64;
    const __nv_bfloat16* Kh = qkvh + 256 + head * 64;
    const __nv_bfloat16* Kl = qkvl + 256 + head * 64;
    const __nv_bfloat16* Vh = vth + (size_t)head * 64 * 4096;
    const __nv_bfloat16* Vl = vtl + (size_t)head * 64 * 4096;

#pragma unroll
    for (int it = 0; it < 4; it++){
        int i = tid + it * 256;
        int r = i >> 3, seg = i & 7;
        uint32_t so = r * 128 + ((seg ^ (r & 7)) << 4);
        cpa16(sb + so,         Qh + (size_t)r * 768 + seg * 8);
        cpa16(sb + 16384 + so, Ql + (size_t)r * 768 + seg * 8);
    }
#pragma unroll
    for (int it = 0; it < 2; it++){
        int i = tid + it * 256;
        int r = i >> 3, seg = i & 7;
        uint32_t so = r * 128 + ((seg ^ (r & 7)) << 4);
        cpa16(sb + 32768 + so,         Kh + (size_t)(kv0 + r) * 768 + seg * 8);
        cpa16(sb + 32768 + 8192 + so,  Kl + (size_t)(kv0 + r) * 768 + seg * 8);
        cpa16(sb + 32768 + 16384 + so, Vh + (size_t)r * 4096 + kv0 + seg * 8);
        cpa16(sb + 32768 + 24576 + so, Vl + (size_t)r * 4096 + kv0 + seg * 8);
    }
    cpa_commit();
    asm volatile("cp.async.wait_group 0;" ::: "memory");
    __syncthreads();

    uint32_t qf_h[4][4], qf_l[4][4];
#pragma unroll
    for (int ks = 0; ks < 4; ks++){
        int r = wid * 16 + (lane & 15);
        int seg = ks * 2 + (lane >> 4);
        uint32_t ad = sb + r * 128 + ((seg ^ (r & 7)) << 4);
        ldm_x4(qf_h[ks], ad);
        ldm_x4(qf_l[ks], ad + 16384);
    }

    float m0 = -1e30f, m1 = -1e30f, l0 = 0.f, l1 = 0.f;
    float acc_o[8][4] = {};
    int buf = 0;

    for (int kt = 0; kt < 32; kt++){
        if (kt < 31){
            uint32_t bo = sb + 32768 + (buf ^ 1) * 32768;
            int key0 = kv0 + (kt + 1) * 64;
#pragma unroll
            for (int it = 0; it < 2; it++){
                int i = tid + it * 256;
                int r = i >> 3, seg = i & 7;
                uint32_t so = r * 128 + ((seg ^ (r & 7)) << 4);
                cpa16(bo + so,         Kh + (size_t)(key0 + r) * 768 + seg * 8);
                cpa16(bo + 8192 + so,  Kl + (size_t)(key0 + r) * 768 + seg * 8);
                cpa16(bo + 16384 + so, Vh + (size_t)r * 4096 + key0 + seg * 8);
                cpa16(bo + 24576 + so, Vl + (size_t)r * 4096 + key0 + seg * 8);
            }
            cpa_commit();
            asm volatile("cp.async.wait_group 1;" ::: "memory");
        } else {
            asm volatile("cp.async.wait_group 0;" ::: "memory");
        }
        __syncthreads();

        uint32_t kb = sb + 32768 + buf * 32768;

        float acc_s[8][4] = {};
#pragma unroll
        for (int ks = 0; ks < 4; ks++){
            uint32_t bh[8][2], bl[8][2];
#pragma unroll
            for (int nt = 0; nt < 8; nt++){
                int r = nt * 8 + (lane & 7);
                int seg = ks * 2 + ((lane >> 3) & 1);
                uint32_t bd = kb + r * 128 + ((seg ^ (r & 7)) << 4);
                ldm_x2(bh[nt], bd);
                ldm_x2(bl[nt], bd + 8192);
            }
#pragma unroll
            for (int nt = 0; nt < 8; nt++){
                mma_bf16(acc_s[nt], qf_h[ks], bh[nt]);
                mma_bf16(acc_s[nt], qf_h[ks], bl[nt]);
                mma_bf16(acc_s[nt], qf_l[ks], bh[nt]);
            }
        }
#pragma unroll
        for (int nt = 0; nt < 8; nt++){
            acc_s[nt][0] *= 0.125f; acc_s[nt][1] *= 0.125f;
            acc_s[nt][2] *= 0.125f; acc_s[nt][3] *= 0.125f;
        }

        float tm0 = -1e30f, tm1 = -1e30f;
#pragma unroll
        for (int nt = 0; nt < 8; nt++){
            tm0 = fmaxf(tm0, fmaxf(acc_s[nt][0], acc_s[nt][1]));
            tm1 = fmaxf(tm1, fmaxf(acc_s[nt][2], acc_s[nt][3]));
        }
        tm0 = fmaxf(tm0, __shfl_xor_sync(~0u, tm0, 1)); tm0 = fmaxf(tm0, __shfl_xor_sync(~0u, tm0, 2));
        tm1 = fmaxf(tm1, __shfl_xor_sync(~0u, tm1, 1)); tm1 = fmaxf(tm1, __shfl_xor_sync(~0u, tm1, 2));
        float mn0 = fmaxf(m0, tm0), mn1 = fmaxf(m1, tm1);
        float sc0 = __expf(m0 - mn0), sc1 = __expf(m1 - mn1);
        m0 = mn0; m1 = mn1;
        l0 *= sc0; l1 *= sc1;
#pragma unroll
        for (int nt = 0; nt < 8; nt++){
            acc_o[nt][0] *= sc0; acc_o[nt][1] *= sc0;
            acc_o[nt][2] *= sc1; acc_o[nt][3] *= sc1;
        }
        float rs0 = 0.f, rs1 = 0.f;
        uint32_t pa_h[4][4], pa_l[4][4];
#pragma unroll
        for (int nt = 0; nt < 8; nt++){
            float p0 = __expf(acc_s[nt][0] - mn0), p1 = __expf(acc_s[nt][1] - mn0);
            float p2 = __expf(acc_s[nt][2] - mn1), p3 = __expf(acc_s[nt][3] - mn1);
            rs0 += p0 + p1; rs1 += p2 + p3;
            int k2 = nt >> 1;
            if (!(nt & 1)){
                splitpack(p0, p1, pa_h[k2][0], pa_l[k2][0]);
                splitpack(p2, p3, pa_h[k2][1], pa_l[k2][1]);
            } else {
                splitpack(p0, p1, pa_h[k2][2], pa_l[k2][2]);
                splitpack(p2, p3, pa_h[k2][3], pa_l[k2][3]);
            }
        }
        rs0 += __shfl_xor_sync(~0u, rs0, 1); rs0 += __shfl_xor_sync(~0u, rs0, 2);
        rs1 += __shfl_xor_sync(~0u, rs1, 1); rs1 += __shfl_xor_sync(~0u, rs1, 2);
        l0 += rs0; l1 += rs1;

        uint32_t vb = kb + 16384;
#pragma unroll
        for (int k2 = 0; k2 < 4; k2++){
            uint32_t vh[8][2], vl[8][2];
#pragma unroll
            for (int nt = 0; nt < 8; nt++){
                int r = nt * 8 + (lane & 7);
                int seg = k2 * 2 + ((lane >> 3) & 1);
                uint32_t vd = vb + r * 128 + ((seg ^ (r & 7)) << 4);
                ldm_x2(vh[nt], vd);
                ldm_x2(vl[nt], vd + 8192);
            }
#pragma unroll
            for (int nt = 0; nt < 8; nt++){
                mma_bf16(acc_o[nt], pa_h[k2], vh[nt]);
                mma_bf16(acc_o[nt], pa_h[k2], vl[nt]);
                mma_bf16(acc_o[nt], pa_l[k2], vh[nt]);
            }
        }
        __syncthreads();
        buf ^= 1;
    }

    int r = row0 + wid * 16 + (lane >> 2);
    size_t ro0 = ((size_t)z * NNODE + r) * 256;
    size_t ro1 = ((size_t)z * NNODE + r + 8) * 256;
#pragma unroll
    for (int nt = 0; nt < 8; nt++){
        int cc = head * 64 + nt * 8 + ((lane & 3) << 1);
        pO[ro0 + cc]     = acc_o[nt][0];
        pO[ro0 + cc + 1] = acc_o[nt][1];
        pO[ro1 + cc]     = acc_o[nt][2];
        pO[ro1 + cc + 1] = acc_o[nt][3];
    }
    if ((lane & 3) == 0){
        pML[((size_t)z * NNODE + r) * 8 + head * 2]     = m0;
        pML[((size_t)z * NNODE + r) * 8 + head * 2 + 1] = l0;
        pML[((size_t)z * NNODE + r + 8) * 8 + head * 2]     = m1;
        pML[((size_t)z * NNODE + r + 8) * 8 + head * 2 + 1] = l1;
    }
}

__global__ void k_fmerge(const float* __restrict__ pO, const float* __restrict__ pML,
                         __nv_bfloat16* __restrict__ Oh, __nv_bfloat16* __restrict__ Ol){
    int row = blockIdx.x, col = threadIdx.x;
    int head = col >> 6;
    float m0 = pML[(size_t)row * 8 + head * 2],            l0 = pML[(size_t)row * 8 + head * 2 + 1];
    float m1 = pML[((size_t)NNODE + row) * 8 + head * 2],  l1 = pML[((size_t)NNODE + row) * 8 + head * 2 + 1];
    float mx = fmaxf(m0, m1);
    float w0 = __expf(m0 - mx), w1 = __expf(m1 - mx);
    float num = pO[(size_t)row * 256 + col] * w0 + pO[((size_t)NNODE + row) * 256 + col] * w1;
    float den = l0 * w0 + l1 * w1;
    f2hl(num / den, Oh, Ol, (size_t)row * 256 + col);
}

// ================= pointwise (lstm + vt fused) =================
__global__ void k_lstmvt(const float* __restrict__ G, float* __restrict__ ht_out,
                         const __nv_bfloat16* __restrict__ qh, const __nv_bfloat16* __restrict__ ql,
                         __nv_bfloat16* __restrict__ vh, __nv_bfloat16* __restrict__ vl){
    int b = blockIdx.x;
    if (b < NNODE){
        int idx = b * 256 + threadIdx.x;
        int n = idx >> 8, j = idx & 255;
        const float* gr = G + (size_t)n * 1024;
        float ig = gr[j], gg = gr[512 + j], og = gr[768 + j];
        float cc = sigmf(ig) * tanhf(gg);
        float hv = sigmf(og) * tanhf(cc);
        ht_out[idx] = hv;
        f2hl(hv, g_hcath, g_hcatl, (size_t)n * 512 + j);
    } else {
        int idx = (b - NNODE) * 256 + threadIdx.x;
        int hd = idx >> 12, n = idx & 4095;
        size_t s = (size_t)n * 768 + 512 + hd;
        vh[idx] = qh[s]; vl[idx] = ql[s];
    }
}

// ================= launch =================
#define SYMADDR(p, s) do { void* _t; cudaGetSymbolAddress(&_t, s); p = (decltype(p))_t; } while(0)

extern "C" void kernel_launch(void* const* d_in, const int* in_sizes, int n_in,
                              void* d_out, int out_size) {
    const float* x     = (const float*)d_in[0];
    const int*   ei_t  = (const int*)d_in[1];
    const int*   ei_c  = (const int*)d_in[2];
    const float* ea_t  = (const float*)d_in[3];
    const float* ea_c  = (const float*)d_in[4];
    const float* W_t   = (const float*)d_in[5];
    const float* asrc_t= (const float*)d_in[6];
    const float* adst_t= (const float*)d_in[7];
    const float* We_t  = (const float*)d_in[8];
    const float* ae_t  = (const float*)d_in[9];
    const float* b_t   = (const float*)d_in[10];
    const float* W_c   = (const float*)d_in[11];
    const float* asrc_c= (const float*)d_in[12];
    const float* adst_c= (const float*)d_in[13];
    const float* We_c  = (const float*)d_in[14];
    const float* ae_c  = (const float*)d_in[15];
    const float* b_c   = (const float*)d_in[16];
    const float* lstm_Wih = (const float*)d_in[17];
    const float* lstm_bih = (const float*)d_in[19];
    const float* lstm_bhh = (const float*)d_in[20];
    const float* mha_in_w  = (const float*)d_in[21];
    const float* mha_in_b  = (const float*)d_in[22];
    const float* mha_out_w = (const float*)d_in[23];
    const float* mha_out_b = (const float*)d_in[24];
    const float* fus_w = (const float*)d_in[25];
    const float* fus_b = (const float*)d_in[26];
    const float* out_w = (const float*)d_in[27];
    const float* out_b = (const float*)d_in[28];

    float* big; SYMADDR(big, g_big);
    float* po;  SYMADDR(po, g_po);
    float* pml; SYMADDR(pml, g_pml);
    float* xp0; SYMADDR(xp0, g_xp);
    float* xp1 = xp0 + (size_t)NNODE * NHC;
    __nv_bfloat16 *hth, *htl, *hch, *hcl, *qkvh, *qkvl, *vth, *vtl;
    __nv_bfloat16 *attnh, *attnl, *hcath, *hcatl, *hfush, *hfusl;
    __nv_bfloat16 *wihh, *wihl, *inwh, *inwl, *mowh, *mowl, *fuwh, *fuwl, *owh, *owl;
    __nv_bfloat16 *xpadh, *xpadl, *wpadh, *wpadl;
    SYMADDR(hth, g_hth); SYMADDR(htl, g_htl); SYMADDR(hch, g_hch); SYMADDR(hcl, g_hcl);
    SYMADDR(qkvh, g_qkvh); SYMADDR(qkvl, g_qkvl); SYMADDR(vth, g_vth); SYMADDR(vtl, g_vtl);
    SYMADDR(attnh, g_attnh); SYMADDR(attnl, g_attnl);
    SYMADDR(hcath, g_hcath); SYMADDR(hcatl, g_hcatl);
    SYMADDR(hfush, g_hfush); SYMADDR(hfusl, g_hfusl);
    SYMADDR(wihh, g_wihh); SYMADDR(wihl, g_wihl);
    SYMADDR(inwh, g_inwh); SYMADDR(inwl, g_inwl);
    SYMADDR(mowh, g_mowh); SYMADDR(mowl, g_mowl);
    SYMADDR(fuwh, g_fuwh); SYMADDR(fuwl, g_fuwl);
    SYMADDR(owh, g_owh); SYMADDR(owl, g_owl);
    SYMADDR(xpadh, g_xpadh); SYMADDR(xpadl, g_xpadl);
    SYMADDR(wpadh, g_wpadh); SYMADDR(wpadl, g_wpadl);

    cudaFuncSetAttribute(k_flash, cudaFuncAttributeMaxDynamicSharedMemorySize, 98304);
    cudaFuncSetAttribute(mma_single, cudaFuncAttributeMaxDynamicSharedMemorySize, 98304);
    cudaFuncSetAttribute(mma_dual, cudaFuncAttributeMaxDynamicSharedMemorySize, 98304);
    const int DYN = 98304;

    float* out_main = (float*)d_out;
    float* out_ht   = out_main + (size_t)NNODE * NOUT;
    float* out_hc   = out_ht   + (size_t)NNODE * HID;

    const int* src_t = ei_t; const int* dst_t = ei_t + NE;
    const int* src_c = ei_c; const int* dst_c = ei_c + NE;
    int nepb = (NEP + 255) / 256, neb = (NE + 255) / 256;

    k_initmean<<<128, 256>>>(ea_t, ea_c);
    k_setup<<<1, 256>>>(We_t, ae_t, We_c, ae_c, lstm_bih, lstm_bhh);
    k_convall<<<(CW6 + 255) / 256, 256>>>(lstm_Wih, mha_in_w, mha_out_w, fus_w, out_w, x, W_t, W_c);

    // ---- xp = x @ W for both graphs (tensor cores, batched) ----
    {
        GA a0 = { xpadh, xpadl, wpadh, wpadl, xp0, nullptr, nullptr, nullptr,
                  64, 64, NHC, 0, 0, 64, 0, 32, 1.f };
        GA a1 = { xpadh, xpadl, wpadh + (size_t)NHC * 64, wpadl + (size_t)NHC * 64, xp1,
                  nullptr, nullptr, nullptr, 64, 64, NHC, 0, 0, 64, 0, 32, 1.f };
        mma_dual<<<dim3(32, 32, 2), 256, DYN>>>(a0, a1);
    }

    // ---- GAT edge pipeline (both graphs per launch) ----
    k_asd<<<dim3(NNODE, 2), 256>>>(asrc_t, adst_t, asrc_c, adst_c);
    k_count<<<dim3(neb, 2), 256>>>(dst_t, dst_c);
    k_scan<<<2, 1024>>>();
    k_scatter<<<dim3(neb, 2), 256>>>(dst_t, dst_c);
    k_alpha<<<dim3(nepb, 2), 256>>>(src_t, dst_t, ea_t, src_c, dst_c, ea_c);
    k_ex<<<dim3(nepb, 2), 256>>>(dst_t, dst_c);
    k_agg<<<dim3(NNODE, 2), 256>>>(src_t, src_c, b_t, b_c);

    // ---- qkv (z=0) + LSTM gates (z=1) in one launch ----
    {
        GA a0 = { hch, hcl, inwh, inwl, nullptr, qkvh, qkvl, mha_in_b,
                  256, 256, 0, 768, 0, 256, 0, 12, 1.f };
        GA a1 = { hth, htl, wihh, wihl, big + OFF_G, nullptr, nullptr, big + OFF_BSUM,
                  NHC, NHC, 1024, 0, 0, NHC, 0, 16, 1.f };
        mma_dual<<<dim3(16, 32, 2), 256, DYN>>>(a0, a1);
    }
    k_lstmvt<<<2 * NNODE, 256>>>(big + OFF_G, out_ht, qkvh, qkvl, vth, vtl);

    // ---- fused attention, split-KV x2 + merge ----
    k_flash<<<dim3(32, 4, 2), 256, DYN>>>(qkvh, qkvl, vth, vtl, po, pml);
    k_fmerge<<<NNODE, 256>>>(po, pml, attnh, attnl);

    // ---- proj (4096x256x256) ----
    {
        GA a = { attnh, attnl, mowh, mowl, out_hc, hcath, hcatl, mha_out_b,
                 256, 256, 256, 512, 256, 256, 0, 4, 1.f };
        mma_single<<<dim3(4, 32), 256, DYN>>>(a);
    }
    // ---- fusion relu (4096x256x512) ----
    {
        GA a = { hcath, hcatl, fuwh, fuwl, nullptr, hfush, hfusl, fus_b,
                 512, 512, 0, 256, 0, 512, 1, 4, 1.f };
        mma_single<<<dim3(4, 32), 256, DYN>>>(a);
    }
    // ---- out (4096x128x256) ----
    {
        GA a = { hfush, hfusl, owh, owl, out_main, nullptr, nullptr, out_b,
                 256, 256, NOUT, 0, 0, 256, 0, 2, 1.f };
        mma_single<<<dim3(2, 32), 256, DYN>>>(a);
    }
}

// round 9
// speedup vs baseline: 2.4063x; 1.0333x over previous
#include <cuda_runtime.h>
#include <cuda_bf16.h>
#include <math.h>
#include <float.h>
#include <stdint.h>

#define NNODE 4096
#define NIN   28
#define NE    131072
#define NEP   (NE + NNODE)
#define NH    8
#define NC    256
#define NHC   2048
#define HID   256
#define NOUT  128

// ---------------- fp32 scratch ----------------
#define OFF_G    ((size_t)0)
#define OFF_BSUM (OFF_G + (size_t)NNODE * 1024)
#define BIG_SZ   (OFF_BSUM + 1024)
__device__ float g_big[BIG_SZ];

__device__ float g_xp[2][(size_t)NNODE * NHC];
__device__ float g_as[2][NNODE * NH];
__device__ float g_ad[2][NNODE * NH];
__device__ float g_w [2][(size_t)NEP * NH];
__device__ int   g_mx[2][NNODE * NH];
__device__ float g_den[2][NNODE * NH];
__device__ int   g_cnt[2][NNODE];
__device__ int   g_cur[2][NNODE];
__device__ int   g_start[2][NNODE];
__device__ int   g_sorted[2][NE];
__device__ float g_part[2][128];
__device__ float g_mean[2];
__device__ float g_ce[2][NH];

// flash split-K partials
__device__ float g_po[(size_t)2 * NNODE * 256];
__device__ float g_pml[(size_t)2 * NNODE * 8];

// ---------------- bf16 hi/lo tensors ----------------
__device__ __nv_bfloat16 g_hth[(size_t)NNODE * NHC], g_htl[(size_t)NNODE * NHC];
__device__ __nv_bfloat16 g_hch[(size_t)NNODE * 256], g_hcl[(size_t)NNODE * 256];
__device__ __nv_bfloat16 g_qkvh[(size_t)NNODE * 768], g_qkvl[(size_t)NNODE * 768];
__device__ __nv_bfloat16 g_vth[(size_t)4 * 64 * NNODE], g_vtl[(size_t)4 * 64 * NNODE];
__device__ __nv_bfloat16 g_attnh[(size_t)NNODE * 256], g_attnl[(size_t)NNODE * 256];
__device__ __nv_bfloat16 g_hcath[(size_t)NNODE * 512], g_hcatl[(size_t)NNODE * 512];
__device__ __nv_bfloat16 g_hfush[(size_t)NNODE * 256], g_hfusl[(size_t)NNODE * 256];
// weights
__device__ __nv_bfloat16 g_wihh[1024 * 2048], g_wihl[1024 * 2048];
__device__ __nv_bfloat16 g_inwh[768 * 256],   g_inwl[768 * 256];
__device__ __nv_bfloat16 g_mowh[256 * 256],   g_mowl[256 * 256];
__device__ __nv_bfloat16 g_fuwh[256 * 512],   g_fuwl[256 * 512];
__device__ __nv_bfloat16 g_owh[128 * 256],    g_owl[128 * 256];
// padded x / W for tensor-core xp GEMM (K padded 28 -> 64)
__device__ __nv_bfloat16 g_xpadh[(size_t)NNODE * 64], g_xpadl[(size_t)NNODE * 64];
__device__ __nv_bfloat16 g_wpadh[(size_t)2 * NHC * 64], g_wpadl[(size_t)2 * NHC * 64];

// ---------------- helpers ----------------
__device__ __forceinline__ int   f2ord(float f){ int i = __float_as_int(f); return i >= 0 ? i : i ^ 0x7fffffff; }
__device__ __forceinline__ float ord2f(int k){ return __int_as_float(k >= 0 ? k : k ^ 0x7fffffff); }
__device__ __forceinline__ float sigmf(float x){ return 1.f / (1.f + expf(-x)); }
__device__ __forceinline__ void f2hl(float v, __nv_bfloat16* H, __nv_bfloat16* L, size_t i){
    __nv_bfloat16 h = __float2bfloat16(v);
    H[i] = h; L[i] = __float2bfloat16(v - __bfloat162float(h));
}
__device__ __forceinline__ uint32_t smem_u32(const void* p){
    uint32_t a;
    asm("{ .reg .u64 t; cvta.to.shared.u64 t, %1; cvt.u32.u64 %0, t; }" : "=r"(a) : "l"(p));
    return a;
}
__device__ __forceinline__ void ldm_x4(uint32_t* r, uint32_t addr){
    asm volatile("ldmatrix.sync.aligned.m8n8.x4.shared.b16 {%0,%1,%2,%3}, [%4];"
        : "=r"(r[0]), "=r"(r[1]), "=r"(r[2]), "=r"(r[3]) : "r"(addr));
}
__device__ __forceinline__ void ldm_x2(uint32_t* r, uint32_t addr){
    asm volatile("ldmatrix.sync.aligned.m8n8.x2.shared.b16 {%0,%1}, [%2];"
        : "=r"(r[0]), "=r"(r[1]) : "r"(addr));
}
__device__ __forceinline__ void mma_bf16(float* c, const uint32_t* a, const uint32_t* b){
    asm volatile("mma.sync.aligned.m16n8k16.row.col.f32.bf16.bf16.f32 "
        "{%0,%1,%2,%3}, {%4,%5,%6,%7}, {%8,%9}, {%0,%1,%2,%3};"
        : "+f"(c[0]), "+f"(c[1]), "+f"(c[2]), "+f"(c[3])
        : "r"(a[0]), "r"(a[1]), "r"(a[2]), "r"(a[3]), "r"(b[0]), "r"(b[1]));
}
__device__ __forceinline__ void cpa16(uint32_t saddr, const void* g){
    asm volatile("cp.async.ca.shared.global [%0], [%1], 16;" :: "r"(saddr), "l"(g));
}
__device__ __forceinline__ void cpa_commit(){ asm volatile("cp.async.commit_group;" ::: "memory"); }
__device__ __forceinline__ void splitpack(float a, float b, uint32_t& hi, uint32_t& lo){
    __nv_bfloat16 ha = __float2bfloat16(a), hb = __float2bfloat16(b);
    __nv_bfloat16 la = __float2bfloat16(a - __bfloat162float(ha));
    __nv_bfloat16 lb = __float2bfloat16(b - __bfloat162float(hb));
    hi = ((uint32_t)__bfloat16_as_ushort(hb) << 16) | (uint32_t)__bfloat16_as_ushort(ha);
    lo = ((uint32_t)__bfloat16_as_ushort(lb) << 16) | (uint32_t)__bfloat16_as_ushort(la);
}

// ================= setup =================
__global__ void k_initmean(const float* __restrict__ ea_t, const float* __restrict__ ea_c){
    int idx = blockIdx.x * 256 + threadIdx.x, stride = gridDim.x * 256;
    int mi = f2ord(-FLT_MAX);
    for (int i = idx; i < NNODE * NH; i += stride){
        g_mx[0][i] = mi; g_mx[1][i] = mi;
        g_den[0][i] = 0.f; g_den[1][i] = 0.f;
        g_as[0][i] = 0.f; g_as[1][i] = 0.f;
        g_ad[0][i] = 0.f; g_ad[1][i] = 0.f;
    }
    for (int i = idx; i < NNODE; i += stride){
        g_cnt[0][i] = 0; g_cnt[1][i] = 0;
        g_cur[0][i] = 0; g_cur[1][i] = 0;
    }
    __shared__ float s0[256], s1[256];
    float a = 0.f, b = 0.f;
    for (int i = blockIdx.x * 256 + threadIdx.x; i < NE; i += 128 * 256){ a += ea_t[i]; b += ea_c[i]; }
    s0[threadIdx.x] = a; s1[threadIdx.x] = b; __syncthreads();
    for (int s = 128; s; s >>= 1){
        if (threadIdx.x < s){ s0[threadIdx.x] += s0[threadIdx.x+s]; s1[threadIdx.x] += s1[threadIdx.x+s]; }
        __syncthreads();
    }
    if (!threadIdx.x){ g_part[0][blockIdx.x] = s0[0]; g_part[1][blockIdx.x] = s1[0]; }
}

__global__ void k_setup(const float* __restrict__ We_t, const float* __restrict__ ae_t,
                        const float* __restrict__ We_c, const float* __restrict__ ae_c,
                        const float* __restrict__ bih,  const float* __restrict__ bhh){
    __shared__ float sh[256];
    int tid = threadIdx.x;
    for (int g = 0; g < 2; g++){
        sh[tid] = (tid < 128) ? g_part[g][tid] : 0.f;
        __syncthreads();
        for (int s = 128; s; s >>= 1){ if (tid < s) sh[tid] += sh[tid+s]; __syncthreads(); }
        if (!tid) g_mean[g] = sh[0] / (float)NE;
        __syncthreads();
    }
    int wid = tid >> 5, lane = tid & 31;
    for (int c = wid; c < 16; c += 8){
        int g = c >> 3, h = c & 7;
        const float* We = g ? We_c : We_t;
        const float* ae = g ? ae_c : ae_t;
        float s = 0.f;
        for (int i = lane; i < NC; i += 32) s = fmaf(We[h*NC + i], ae[h*NC + i], s);
        for (int o = 16; o; o >>= 1) s += __shfl_down_sync(0xffffffffu, s, o);
        if (!lane) g_ce[g][h] = s;
    }
    for (int j = tid; j < 1024; j += 256) g_big[OFF_BSUM + j] = bih[j] + bhh[j];
}

#define CW0 2097152
#define CW1 (CW0 + 196608)
#define CW2 (CW1 + 65536)
#define CW3 (CW2 + 131072)
#define CW4 (CW3 + 32768)
#define CW5 (CW4 + NNODE * 64)
#define CW6 (CW5 + 2 * NHC * 64)
__global__ void k_convall(const float* __restrict__ w0, const float* __restrict__ w1,
                          const float* __restrict__ w2, const float* __restrict__ w3,
                          const float* __restrict__ w4, const float* __restrict__ x,
                          const float* __restrict__ W_t, const float* __restrict__ W_c){
    int i = blockIdx.x * 256 + threadIdx.x;
    if (i < CW0)      f2hl(w0[i], g_wihh, g_wihl, i);
    else if (i < CW1) f2hl(w1[i - CW0], g_inwh, g_inwl, i - CW0);
    else if (i < CW2) f2hl(w2[i - CW1], g_mowh, g_mowl, i - CW1);
    else if (i < CW3) f2hl(w3[i - CW2], g_fuwh, g_fuwl, i - CW2);
    else if (i < CW4) f2hl(w4[i - CW3], g_owh, g_owl, i - CW3);
    else if (i < CW5){
        int j = i - CW4; int n = j >> 6, k = j & 63;
        float v = (k < NIN) ? x[n * NIN + k] : 0.f;
        f2hl(v, g_xpadh, g_xpadl, j);
    } else if (i < CW6){
        int j = i - CW5; int g = j >> 17; int r = j & 131071;
        int n = r >> 6, k = r & 63;
        const float* W = g ? W_c : W_t;
        float v = (k < NIN) ? W[k * NHC + n] : 0.f;
        f2hl(v, g_wpadh, g_wpadl, j);
    }
}

// ================= GAT edge pipeline =================
__global__ void k_count(const int* __restrict__ dst_t, const int* __restrict__ dst_c){
    int g = blockIdx.y;
    const int* dst = g ? dst_c : dst_t;
    int e = blockIdx.x * 256 + threadIdx.x;
    if (e < NE) atomicAdd(&g_cnt[g][dst[e]], 1);
}

__global__ void k_scan(){
    int g = blockIdx.x, tid = threadIdx.x;
    __shared__ int sh[1024];
    int base = tid * 4;
    int c0 = g_cnt[g][base], c1 = g_cnt[g][base+1], c2 = g_cnt[g][base+2], c3 = g_cnt[g][base+3];
    int s = c0 + c1 + c2 + c3;
    sh[tid] = s; __syncthreads();
    for (int off = 1; off < 1024; off <<= 1){
        int v = (tid >= off) ? sh[tid - off] : 0;
        __syncthreads();
        sh[tid] += v;
        __syncthreads();
    }
    int excl = sh[tid] - s;
    g_start[g][base]   = excl;
    g_start[g][base+1] = excl + c0;
    g_start[g][base+2] = excl + c0 + c1;
    g_start[g][base+3] = excl + c0 + c1 + c2;
}

// fused: scatter (counting-sort placement) + alpha (attention logits + seg-max)
__global__ void k_scatalpha(const int* __restrict__ src_t, const int* __restrict__ dst_t, const float* __restrict__ ea_t,
                            const int* __restrict__ src_c, const int* __restrict__ dst_c, const float* __restrict__ ea_c){
    int g = blockIdx.y;
    const int* src = g ? src_c : src_t;
    const int* dst = g ? dst_c : dst_t;
    const float* ea = g ? ea_c : ea_t;
    int e = blockIdx.x * 256 + threadIdx.x;
    if (e >= NEP) return;
    int s, d; float av;
    if (e < NE){
        s = src[e]; d = dst[e]; av = ea[e];
        int pos = g_start[g][d] + atomicAdd(&g_cur[g][d], 1);
        g_sorted[g][pos] = e;
    } else { s = d = e - NE; av = g_mean[g]; }
#pragma unroll
    for (int h = 0; h < NH; h++){
        float al = g_as[g][s*NH + h] + g_ad[g][d*NH + h] + av * g_ce[g][h];
        al = al > 0.f ? al : 0.2f * al;
        g_w[g][(size_t)e * NH + h] = al;
        atomicMax(&g_mx[g][d*NH + h], f2ord(al));
    }
}

__global__ void k_ex(const int* __restrict__ dst_t, const int* __restrict__ dst_c){
    int g = blockIdx.y;
    const int* dst = g ? dst_c : dst_t;
    int e = blockIdx.x * 256 + threadIdx.x;
    if (e >= NEP) return;
    int d = (e < NE) ? dst[e] : e - NE;
#pragma unroll
    for (int h = 0; h < NH; h++){
        float al = g_w[g][(size_t)e * NH + h];
        float ex = expf(al - ord2f(g_mx[g][d*NH + h]));
        g_w[g][(size_t)e * NH + h] = ex;
        atomicAdd(&g_den[g][d*NH + h], ex);
    }
}

__global__ void __launch_bounds__(256) k_agg(const int* __restrict__ src_t, const int* __restrict__ src_c,
                                             const float* __restrict__ b_t, const float* __restrict__ b_c){
    int g = blockIdx.y;
    const int* src = g ? src_c : src_t;
    const float* bias = g ? b_c : b_t;
    int n = blockIdx.x, t = threadIdx.x;
    const float* xp = g_xp[g];
    const float* w  = g_w[g];
    float acc[NH];
    {
        size_t e = (size_t)(NE + n) * NH;
        const float* xr = xp + (size_t)n * NHC + t;
#pragma unroll
        for (int h = 0; h < NH; h++) acc[h] = w[e + h] * xr[h * NC];
    }
    __shared__ int   ssrc[32];
    __shared__ float sw[32][NH];
    int st = g_start[g][n], c = g_cnt[g][n];
    for (int i0 = 0; i0 < c; i0 += 32){
        int m = min(32, c - i0);
        __syncthreads();
        if (t < m) ssrc[t] = src[g_sorted[g][st + i0 + t]];
        {
            int j = t >> 3, h = t & 7;
            if (j < m) sw[j][h] = w[(size_t)g_sorted[g][st + i0 + j] * NH + h];
        }
        __syncthreads();
        int jj = 0;
        for (; jj + 4 <= m; jj += 4){
            const float* x0 = xp + (size_t)ssrc[jj+0] * NHC + t;
            const float* x1 = xp + (size_t)ssrc[jj+1] * NHC + t;
            const float* x2 = xp + (size_t)ssrc[jj+2] * NHC + t;
            const float* x3 = xp + (size_t)ssrc[jj+3] * NHC + t;
            float v0[NH], v1[NH], v2[NH], v3[NH];
#pragma unroll
            for (int h = 0; h < NH; h++){ v0[h] = x0[h*NC]; v1[h] = x1[h*NC]; v2[h] = x2[h*NC]; v3[h] = x3[h*NC]; }
#pragma unroll
            for (int h = 0; h < NH; h++){
                acc[h] = fmaf(sw[jj+0][h], v0[h], acc[h]);
                acc[h] = fmaf(sw[jj+1][h], v1[h], acc[h]);
                acc[h] = fmaf(sw[jj+2][h], v2[h], acc[h]);
                acc[h] = fmaf(sw[jj+3][h], v3[h], acc[h]);
            }
        }
        for (; jj < m; jj++){
            const float* xr = xp + (size_t)ssrc[jj] * NHC + t;
#pragma unroll
            for (int h = 0; h < NH; h++) acc[h] = fmaf(sw[jj][h], xr[h * NC], acc[h]);
        }
    }
    const float* den = g_den[g] + n * NH;
    if (g == 0){
#pragma unroll
        for (int h = 0; h < NH; h++){
            float v = acc[h] / (den[h] + 1e-16f) + bias[h * NC + t];
            f2hl(v, g_hth, g_htl, (size_t)n * NHC + h * NC + t);
        }
    } else {
        float s = 0.f;
#pragma unroll
        for (int h = 0; h < NH; h++) s += acc[h] / (den[h] + 1e-16f);
        f2hl(s * 0.125f + bias[t], g_hch, g_hcl, (size_t)n * NC + t);
    }
}

// ================= HMMA bf16x3 GEMM core (cp.async 2-stage pipelined) =================
struct GA {
    const __nv_bfloat16 *Ah, *Al, *Bh, *Bl;
    float* C;
    __nv_bfloat16 *Ch, *Cl;
    const float* bias;
    const float *pas, *pad;    // optional: fused a_src/a_dst dot (xp GEMM)
    float *oas, *oad;
    int lda, ldb, ldc, ldc2, c2off, K, act, gx;
    float alpha;
};

__device__ __forceinline__ void gemm_core(const GA a){
    extern __shared__ char sm[];
    int tid = threadIdx.x, lane = tid & 31, wid = tid >> 5;
    int wm = wid & 3, wn = wid >> 2;
    int row0 = blockIdx.y * 128, col0 = blockIdx.x * 64;
    const __nv_bfloat16* Ah = a.Ah + (size_t)row0 * a.lda;
    const __nv_bfloat16* Al = a.Al + (size_t)row0 * a.lda;
    const __nv_bfloat16* Bh = a.Bh + (size_t)col0 * a.ldb;
    const __nv_bfloat16* Bl = a.Bl + (size_t)col0 * a.ldb;

    uint32_t sbase = smem_u32(sm);
    int nkb = a.K >> 6;

    auto issue = [&](int kb, int st){
        uint32_t su = sbase + st * 49152;
        int k0 = kb << 6;
#pragma unroll
        for (int it = 0; it < 4; it++){
            int i = tid + it * 256;
            int row = i >> 3, seg = i & 7;
            size_t goff = (size_t)row * a.lda + k0 + seg * 8;
            uint32_t so = row * 128 + ((seg ^ (row & 7)) << 4);
            cpa16(su + so,         Ah + goff);
            cpa16(su + 16384 + so, Al + goff);
        }
#pragma unroll
        for (int it = 0; it < 2; it++){
            int i = tid + it * 256;
            int row = i >> 3, seg = i & 7;
            size_t goff = (size_t)row * a.ldb + k0 + seg * 8;
            uint32_t so = row * 128 + ((seg ^ (row & 7)) << 4);
            cpa16(su + 32768 + so, Bh + goff);
            cpa16(su + 40960 + so, Bl + goff);
        }
        cpa_commit();
    };

    issue(0, 0);
    if (nkb > 1) issue(1, 1);

    float acc[2][4][4] = {};
    for (int kb = 0; kb < nkb; kb++){
        if (kb + 1 < nkb) asm volatile("cp.async.wait_group 1;" ::: "memory");
        else              asm volatile("cp.async.wait_group 0;" ::: "memory");
        __syncthreads();
        uint32_t sb2 = sbase + (kb & 1) * 49152;
#pragma unroll
        for (int ks = 0; ks < 4; ks++){
            uint32_t a_h[2][4], a_l[2][4], b_h[4][2], b_l[4][2];
#pragma unroll
            for (int mt = 0; mt < 2; mt++){
                int r = wm * 32 + mt * 16 + (lane & 15);
                int seg = ks * 2 + (lane >> 4);
                uint32_t ad = sb2 + r * 128 + ((seg ^ (r & 7)) << 4);
                ldm_x4(a_h[mt], ad);
                ldm_x4(a_l[mt], ad + 16384);
            }
#pragma unroll
            for (int nt = 0; nt < 4; nt++){
                int r = wn * 32 + nt * 8 + (lane & 7);
                int seg = ks * 2 + ((lane >> 3) & 1);
                uint32_t bd = sb2 + 32768 + r * 128 + ((seg ^ (r & 7)) << 4);
                ldm_x2(b_h[nt], bd);
                ldm_x2(b_l[nt], bd + 8192);
            }
#pragma unroll
            for (int mt = 0; mt < 2; mt++)
#pragma unroll
                for (int nt = 0; nt < 4; nt++){
                    mma_bf16(acc[mt][nt], a_h[mt], b_h[nt]);
                    mma_bf16(acc[mt][nt], a_h[mt], b_l[nt]);
                    mma_bf16(acc[mt][nt], a_l[mt], b_h[nt]);
                }
        }
        __syncthreads();
        if (kb + 2 < nkb) issue(kb + 2, kb & 1);
    }

    float s1[4] = {}, s2[4] = {};
    int h = col0 >> 8;   // head index (only used when pas != null; 64-col tile within one head)
#pragma unroll
    for (int mt = 0; mt < 2; mt++){
#pragma unroll
        for (int nt = 0; nt < 4; nt++){
            int r0 = row0 + wm * 32 + mt * 16 + (lane >> 2);
            int c0 = col0 + wn * 32 + nt * 8 + ((lane & 3) << 1);
#pragma unroll
            for (int q = 0; q < 4; q++){
                int r = r0 + (q >> 1) * 8;
                int cc = c0 + (q & 1);
                float v = acc[mt][nt][q] * a.alpha;
                if (a.bias) v += a.bias[cc];
                if (a.act == 1) v = fmaxf(v, 0.f);
                if (a.C) a.C[(size_t)r * a.ldc + cc] = v;
                if (a.Ch) f2hl(v, a.Ch, a.Cl, (size_t)r * a.ldc2 + a.c2off + cc);
                if (a.pas){
                    int ridx = mt * 2 + (q >> 1);
                    int ci = h * 256 + (cc & 255);
                    s1[ridx] = fmaf(v, a.pas[ci], s1[ridx]);
                    s2[ridx] = fmaf(v, a.pad[ci], s2[ridx]);
                }
            }
        }
    }
    if (a.pas){
#pragma unroll
        for (int i = 0; i < 4; i++){
            s1[i] += __shfl_xor_sync(~0u, s1[i], 1); s1[i] += __shfl_xor_sync(~0u, s1[i], 2);
            s2[i] += __shfl_xor_sync(~0u, s2[i], 1); s2[i] += __shfl_xor_sync(~0u, s2[i], 2);
        }
        if ((lane & 3) == 0){
#pragma unroll
            for (int i = 0; i < 4; i++){
                int mt = i >> 1, rr = i & 1;
                int r = row0 + wm * 32 + mt * 16 + (lane >> 2) + rr * 8;
                atomicAdd(&a.oas[r * NH + h], s1[i]);
                atomicAdd(&a.oad[r * NH + h], s2[i]);
            }
        }
    }
}

__global__ void __launch_bounds__(256) mma_single(GA a){
    if ((int)blockIdx.x >= a.gx) return;
    gemm_core(a);
}
__global__ void __launch_bounds__(256) mma_dual(GA a0, GA a1){
    GA a = blockIdx.z ? a1 : a0;
    if ((int)blockIdx.x >= a.gx) return;
    gemm_core(a);
}

// ================= flash attention (split-KV, 2 partials) =================
__global__ void __launch_bounds__(256) k_flash(
    const __nv_bfloat16* __restrict__ qkvh, const __nv_bfloat16* __restrict__ qkvl,
    const __nv_bfloat16* __restrict__ vth, const __nv_bfloat16* __restrict__ vtl,
    float* __restrict__ pO, float* __restrict__ pML)
{
    extern __shared__ char sm[];
    int tid = threadIdx.x, lane = tid & 31, wid = tid >> 5;
    int head = blockIdx.y;
    int row0 = blockIdx.x * 128;
    int z = blockIdx.z;
    int kv0 = z * 2048;
    uint32_t sb = smem_u32(sm);

    const __nv_bfloat16* Qh = qkvh + (size_t)row0 * 768 + head * 64;
    const __nv_bfloat16* Ql = qkvl + (size_t)row0 * 768 + head * 64;
    const __nv_bfloat16* Kh = qkvh + 256 + head * 64;
    const __nv_bfloat16* Kl = qkvl + 256 + head * 64;
    const __nv_bfloat16* Vh = vth + (size_t)head * 64 * 4096;
    const __nv_bfloat16* Vl = vtl + (size_t)head * 64 * 4096;

#pragma unroll
    for (int it = 0; it < 4; it++){
        int i = tid + it * 256;
        int r = i >> 3, seg = i & 7;
        uint32_t so = r * 128 + ((seg ^ (r & 7)) << 4);
        cpa16(sb + so,         Qh + (size_t)r * 768 + seg * 8);
        cpa16(sb + 16384 + so, Ql + (size_t)r * 768 + seg * 8);
    }
#pragma unroll
    for (int it = 0; it < 2; it++){
        int i = tid + it * 256;
        int r = i >> 3, seg = i & 7;
        uint32_t so = r * 128 + ((seg ^ (r & 7)) << 4);
        cpa16(sb + 32768 + so,         Kh + (size_t)(kv0 + r) * 768 + seg * 8);
        cpa16(sb + 32768 + 8192 + so,  Kl + (size_t)(kv0 + r) * 768 + seg * 8);
        cpa16(sb + 32768 + 16384 + so, Vh + (size_t)r * 4096 + kv0 + seg * 8);
        cpa16(sb + 32768 + 24576 + so, Vl + (size_t)r * 4096 + kv0 + seg * 8);
    }
    cpa_commit();
    asm volatile("cp.async.wait_group 0;" ::: "memory");
    __syncthreads();

    uint32_t qf_h[4][4], qf_l[4][4];
#pragma unroll
    for (int ks = 0; ks < 4; ks++){
        int r = wid * 16 + (lane & 15);
        int seg = ks * 2 + (lane >> 4);
        uint32_t ad = sb + r * 128 + ((seg ^ (r & 7)) << 4);
        ldm_x4(qf_h[ks], ad);
        ldm_x4(qf_l[ks], ad + 16384);
    }

    float m0 = -1e30f, m1 = -1e30f, l0 = 0.f, l1 = 0.f;
    float acc_o[8][4] = {};
    int buf = 0;

    for (int kt = 0; kt < 32; kt++){
        if (kt < 31){
            uint32_t bo = sb + 32768 + (buf ^ 1) * 32768;
            int key0 = kv0 + (kt + 1) * 64;
#pragma unroll
            for (int it = 0; it < 2; it++){
                int i = tid + it * 256;
                int r = i >> 3, seg = i & 7;
                uint32_t so = r * 128 + ((seg ^ (r & 7)) << 4);
                cpa16(bo + so,         Kh + (size_t)(key0 + r) * 768 + seg * 8);
                cpa16(bo + 8192 + so,  Kl + (size_t)(key0 + r) * 768 + seg * 8);
                cpa16(bo + 16384 + so, Vh + (size_t)r * 4096 + key0 + seg * 8);
                cpa16(bo + 24576 + so, Vl + (size_t)r * 4096 + key0 + seg * 8);
            }
            cpa_commit();
            asm volatile("cp.async.wait_group 1;" ::: "memory");
        } else {
            asm volatile("cp.async.wait_group 0;" ::: "memory");
        }
        __syncthreads();

        uint32_t kb = sb + 32768 + buf * 32768;

        float acc_s[8][4] = {};
#pragma unroll
        for (int ks = 0; ks < 4; ks++){
            uint32_t bh[8][2], bl[8][2];
#pragma unroll
            for (int nt = 0; nt < 8; nt++){
                int r = nt * 8 + (lane & 7);
                int seg = ks * 2 + ((lane >> 3) & 1);
                uint32_t bd = kb + r * 128 + ((seg ^ (r & 7)) << 4);
                ldm_x2(bh[nt], bd);
                ldm_x2(bl[nt], bd + 8192);
            }
#pragma unroll
            for (int nt = 0; nt < 8; nt++){
                mma_bf16(acc_s[nt], qf_h[ks], bh[nt]);
                mma_bf16(acc_s[nt], qf_h[ks], bl[nt]);
                mma_bf16(acc_s[nt], qf_l[ks], bh[nt]);
            }
        }
#pragma unroll
        for (int nt = 0; nt < 8; nt++){
            acc_s[nt][0] *= 0.125f; acc_s[nt][1] *= 0.125f;
            acc_s[nt][2] *= 0.125f; acc_s[nt][3] *= 0.125f;
        }

        float tm0 = -1e30f, tm1 = -1e30f;
#pragma unroll
        for (int nt = 0; nt < 8; nt++){
            tm0 = fmaxf(tm0, fmaxf(acc_s[nt][0], acc_s[nt][1]));
            tm1 = fmaxf(tm1, fmaxf(acc_s[nt][2], acc_s[nt][3]));
        }
        tm0 = fmaxf(tm0, __shfl_xor_sync(~0u, tm0, 1)); tm0 = fmaxf(tm0, __shfl_xor_sync(~0u, tm0, 2));
        tm1 = fmaxf(tm1, __shfl_xor_sync(~0u, tm1, 1)); tm1 = fmaxf(tm1, __shfl_xor_sync(~0u, tm1, 2));
        float mn0 = fmaxf(m0, tm0), mn1 = fmaxf(m1, tm1);
        float sc0 = __expf(m0 - mn0), sc1 = __expf(m1 - mn1);
        m0 = mn0; m1 = mn1;
        l0 *= sc0; l1 *= sc1;
#pragma unroll
        for (int nt = 0; nt < 8; nt++){
            acc_o[nt][0] *= sc0; acc_o[nt][1] *= sc0;
            acc_o[nt][2] *= sc1; acc_o[nt][3] *= sc1;
        }
        float rs0 = 0.f, rs1 = 0.f;
        uint32_t pa_h[4][4], pa_l[4][4];
#pragma unroll
        for (int nt = 0; nt < 8; nt++){
            float p0 = __expf(acc_s[nt][0] - mn0), p1 = __expf(acc_s[nt][1] - mn0);
            float p2 = __expf(acc_s[nt][2] - mn1), p3 = __expf(acc_s[nt][3] - mn1);
            rs0 += p0 + p1; rs1 += p2 + p3;
            int k2 = nt >> 1;
            if (!(nt & 1)){
                splitpack(p0, p1, pa_h[k2][0], pa_l[k2][0]);
                splitpack(p2, p3, pa_h[k2][1], pa_l[k2][1]);
            } else {
                splitpack(p0, p1, pa_h[k2][2], pa_l[k2][2]);
                splitpack(p2, p3, pa_h[k2][3], pa_l[k2][3]);
            }
        }
        rs0 += __shfl_xor_sync(~0u, rs0, 1); rs0 += __shfl_xor_sync(~0u, rs0, 2);
        rs1 += __shfl_xor_sync(~0u, rs1, 1); rs1 += __shfl_xor_sync(~0u, rs1, 2);
        l0 += rs0; l1 += rs1;

        uint32_t vb = kb + 16384;
#pragma unroll
        for (int k2 = 0; k2 < 4; k2++){
            uint32_t vh[8][2], vl[8][2];
#pragma unroll
            for (int nt = 0; nt < 8; nt++){
                int r = nt * 8 + (lane & 7);
                int seg = k2 * 2 + ((lane >> 3) & 1);
                uint32_t vd = vb + r * 128 + ((seg ^ (r & 7)) << 4);
                ldm_x2(vh[nt], vd);
                ldm_x2(vl[nt], vd + 8192);
            }
#pragma unroll
            for (int nt = 0; nt < 8; nt++){
                mma_bf16(acc_o[nt], pa_h[k2], vh[nt]);
                mma_bf16(acc_o[nt], pa_h[k2], vl[nt]);
                mma_bf16(acc_o[nt], pa_l[k2], vh[nt]);
            }
        }
        __syncthreads();
        buf ^= 1;
    }

    int r = row0 + wid * 16 + (lane >> 2);
    size_t ro0 = ((size_t)z * NNODE + r) * 256;
    size_t ro1 = ((size_t)z * NNODE + r + 8) * 256;
#pragma unroll
    for (int nt = 0; nt < 8; nt++){
        int cc = head * 64 + nt * 8 + ((lane & 3) << 1);
        pO[ro0 + cc]     = acc_o[nt][0];
        pO[ro0 + cc + 1] = acc_o[nt][1];
        pO[ro1 + cc]     = acc_o[nt][2];
        pO[ro1 + cc + 1] = acc_o[nt][3];
    }
    if ((lane & 3) == 0){
        pML[((size_t)z * NNODE + r) * 8 + head * 2]     = m0;
        pML[((size_t)z * NNODE + r) * 8 + head * 2 + 1] = l0;
        pML[((size_t)z * NNODE + r + 8) * 8 + head * 2]     = m1;
        pML[((size_t)z * NNODE + r + 8) * 8 + head * 2 + 1] = l1;
    }
}

__global__ void k_fmerge(const float* __restrict__ pO, const float* __restrict__ pML,
                         __nv_bfloat16* __restrict__ Oh, __nv_bfloat16* __restrict__ Ol){
    int row = blockIdx.x, col = threadIdx.x;
    int head = col >> 6;
    float m0 = pML[(size_t)row * 8 + head * 2],            l0 = pML[(size_t)row * 8 + head * 2 + 1];
    float m1 = pML[((size_t)NNODE + row) * 8 + head * 2],  l1 = pML[((size_t)NNODE + row) * 8 + head * 2 + 1];
    float mx = fmaxf(m0, m1);
    float w0 = __expf(m0 - mx), w1 = __expf(m1 - mx);
    float num = pO[(size_t)row * 256 + col] * w0 + pO[((size_t)NNODE + row) * 256 + col] * w1;
    float den = l0 * w0 + l1 * w1;
    f2hl(num / den, Oh, Ol, (size_t)row * 256 + col);
}

// ================= pointwise (lstm + vt fused) =================
__global__ void k_lstmvt(const float* __restrict__ G, float* __restrict__ ht_out,
                         const __nv_bfloat16* __restrict__ qh, const __nv_bfloat16* __restrict__ ql,
                         __nv_bfloat16* __restrict__ vh, __nv_bfloat16* __restrict__ vl){
    int b = blockIdx.x;
    if (b < NNODE){
        int idx = b * 256 + threadIdx.x;
        int n = idx >> 8, j = idx & 255;
        const float* gr = G + (size_t)n * 1024;
        float ig = gr[j], gg = gr[512 + j], og = gr[768 + j];
        float cc = sigmf(ig) * tanhf(gg);
        float hv = sigmf(og) * tanhf(cc);
        ht_out[idx] = hv;
        f2hl(hv, g_hcath, g_hcatl, (size_t)n * 512 + j);
    } else {
        int idx = (b - NNODE) * 256 + threadIdx.x;
        int hd = idx >> 12, n = idx & 4095;
        size_t s = (size_t)n * 768 + 512 + hd;
        vh[idx] = qh[s]; vl[idx] = ql[s];
    }
}

// ================= launch =================
#define SYMADDR(p, s) do { void* _t; cudaGetSymbolAddress(&_t, s); p = (decltype(p))_t; } while(0)

extern "C" void kernel_launch(void* const* d_in, const int* in_sizes, int n_in,
                              void* d_out, int out_size) {
    const float* x     = (const float*)d_in[0];
    const int*   ei_t  = (const int*)d_in[1];
    const int*   ei_c  = (const int*)d_in[2];
    const float* ea_t  = (const float*)d_in[3];
    const float* ea_c  = (const float*)d_in[4];
    const float* W_t   = (const float*)d_in[5];
    const float* asrc_t= (const float*)d_in[6];
    const float* adst_t= (const float*)d_in[7];
    const float* We_t  = (const float*)d_in[8];
    const float* ae_t  = (const float*)d_in[9];
    const float* b_t   = (const float*)d_in[10];
    const float* W_c   = (const float*)d_in[11];
    const float* asrc_c= (const float*)d_in[12];
    const float* adst_c= (const float*)d_in[13];
    const float* We_c  = (const float*)d_in[14];
    const float* ae_c  = (const float*)d_in[15];
    const float* b_c   = (const float*)d_in[16];
    const float* lstm_Wih = (const float*)d_in[17];
    const float* lstm_bih = (const float*)d_in[19];
    const float* lstm_bhh = (const float*)d_in[20];
    const float* mha_in_w  = (const float*)d_in[21];
    const float* mha_in_b  = (const float*)d_in[22];
    const float* mha_out_w = (const float*)d_in[23];
    const float* mha_out_b = (const float*)d_in[24];
    const float* fus_w = (const float*)d_in[25];
    const float* fus_b = (const float*)d_in[26];
    const float* out_w = (const float*)d_in[27];
    const float* out_b = (const float*)d_in[28];

    float* big; SYMADDR(big, g_big);
    float* po;  SYMADDR(po, g_po);
    float* pml; SYMADDR(pml, g_pml);
    float* xp0; SYMADDR(xp0, g_xp);
    float* xp1 = xp0 + (size_t)NNODE * NHC;
    float* as0; SYMADDR(as0, g_as);
    float* as1 = as0 + NNODE * NH;
    float* ad0; SYMADDR(ad0, g_ad);
    float* ad1 = ad0 + NNODE * NH;
    __nv_bfloat16 *hth, *htl, *hch, *hcl, *qkvh, *qkvl, *vth, *vtl;
    __nv_bfloat16 *attnh, *attnl, *hcath, *hcatl, *hfush, *hfusl;
    __nv_bfloat16 *wihh, *wihl, *inwh, *inwl, *mowh, *mowl, *fuwh, *fuwl, *owh, *owl;
    __nv_bfloat16 *xpadh, *xpadl, *wpadh, *wpadl;
    SYMADDR(hth, g_hth); SYMADDR(htl, g_htl); SYMADDR(hch, g_hch); SYMADDR(hcl, g_hcl);
    SYMADDR(qkvh, g_qkvh); SYMADDR(qkvl, g_qkvl); SYMADDR(vth, g_vth); SYMADDR(vtl, g_vtl);
    SYMADDR(attnh, g_attnh); SYMADDR(attnl, g_attnl);
    SYMADDR(hcath, g_hcath); SYMADDR(hcatl, g_hcatl);
    SYMADDR(hfush, g_hfush); SYMADDR(hfusl, g_hfusl);
    SYMADDR(wihh, g_wihh); SYMADDR(wihl, g_wihl);
    SYMADDR(inwh, g_inwh); SYMADDR(inwl, g_inwl);
    SYMADDR(mowh, g_mowh); SYMADDR(mowl, g_mowl);
    SYMADDR(fuwh, g_fuwh); SYMADDR(fuwl, g_fuwl);
    SYMADDR(owh, g_owh); SYMADDR(owl, g_owl);
    SYMADDR(xpadh, g_xpadh); SYMADDR(xpadl, g_xpadl);
    SYMADDR(wpadh, g_wpadh); SYMADDR(wpadl, g_wpadl);

    cudaFuncSetAttribute(k_flash, cudaFuncAttributeMaxDynamicSharedMemorySize, 98304);
    cudaFuncSetAttribute(mma_single, cudaFuncAttributeMaxDynamicSharedMemorySize, 98304);
    cudaFuncSetAttribute(mma_dual, cudaFuncAttributeMaxDynamicSharedMemorySize, 98304);
    const int DYN = 98304;

    float* out_main = (float*)d_out;
    float* out_ht   = out_main + (size_t)NNODE * NOUT;
    float* out_hc   = out_ht   + (size_t)NNODE * HID;

    const int* src_t = ei_t; const int* dst_t = ei_t + NE;
    const int* src_c = ei_c; const int* dst_c = ei_c + NE;
    int nepb = (NEP + 255) / 256, neb = (NE + 255) / 256;

    k_initmean<<<128, 256>>>(ea_t, ea_c);
    k_setup<<<1, 256>>>(We_t, ae_t, We_c, ae_c, lstm_bih, lstm_bhh);
    k_convall<<<(CW6 + 255) / 256, 256>>>(lstm_Wih, mha_in_w, mha_out_w, fus_w, out_w, x, W_t, W_c);

    // count/scan can proceed before xp (only need dst + zeroed cnt)
    k_count<<<dim3(neb, 2), 256>>>(dst_t, dst_c);
    k_scan<<<2, 1024>>>();

    // ---- xp = x @ W for both graphs (tensor cores, batched), a_s/a_d fused in epilogue ----
    {
        GA a0 = { xpadh, xpadl, wpadh, wpadl, xp0, nullptr, nullptr, nullptr,
                  asrc_t, adst_t, as0, ad0,
                  64, 64, NHC, 0, 0, 64, 0, 32, 1.f };
        GA a1 = { xpadh, xpadl, wpadh + (size_t)NHC * 64, wpadl + (size_t)NHC * 64, xp1,
                  nullptr, nullptr, nullptr,
                  asrc_c, adst_c, as1, ad1,
                  64, 64, NHC, 0, 0, 64, 0, 32, 1.f };
        mma_dual<<<dim3(32, 32, 2), 256, DYN>>>(a0, a1);
    }

    // ---- GAT edge pipeline ----
    k_scatalpha<<<dim3(nepb, 2), 256>>>(src_t, dst_t, ea_t, src_c, dst_c, ea_c);
    k_ex<<<dim3(nepb, 2), 256>>>(dst_t, dst_c);
    k_agg<<<dim3(NNODE, 2), 256>>>(src_t, src_c, b_t, b_c);

    // ---- qkv (z=0) + LSTM gates (z=1) in one launch ----
    {
        GA a0 = { hch, hcl, inwh, inwl, nullptr, qkvh, qkvl, mha_in_b,
                  nullptr, nullptr, nullptr, nullptr,
                  256, 256, 0, 768, 0, 256, 0, 12, 1.f };
        GA a1 = { hth, htl, wihh, wihl, big + OFF_G, nullptr, nullptr, big + OFF_BSUM,
                  nullptr, nullptr, nullptr, nullptr,
                  NHC, NHC, 1024, 0, 0, NHC, 0, 16, 1.f };
        mma_dual<<<dim3(16, 32, 2), 256, DYN>>>(a0, a1);
    }
    k_lstmvt<<<2 * NNODE, 256>>>(big + OFF_G, out_ht, qkvh, qkvl, vth, vtl);

    // ---- fused attention, split-KV x2 + merge ----
    k_flash<<<dim3(32, 4, 2), 256, DYN>>>(qkvh, qkvl, vth, vtl, po, pml);
    k_fmerge<<<NNODE, 256>>>(po, pml, attnh, attnl);

    // ---- proj (4096x256x256) ----
    {
        GA a = { attnh, attnl, mowh, mowl, out_hc, hcath, hcatl, mha_out_b,
                 nullptr, nullptr, nullptr, nullptr,
                 256, 256, 256, 512, 256, 256, 0, 4, 1.f };
        mma_single<<<dim3(4, 32), 256, DYN>>>(a);
    }
    // ---- fusion relu (4096x256x512) ----
    {
        GA a = { hcath, hcatl, fuwh, fuwl, nullptr, hfush, hfusl, fus_b,
                 nullptr, nullptr, nullptr, nullptr,
                 512, 512, 0, 256, 0, 512, 1, 4, 1.f };
        mma_single<<<dim3(4, 32), 256, DYN>>>(a);
    }
    // ---- out (4096x128x256) ----
    {
        GA a = { hfush, hfusl, owh, owl, out_main, nullptr, nullptr, out_b,
                 nullptr, nullptr, nullptr, nullptr,
                 256, 256, NOUT, 0, 0, 256, 0, 2, 1.f };
        mma_single<<<dim3(2, 32), 256, DYN>>>(a);
    }
}

// round 10
// speedup vs baseline: 2.4396x; 1.0138x over previous
#include <cuda_runtime.h>
#include <cuda_bf16.h>
#include <math.h>
#include <float.h>
#include <stdint.h>

#define NNODE 4096
#define NIN   28
#define NE    131072
#define NEP   (NE + NNODE)
#define NH    8
#define NC    256
#define NHC   2048
#define HID   256
#define NOUT  128

// ---------------- fp32 scratch ----------------
#define OFF_G    ((size_t)0)
#define OFF_BSUM (OFF_G + (size_t)NNODE * 1024)
#define BIG_SZ   (OFF_BSUM + 1024)
__device__ float g_big[BIG_SZ];

__device__ float g_xp[2][(size_t)NNODE * NHC];
__device__ float g_as[2][NNODE * NH];
__device__ float g_ad[2][NNODE * NH];
__device__ float g_w [2][(size_t)NEP * NH];
__device__ int   g_mx[2][NNODE * NH];
__device__ int   g_cnt[2][NNODE];
__device__ int   g_cur[2][NNODE];
__device__ int   g_start[2][NNODE];
__device__ int   g_sorted[2][NE];
__device__ float g_part[2][128];
__device__ float g_mean[2];
__device__ float g_ce[2][NH];

// flash split-K partials
__device__ float g_po[(size_t)2 * NNODE * 256];
__device__ float g_pml[(size_t)2 * NNODE * 8];

// ---------------- bf16 hi/lo tensors ----------------
__device__ __nv_bfloat16 g_hth[(size_t)NNODE * NHC], g_htl[(size_t)NNODE * NHC];
__device__ __nv_bfloat16 g_hch[(size_t)NNODE * 256], g_hcl[(size_t)NNODE * 256];
__device__ __nv_bfloat16 g_qkvh[(size_t)NNODE * 768], g_qkvl[(size_t)NNODE * 768];
__device__ __nv_bfloat16 g_vth[(size_t)4 * 64 * NNODE], g_vtl[(size_t)4 * 64 * NNODE];
__device__ __nv_bfloat16 g_attnh[(size_t)NNODE * 256], g_attnl[(size_t)NNODE * 256];
__device__ __nv_bfloat16 g_hcath[(size_t)NNODE * 512], g_hcatl[(size_t)NNODE * 512];
__device__ __nv_bfloat16 g_hfush[(size_t)NNODE * 256], g_hfusl[(size_t)NNODE * 256];
// weights
__device__ __nv_bfloat16 g_wihh[1024 * 2048], g_wihl[1024 * 2048];
__device__ __nv_bfloat16 g_inwh[768 * 256],   g_inwl[768 * 256];
__device__ __nv_bfloat16 g_mowh[256 * 256],   g_mowl[256 * 256];
__device__ __nv_bfloat16 g_fuwh[256 * 512],   g_fuwl[256 * 512];
__device__ __nv_bfloat16 g_owh[128 * 256],    g_owl[128 * 256];
// padded x / W for tensor-core xp GEMM (K padded 28 -> 64)
__device__ __nv_bfloat16 g_xpadh[(size_t)NNODE * 64], g_xpadl[(size_t)NNODE * 64];
__device__ __nv_bfloat16 g_wpadh[(size_t)2 * NHC * 64], g_wpadl[(size_t)2 * NHC * 64];

// ---------------- helpers ----------------
__device__ __forceinline__ int   f2ord(float f){ int i = __float_as_int(f); return i >= 0 ? i : i ^ 0x7fffffff; }
__device__ __forceinline__ float ord2f(int k){ return __int_as_float(k >= 0 ? k : k ^ 0x7fffffff); }
__device__ __forceinline__ float sigmf(float x){ return 1.f / (1.f + expf(-x)); }
__device__ __forceinline__ void f2hl(float v, __nv_bfloat16* H, __nv_bfloat16* L, size_t i){
    __nv_bfloat16 h = __float2bfloat16(v);
    H[i] = h; L[i] = __float2bfloat16(v - __bfloat162float(h));
}
__device__ __forceinline__ uint32_t smem_u32(const void* p){
    uint32_t a;
    asm("{ .reg .u64 t; cvta.to.shared.u64 t, %1; cvt.u32.u64 %0, t; }" : "=r"(a) : "l"(p));
    return a;
}
__device__ __forceinline__ void ldm_x4(uint32_t* r, uint32_t addr){
    asm volatile("ldmatrix.sync.aligned.m8n8.x4.shared.b16 {%0,%1,%2,%3}, [%4];"
        : "=r"(r[0]), "=r"(r[1]), "=r"(r[2]), "=r"(r[3]) : "r"(addr));
}
__device__ __forceinline__ void ldm_x2(uint32_t* r, uint32_t addr){
    asm volatile("ldmatrix.sync.aligned.m8n8.x2.shared.b16 {%0,%1}, [%2];"
        : "=r"(r[0]), "=r"(r[1]) : "r"(addr));
}
__device__ __forceinline__ void mma_bf16(float* c, const uint32_t* a, const uint32_t* b){
    asm volatile("mma.sync.aligned.m16n8k16.row.col.f32.bf16.bf16.f32 "
        "{%0,%1,%2,%3}, {%4,%5,%6,%7}, {%8,%9}, {%0,%1,%2,%3};"
        : "+f"(c[0]), "+f"(c[1]), "+f"(c[2]), "+f"(c[3])
        : "r"(a[0]), "r"(a[1]), "r"(a[2]), "r"(a[3]), "r"(b[0]), "r"(b[1]));
}
__device__ __forceinline__ void cpa16(uint32_t saddr, const void* g){
    asm volatile("cp.async.ca.shared.global [%0], [%1], 16;" :: "r"(saddr), "l"(g));
}
__device__ __forceinline__ void cpa_commit(){ asm volatile("cp.async.commit_group;" ::: "memory"); }
__device__ __forceinline__ void splitpack(float a, float b, uint32_t& hi, uint32_t& lo){
    __nv_bfloat16 ha = __float2bfloat16(a), hb = __float2bfloat16(b);
    __nv_bfloat16 la = __float2bfloat16(a - __bfloat162float(ha));
    __nv_bfloat16 lb = __float2bfloat16(b - __bfloat162float(hb));
    hi = ((uint32_t)__bfloat16_as_ushort(hb) << 16) | (uint32_t)__bfloat16_as_ushort(ha);
    lo = ((uint32_t)__bfloat16_as_ushort(lb) << 16) | (uint32_t)__bfloat16_as_ushort(la);
}

// ================= setup =================
__global__ void k_initmean(const float* __restrict__ ea_t, const float* __restrict__ ea_c){
    int idx = blockIdx.x * 256 + threadIdx.x, stride = gridDim.x * 256;
    int mi = f2ord(-FLT_MAX);
    for (int i = idx; i < NNODE * NH; i += stride){
        g_mx[0][i] = mi; g_mx[1][i] = mi;
        g_as[0][i] = 0.f; g_as[1][i] = 0.f;
        g_ad[0][i] = 0.f; g_ad[1][i] = 0.f;
    }
    for (int i = idx; i < NNODE; i += stride){
        g_cnt[0][i] = 0; g_cnt[1][i] = 0;
        g_cur[0][i] = 0; g_cur[1][i] = 0;
    }
    __shared__ float s0[256], s1[256];
    float a = 0.f, b = 0.f;
    for (int i = blockIdx.x * 256 + threadIdx.x; i < NE; i += 128 * 256){ a += ea_t[i]; b += ea_c[i]; }
    s0[threadIdx.x] = a; s1[threadIdx.x] = b; __syncthreads();
    for (int s = 128; s; s >>= 1){
        if (threadIdx.x < s){ s0[threadIdx.x] += s0[threadIdx.x+s]; s1[threadIdx.x] += s1[threadIdx.x+s]; }
        __syncthreads();
    }
    if (!threadIdx.x){ g_part[0][blockIdx.x] = s0[0]; g_part[1][blockIdx.x] = s1[0]; }
}

__global__ void k_setup(const float* __restrict__ We_t, const float* __restrict__ ae_t,
                        const float* __restrict__ We_c, const float* __restrict__ ae_c,
                        const float* __restrict__ bih,  const float* __restrict__ bhh){
    __shared__ float sh[256];
    int tid = threadIdx.x;
    for (int g = 0; g < 2; g++){
        sh[tid] = (tid < 128) ? g_part[g][tid] : 0.f;
        __syncthreads();
        for (int s = 128; s; s >>= 1){ if (tid < s) sh[tid] += sh[tid+s]; __syncthreads(); }
        if (!tid) g_mean[g] = sh[0] / (float)NE;
        __syncthreads();
    }
    int wid = tid >> 5, lane = tid & 31;
    for (int c = wid; c < 16; c += 8){
        int g = c >> 3, h = c & 7;
        const float* We = g ? We_c : We_t;
        const float* ae = g ? ae_c : ae_t;
        float s = 0.f;
        for (int i = lane; i < NC; i += 32) s = fmaf(We[h*NC + i], ae[h*NC + i], s);
        for (int o = 16; o; o >>= 1) s += __shfl_down_sync(0xffffffffu, s, o);
        if (!lane) g_ce[g][h] = s;
    }
    for (int j = tid; j < 1024; j += 256) g_big[OFF_BSUM + j] = bih[j] + bhh[j];
}

#define CW0 2097152
#define CW1 (CW0 + 196608)
#define CW2 (CW1 + 65536)
#define CW3 (CW2 + 131072)
#define CW4 (CW3 + 32768)
#define CW5 (CW4 + NNODE * 64)
#define CW6 (CW5 + 2 * NHC * 64)
__global__ void k_convall(const float* __restrict__ w0, const float* __restrict__ w1,
                          const float* __restrict__ w2, const float* __restrict__ w3,
                          const float* __restrict__ w4, const float* __restrict__ x,
                          const float* __restrict__ W_t, const float* __restrict__ W_c){
    int i = blockIdx.x * 256 + threadIdx.x;
    if (i < CW0)      f2hl(w0[i], g_wihh, g_wihl, i);
    else if (i < CW1) f2hl(w1[i - CW0], g_inwh, g_inwl, i - CW0);
    else if (i < CW2) f2hl(w2[i - CW1], g_mowh, g_mowl, i - CW1);
    else if (i < CW3) f2hl(w3[i - CW2], g_fuwh, g_fuwl, i - CW2);
    else if (i < CW4) f2hl(w4[i - CW3], g_owh, g_owl, i - CW3);
    else if (i < CW5){
        int j = i - CW4; int n = j >> 6, k = j & 63;
        float v = (k < NIN) ? x[n * NIN + k] : 0.f;
        f2hl(v, g_xpadh, g_xpadl, j);
    } else if (i < CW6){
        int j = i - CW5; int g = j >> 17; int r = j & 131071;
        int n = r >> 6, k = r & 63;
        const float* W = g ? W_c : W_t;
        float v = (k < NIN) ? W[k * NHC + n] : 0.f;
        f2hl(v, g_wpadh, g_wpadl, j);
    }
}

// ================= GAT edge pipeline =================
__global__ void k_count(const int* __restrict__ dst_t, const int* __restrict__ dst_c){
    int g = blockIdx.y;
    const int* dst = g ? dst_c : dst_t;
    int e = blockIdx.x * 256 + threadIdx.x;
    if (e < NE) atomicAdd(&g_cnt[g][dst[e]], 1);
}

__global__ void k_scan(){
    int g = blockIdx.x, tid = threadIdx.x;
    __shared__ int sh[1024];
    int base = tid * 4;
    int c0 = g_cnt[g][base], c1 = g_cnt[g][base+1], c2 = g_cnt[g][base+2], c3 = g_cnt[g][base+3];
    int s = c0 + c1 + c2 + c3;
    sh[tid] = s; __syncthreads();
    for (int off = 1; off < 1024; off <<= 1){
        int v = (tid >= off) ? sh[tid - off] : 0;
        __syncthreads();
        sh[tid] += v;
        __syncthreads();
    }
    int excl = sh[tid] - s;
    g_start[g][base]   = excl;
    g_start[g][base+1] = excl + c0;
    g_start[g][base+2] = excl + c0 + c1;
    g_start[g][base+3] = excl + c0 + c1 + c2;
}

// fused: scatter (counting-sort placement) + alpha (attention logits + seg-max)
__global__ void k_scatalpha(const int* __restrict__ src_t, const int* __restrict__ dst_t, const float* __restrict__ ea_t,
                            const int* __restrict__ src_c, const int* __restrict__ dst_c, const float* __restrict__ ea_c){
    int g = blockIdx.y;
    const int* src = g ? src_c : src_t;
    const int* dst = g ? dst_c : dst_t;
    const float* ea = g ? ea_c : ea_t;
    int e = blockIdx.x * 256 + threadIdx.x;
    if (e >= NEP) return;
    int s, d; float av;
    if (e < NE){
        s = src[e]; d = dst[e]; av = ea[e];
        int pos = g_start[g][d] + atomicAdd(&g_cur[g][d], 1);
        g_sorted[g][pos] = e;
    } else { s = d = e - NE; av = g_mean[g]; }
#pragma unroll
    for (int h = 0; h < NH; h++){
        float al = g_as[g][s*NH + h] + g_ad[g][d*NH + h] + av * g_ce[g][h];
        al = al > 0.f ? al : 0.2f * al;
        g_w[g][(size_t)e * NH + h] = al;
        atomicMax(&g_mx[g][d*NH + h], f2ord(al));
    }
}

// fused: exp + denominator + weighted aggregation (per-destination CTA)
__global__ void __launch_bounds__(256) k_agg(const int* __restrict__ src_t, const int* __restrict__ src_c,
                                             const float* __restrict__ b_t, const float* __restrict__ b_c){
    int g = blockIdx.y;
    const int* src = g ? src_c : src_t;
    const float* bias = g ? b_c : b_t;
    int n = blockIdx.x, t = threadIdx.x;
    const float* xp = g_xp[g];
    const float* w  = g_w[g];

    __shared__ float smx[NH];
    __shared__ int   ssrc[32];
    __shared__ float sw[32][NH];
    if (t < NH) smx[t] = ord2f(g_mx[g][n*NH + t]);
    __syncthreads();

    float acc[NH], den[NH];
    {   // self loop
        size_t e = (size_t)(NE + n) * NH;
        const float* xr = xp + (size_t)n * NHC + t;
#pragma unroll
        for (int h = 0; h < NH; h++){
            float exs = expf(w[e + h] - smx[h]);
            acc[h] = exs * xr[h * NC];
            den[h] = exs;
        }
    }
    int st = g_start[g][n], c = g_cnt[g][n];
    for (int i0 = 0; i0 < c; i0 += 32){
        int m = min(32, c - i0);
        __syncthreads();
        if (t < m) ssrc[t] = src[g_sorted[g][st + i0 + t]];
        {
            int j = t >> 3, h = t & 7;
            if (j < m) sw[j][h] = expf(w[(size_t)g_sorted[g][st + i0 + j] * NH + h] - smx[h]);
        }
        __syncthreads();
        int jj = 0;
        for (; jj + 4 <= m; jj += 4){
            const float* x0 = xp + (size_t)ssrc[jj+0] * NHC + t;
            const float* x1 = xp + (size_t)ssrc[jj+1] * NHC + t;
            const float* x2 = xp + (size_t)ssrc[jj+2] * NHC + t;
            const float* x3 = xp + (size_t)ssrc[jj+3] * NHC + t;
            float v0[NH], v1[NH], v2[NH], v3[NH];
#pragma unroll
            for (int h = 0; h < NH; h++){ v0[h] = x0[h*NC]; v1[h] = x1[h*NC]; v2[h] = x2[h*NC]; v3[h] = x3[h*NC]; }
#pragma unroll
            for (int h = 0; h < NH; h++){
                float w0 = sw[jj+0][h], w1 = sw[jj+1][h], w2 = sw[jj+2][h], w3 = sw[jj+3][h];
                acc[h] = fmaf(w0, v0[h], acc[h]);
                acc[h] = fmaf(w1, v1[h], acc[h]);
                acc[h] = fmaf(w2, v2[h], acc[h]);
                acc[h] = fmaf(w3, v3[h], acc[h]);
                den[h] += (w0 + w1) + (w2 + w3);
            }
        }
        for (; jj < m; jj++){
            const float* xr = xp + (size_t)ssrc[jj] * NHC + t;
#pragma unroll
            for (int h = 0; h < NH; h++){
                float ww = sw[jj][h];
                acc[h] = fmaf(ww, xr[h * NC], acc[h]);
                den[h] += ww;
            }
        }
    }
    if (g == 0){
#pragma unroll
        for (int h = 0; h < NH; h++){
            float v = acc[h] / (den[h] + 1e-16f) + bias[h * NC + t];
            f2hl(v, g_hth, g_htl, (size_t)n * NHC + h * NC + t);
        }
    } else {
        float s = 0.f;
#pragma unroll
        for (int h = 0; h < NH; h++) s += acc[h] / (den[h] + 1e-16f);
        f2hl(s * 0.125f + bias[t], g_hch, g_hcl, (size_t)n * NC + t);
    }
}

// ================= HMMA bf16x3 GEMM core (cp.async 2-stage pipelined) =================
struct GA {
    const __nv_bfloat16 *Ah, *Al, *Bh, *Bl;
    float* C;
    __nv_bfloat16 *Ch, *Cl;
    const float* bias;
    const float *pas, *pad;    // optional: fused a_src/a_dst dot (xp GEMM)
    float *oas, *oad;
    int lda, ldb, ldc, ldc2, c2off, K, act, gx;
    float alpha;
};

__device__ __forceinline__ void gemm_core(const GA a){
    extern __shared__ char sm[];
    int tid = threadIdx.x, lane = tid & 31, wid = tid >> 5;
    int wm = wid & 3, wn = wid >> 2;
    int row0 = blockIdx.y * 128, col0 = blockIdx.x * 64;
    const __nv_bfloat16* Ah = a.Ah + (size_t)row0 * a.lda;
    const __nv_bfloat16* Al = a.Al + (size_t)row0 * a.lda;
    const __nv_bfloat16* Bh = a.Bh + (size_t)col0 * a.ldb;
    const __nv_bfloat16* Bl = a.Bl + (size_t)col0 * a.ldb;

    uint32_t sbase = smem_u32(sm);
    int nkb = a.K >> 6;

    auto issue = [&](int kb, int st){
        uint32_t su = sbase + st * 49152;
        int k0 = kb << 6;
#pragma unroll
        for (int it = 0; it < 4; it++){
            int i = tid + it * 256;
            int row = i >> 3, seg = i & 7;
            size_t goff = (size_t)row * a.lda + k0 + seg * 8;
            uint32_t so = row * 128 + ((seg ^ (row & 7)) << 4);
            cpa16(su + so,         Ah + goff);
            cpa16(su + 16384 + so, Al + goff);
        }
#pragma unroll
        for (int it = 0; it < 2; it++){
            int i = tid + it * 256;
            int row = i >> 3, seg = i & 7;
            size_t goff = (size_t)row * a.ldb + k0 + seg * 8;
            uint32_t so = row * 128 + ((seg ^ (row & 7)) << 4);
            cpa16(su + 32768 + so, Bh + goff);
            cpa16(su + 40960 + so, Bl + goff);
        }
        cpa_commit();
    };

    issue(0, 0);
    if (nkb > 1) issue(1, 1);

    float acc[2][4][4] = {};
    for (int kb = 0; kb < nkb; kb++){
        if (kb + 1 < nkb) asm volatile("cp.async.wait_group 1;" ::: "memory");
        else              asm volatile("cp.async.wait_group 0;" ::: "memory");
        __syncthreads();
        uint32_t sb2 = sbase + (kb & 1) * 49152;
#pragma unroll
        for (int ks = 0; ks < 4; ks++){
            uint32_t a_h[2][4], a_l[2][4], b_h[4][2], b_l[4][2];
#pragma unroll
            for (int mt = 0; mt < 2; mt++){
                int r = wm * 32 + mt * 16 + (lane & 15);
                int seg = ks * 2 + (lane >> 4);
                uint32_t ad = sb2 + r * 128 + ((seg ^ (r & 7)) << 4);
                ldm_x4(a_h[mt], ad);
                ldm_x4(a_l[mt], ad + 16384);
            }
#pragma unroll
            for (int nt = 0; nt < 4; nt++){
                int r = wn * 32 + nt * 8 + (lane & 7);
                int seg = ks * 2 + ((lane >> 3) & 1);
                uint32_t bd = sb2 + 32768 + r * 128 + ((seg ^ (r & 7)) << 4);
                ldm_x2(b_h[nt], bd);
                ldm_x2(b_l[nt], bd + 8192);
            }
#pragma unroll
            for (int mt = 0; mt < 2; mt++)
#pragma unroll
                for (int nt = 0; nt < 4; nt++){
                    mma_bf16(acc[mt][nt], a_h[mt], b_h[nt]);
                    mma_bf16(acc[mt][nt], a_h[mt], b_l[nt]);
                    mma_bf16(acc[mt][nt], a_l[mt], b_h[nt]);
                }
        }
        __syncthreads();
        if (kb + 2 < nkb) issue(kb + 2, kb & 1);
    }

    float s1[4] = {}, s2[4] = {};
    int h = col0 >> 8;
#pragma unroll
    for (int mt = 0; mt < 2; mt++){
#pragma unroll
        for (int nt = 0; nt < 4; nt++){
            int r0 = row0 + wm * 32 + mt * 16 + (lane >> 2);
            int c0 = col0 + wn * 32 + nt * 8 + ((lane & 3) << 1);
#pragma unroll
            for (int q = 0; q < 4; q++){
                int r = r0 + (q >> 1) * 8;
                int cc = c0 + (q & 1);
                float v = acc[mt][nt][q] * a.alpha;
                if (a.bias) v += a.bias[cc];
                if (a.act == 1) v = fmaxf(v, 0.f);
                if (a.C) a.C[(size_t)r * a.ldc + cc] = v;
                if (a.Ch) f2hl(v, a.Ch, a.Cl, (size_t)r * a.ldc2 + a.c2off + cc);
                if (a.pas){
                    int ridx = mt * 2 + (q >> 1);
                    int ci = h * 256 + (cc & 255);
                    s1[ridx] = fmaf(v, a.pas[ci], s1[ridx]);
                    s2[ridx] = fmaf(v, a.pad[ci], s2[ridx]);
                }
            }
        }
    }
    if (a.pas){
#pragma unroll
        for (int i = 0; i < 4; i++){
            s1[i] += __shfl_xor_sync(~0u, s1[i], 1); s1[i] += __shfl_xor_sync(~0u, s1[i], 2);
            s2[i] += __shfl_xor_sync(~0u, s2[i], 1); s2[i] += __shfl_xor_sync(~0u, s2[i], 2);
        }
        if ((lane & 3) == 0){
#pragma unroll
            for (int i = 0; i < 4; i++){
                int mt = i >> 1, rr = i & 1;
                int r = row0 + wm * 32 + mt * 16 + (lane >> 2) + rr * 8;
                atomicAdd(&a.oas[r * NH + h], s1[i]);
                atomicAdd(&a.oad[r * NH + h], s2[i]);
            }
        }
    }
}

__global__ void __launch_bounds__(256) mma_single(GA a){
    if ((int)blockIdx.x >= a.gx) return;
    gemm_core(a);
}
__global__ void __launch_bounds__(256) mma_dual(GA a0, GA a1){
    GA a = blockIdx.z ? a1 : a0;
    if ((int)blockIdx.x >= a.gx) return;
    gemm_core(a);
}

// ================= flash attention (split-KV, 2 partials) =================
__global__ void __launch_bounds__(256) k_flash(
    const __nv_bfloat16* __restrict__ qkvh, const __nv_bfloat16* __restrict__ qkvl,
    const __nv_bfloat16* __restrict__ vth, const __nv_bfloat16* __restrict__ vtl,
    float* __restrict__ pO, float* __restrict__ pML)
{
    extern __shared__ char sm[];
    int tid = threadIdx.x, lane = tid & 31, wid = tid >> 5;
    int head = blockIdx.y;
    int row0 = blockIdx.x * 128;
    int z = blockIdx.z;
    int kv0 = z * 2048;
    uint32_t sb = smem_u32(sm);

    const __nv_bfloat16* Qh = qkvh + (size_t)row0 * 768 + head * 64;
    const __nv_bfloat16* Ql = qkvl + (size_t)row0 * 768 + head * 64;
    const __nv_bfloat16* Kh = qkvh + 256 + head * 64;
    const __nv_bfloat16* Kl = qkvl + 256 + head * 64;
    const __nv_bfloat16* Vh = vth + (size_t)head * 64 * 4096;
    const __nv_bfloat16* Vl = vtl + (size_t)head * 64 * 4096;

#pragma unroll
    for (int it = 0; it < 4; it++){
        int i = tid + it * 256;
        int r = i >> 3, seg = i & 7;
        uint32_t so = r * 128 + ((seg ^ (r & 7)) << 4);
        cpa16(sb + so,         Qh + (size_t)r * 768 + seg * 8);
        cpa16(sb + 16384 + so, Ql + (size_t)r * 768 + seg * 8);
    }
#pragma unroll
    for (int it = 0; it < 2; it++){
        int i = tid + it * 256;
        int r = i >> 3, seg = i & 7;
        uint32_t so = r * 128 + ((seg ^ (r & 7)) << 4);
        cpa16(sb + 32768 + so,         Kh + (size_t)(kv0 + r) * 768 + seg * 8);
        cpa16(sb + 32768 + 8192 + so,  Kl + (size_t)(kv0 + r) * 768 + seg * 8);
        cpa16(sb + 32768 + 16384 + so, Vh + (size_t)r * 4096 + kv0 + seg * 8);
        cpa16(sb + 32768 + 24576 + so, Vl + (size_t)r * 4096 + kv0 + seg * 8);
    }
    cpa_commit();
    asm volatile("cp.async.wait_group 0;" ::: "memory");
    __syncthreads();

    uint32_t qf_h[4][4], qf_l[4][4];
#pragma unroll
    for (int ks = 0; ks < 4; ks++){
        int r = wid * 16 + (lane & 15);
        int seg = ks * 2 + (lane >> 4);
        uint32_t ad = sb + r * 128 + ((seg ^ (r & 7)) << 4);
        ldm_x4(qf_h[ks], ad);
        ldm_x4(qf_l[ks], ad + 16384);
    }

    float m0 = -1e30f, m1 = -1e30f, l0 = 0.f, l1 = 0.f;
    float acc_o[8][4] = {};
    int buf = 0;

    for (int kt = 0; kt < 32; kt++){
        if (kt < 31){
            uint32_t bo = sb + 32768 + (buf ^ 1) * 32768;
            int key0 = kv0 + (kt + 1) * 64;
#pragma unroll
            for (int it = 0; it < 2; it++){
                int i = tid + it * 256;
                int r = i >> 3, seg = i & 7;
                uint32_t so = r * 128 + ((seg ^ (r & 7)) << 4);
                cpa16(bo + so,         Kh + (size_t)(key0 + r) * 768 + seg * 8);
                cpa16(bo + 8192 + so,  Kl + (size_t)(key0 + r) * 768 + seg * 8);
                cpa16(bo + 16384 + so, Vh + (size_t)r * 4096 + key0 + seg * 8);
                cpa16(bo + 24576 + so, Vl + (size_t)r * 4096 + key0 + seg * 8);
            }
            cpa_commit();
            asm volatile("cp.async.wait_group 1;" ::: "memory");
        } else {
            asm volatile("cp.async.wait_group 0;" ::: "memory");
        }
        __syncthreads();

        uint32_t kb = sb + 32768 + buf * 32768;

        float acc_s[8][4] = {};
#pragma unroll
        for (int ks = 0; ks < 4; ks++){
            uint32_t bh[8][2], bl[8][2];
#pragma unroll
            for (int nt = 0; nt < 8; nt++){
                int r = nt * 8 + (lane & 7);
                int seg = ks * 2 + ((lane >> 3) & 1);
                uint32_t bd = kb + r * 128 + ((seg ^ (r & 7)) << 4);
                ldm_x2(bh[nt], bd);
                ldm_x2(bl[nt], bd + 8192);
            }
#pragma unroll
            for (int nt = 0; nt < 8; nt++){
                mma_bf16(acc_s[nt], qf_h[ks], bh[nt]);
                mma_bf16(acc_s[nt], qf_h[ks], bl[nt]);
                mma_bf16(acc_s[nt], qf_l[ks], bh[nt]);
            }
        }
#pragma unroll
        for (int nt = 0; nt < 8; nt++){
            acc_s[nt][0] *= 0.125f; acc_s[nt][1] *= 0.125f;
            acc_s[nt][2] *= 0.125f; acc_s[nt][3] *= 0.125f;
        }

        float tm0 = -1e30f, tm1 = -1e30f;
#pragma unroll
        for (int nt = 0; nt < 8; nt++){
            tm0 = fmaxf(tm0, fmaxf(acc_s[nt][0], acc_s[nt][1]));
            tm1 = fmaxf(tm1, fmaxf(acc_s[nt][2], acc_s[nt][3]));
        }
        tm0 = fmaxf(tm0, __shfl_xor_sync(~0u, tm0, 1)); tm0 = fmaxf(tm0, __shfl_xor_sync(~0u, tm0, 2));
        tm1 = fmaxf(tm1, __shfl_xor_sync(~0u, tm1, 1)); tm1 = fmaxf(tm1, __shfl_xor_sync(~0u, tm1, 2));
        float mn0 = fmaxf(m0, tm0), mn1 = fmaxf(m1, tm1);
        float sc0 = __expf(m0 - mn0), sc1 = __expf(m1 - mn1);
        m0 = mn0; m1 = mn1;
        l0 *= sc0; l1 *= sc1;
#pragma unroll
        for (int nt = 0; nt < 8; nt++){
            acc_o[nt][0] *= sc0; acc_o[nt][1] *= sc0;
            acc_o[nt][2] *= sc1; acc_o[nt][3] *= sc1;
        }
        float rs0 = 0.f, rs1 = 0.f;
        uint32_t pa_h[4][4], pa_l[4][4];
#pragma unroll
        for (int nt = 0; nt < 8; nt++){
            float p0 = __expf(acc_s[nt][0] - mn0), p1 = __expf(acc_s[nt][1] - mn0);
            float p2 = __expf(acc_s[nt][2] - mn1), p3 = __expf(acc_s[nt][3] - mn1);
            rs0 += p0 + p1; rs1 += p2 + p3;
            int k2 = nt >> 1;
            if (!(nt & 1)){
                splitpack(p0, p1, pa_h[k2][0], pa_l[k2][0]);
                splitpack(p2, p3, pa_h[k2][1], pa_l[k2][1]);
            } else {
                splitpack(p0, p1, pa_h[k2][2], pa_l[k2][2]);
                splitpack(p2, p3, pa_h[k2][3], pa_l[k2][3]);
            }
        }
        rs0 += __shfl_xor_sync(~0u, rs0, 1); rs0 += __shfl_xor_sync(~0u, rs0, 2);
        rs1 += __shfl_xor_sync(~0u, rs1, 1); rs1 += __shfl_xor_sync(~0u, rs1, 2);
        l0 += rs0; l1 += rs1;

        uint32_t vb = kb + 16384;
#pragma unroll
        for (int k2 = 0; k2 < 4; k2++){
            uint32_t vh[8][2], vl[8][2];
#pragma unroll
            for (int nt = 0; nt < 8; nt++){
                int r = nt * 8 + (lane & 7);
                int seg = k2 * 2 + ((lane >> 3) & 1);
                uint32_t vd = vb + r * 128 + ((seg ^ (r & 7)) << 4);
                ldm_x2(vh[nt], vd);
                ldm_x2(vl[nt], vd + 8192);
            }
#pragma unroll
            for (int nt = 0; nt < 8; nt++){
                mma_bf16(acc_o[nt], pa_h[k2], vh[nt]);
                mma_bf16(acc_o[nt], pa_h[k2], vl[nt]);
                mma_bf16(acc_o[nt], pa_l[k2], vh[nt]);
            }
        }
        __syncthreads();
        buf ^= 1;
    }

    int r = row0 + wid * 16 + (lane >> 2);
    size_t ro0 = ((size_t)z * NNODE + r) * 256;
    size_t ro1 = ((size_t)z * NNODE + r + 8) * 256;
#pragma unroll
    for (int nt = 0; nt < 8; nt++){
        int cc = head * 64 + nt * 8 + ((lane & 3) << 1);
        pO[ro0 + cc]     = acc_o[nt][0];
        pO[ro0 + cc + 1] = acc_o[nt][1];
        pO[ro1 + cc]     = acc_o[nt][2];
        pO[ro1 + cc + 1] = acc_o[nt][3];
    }
    if ((lane & 3) == 0){
        pML[((size_t)z * NNODE + r) * 8 + head * 2]     = m0;
        pML[((size_t)z * NNODE + r) * 8 + head * 2 + 1] = l0;
        pML[((size_t)z * NNODE + r + 8) * 8 + head * 2]     = m1;
        pML[((size_t)z * NNODE + r + 8) * 8 + head * 2 + 1] = l1;
    }
}

__global__ void k_fmerge(const float* __restrict__ pO, const float* __restrict__ pML,
                         __nv_bfloat16* __restrict__ Oh, __nv_bfloat16* __restrict__ Ol){
    int row = blockIdx.x, col = threadIdx.x;
    int head = col >> 6;
    float m0 = pML[(size_t)row * 8 + head * 2],            l0 = pML[(size_t)row * 8 + head * 2 + 1];
    float m1 = pML[((size_t)NNODE + row) * 8 + head * 2],  l1 = pML[((size_t)NNODE + row) * 8 + head * 2 + 1];
    float mx = fmaxf(m0, m1);
    float w0 = __expf(m0 - mx), w1 = __expf(m1 - mx);
    float num = pO[(size_t)row * 256 + col] * w0 + pO[((size_t)NNODE + row) * 256 + col] * w1;
    float den = l0 * w0 + l1 * w1;
    f2hl(num / den, Oh, Ol, (size_t)row * 256 + col);
}

// ================= pointwise (lstm + vt fused) =================
__global__ void k_lstmvt(const float* __restrict__ G, float* __restrict__ ht_out,
                         const __nv_bfloat16* __restrict__ qh, const __nv_bfloat16* __restrict__ ql,
                         __nv_bfloat16* __restrict__ vh, __nv_bfloat16* __restrict__ vl){
    int b = blockIdx.x;
    if (b < NNODE){
        int idx = b * 256 + threadIdx.x;
        int n = idx >> 8, j = idx & 255;
        const float* gr = G + (size_t)n * 1024;
        float ig = gr[j], gg = gr[512 + j], og = gr[768 + j];
        float cc = sigmf(ig) * tanhf(gg);
        float hv = sigmf(og) * tanhf(cc);
        ht_out[idx] = hv;
        f2hl(hv, g_hcath, g_hcatl, (size_t)n * 512 + j);
    } else {
        int idx = (b - NNODE) * 256 + threadIdx.x;
        int hd = idx >> 12, n = idx & 4095;
        size_t s = (size_t)n * 768 + 512 + hd;
        vh[idx] = qh[s]; vl[idx] = ql[s];
    }
}

// ================= launch =================
#define SYMADDR(p, s) do { void* _t; cudaGetSymbolAddress(&_t, s); p = (decltype(p))_t; } while(0)

extern "C" void kernel_launch(void* const* d_in, const int* in_sizes, int n_in,
                              void* d_out, int out_size) {
    const float* x     = (const float*)d_in[0];
    const int*   ei_t  = (const int*)d_in[1];
    const int*   ei_c  = (const int*)d_in[2];
    const float* ea_t  = (const float*)d_in[3];
    const float* ea_c  = (const float*)d_in[4];
    const float* W_t   = (const float*)d_in[5];
    const float* asrc_t= (const float*)d_in[6];
    const float* adst_t= (const float*)d_in[7];
    const float* We_t  = (const float*)d_in[8];
    const float* ae_t  = (const float*)d_in[9];
    const float* b_t   = (const float*)d_in[10];
    const float* W_c   = (const float*)d_in[11];
    const float* asrc_c= (const float*)d_in[12];
    const float* adst_c= (const float*)d_in[13];
    const float* We_c  = (const float*)d_in[14];
    const float* ae_c  = (const float*)d_in[15];
    const float* b_c   = (const float*)d_in[16];
    const float* lstm_Wih = (const float*)d_in[17];
    const float* lstm_bih = (const float*)d_in[19];
    const float* lstm_bhh = (const float*)d_in[20];
    const float* mha_in_w  = (const float*)d_in[21];
    const float* mha_in_b  = (const float*)d_in[22];
    const float* mha_out_w = (const float*)d_in[23];
    const float* mha_out_b = (const float*)d_in[24];
    const float* fus_w = (const float*)d_in[25];
    const float* fus_b = (const float*)d_in[26];
    const float* out_w = (const float*)d_in[27];
    const float* out_b = (const float*)d_in[28];

    float* big; SYMADDR(big, g_big);
    float* po;  SYMADDR(po, g_po);
    float* pml; SYMADDR(pml, g_pml);
    float* xp0; SYMADDR(xp0, g_xp);
    float* xp1 = xp0 + (size_t)NNODE * NHC;
    float* as0; SYMADDR(as0, g_as);
    float* as1 = as0 + NNODE * NH;
    float* ad0; SYMADDR(ad0, g_ad);
    float* ad1 = ad0 + NNODE * NH;
    __nv_bfloat16 *hth, *htl, *hch, *hcl, *qkvh, *qkvl, *vth, *vtl;
    __nv_bfloat16 *attnh, *attnl, *hcath, *hcatl, *hfush, *hfusl;
    __nv_bfloat16 *wihh, *wihl, *inwh, *inwl, *mowh, *mowl, *fuwh, *fuwl, *owh, *owl;
    __nv_bfloat16 *xpadh, *xpadl, *wpadh, *wpadl;
    SYMADDR(hth, g_hth); SYMADDR(htl, g_htl); SYMADDR(hch, g_hch); SYMADDR(hcl, g_hcl);
    SYMADDR(qkvh, g_qkvh); SYMADDR(qkvl, g_qkvl); SYMADDR(vth, g_vth); SYMADDR(vtl, g_vtl);
    SYMADDR(attnh, g_attnh); SYMADDR(attnl, g_attnl);
    SYMADDR(hcath, g_hcath); SYMADDR(hcatl, g_hcatl);
    SYMADDR(hfush, g_hfush); SYMADDR(hfusl, g_hfusl);
    SYMADDR(wihh, g_wihh); SYMADDR(wihl, g_wihl);
    SYMADDR(inwh, g_inwh); SYMADDR(inwl, g_inwl);
    SYMADDR(mowh, g_mowh); SYMADDR(mowl, g_mowl);
    SYMADDR(fuwh, g_fuwh); SYMADDR(fuwl, g_fuwl);
    SYMADDR(owh, g_owh); SYMADDR(owl, g_owl);
    SYMADDR(xpadh, g_xpadh); SYMADDR(xpadl, g_xpadl);
    SYMADDR(wpadh, g_wpadh); SYMADDR(wpadl, g_wpadl);

    cudaFuncSetAttribute(k_flash, cudaFuncAttributeMaxDynamicSharedMemorySize, 98304);
    cudaFuncSetAttribute(mma_single, cudaFuncAttributeMaxDynamicSharedMemorySize, 98304);
    cudaFuncSetAttribute(mma_dual, cudaFuncAttributeMaxDynamicSharedMemorySize, 98304);
    const int DYN = 98304;

    float* out_main = (float*)d_out;
    float* out_ht   = out_main + (size_t)NNODE * NOUT;
    float* out_hc   = out_ht   + (size_t)NNODE * HID;

    const int* src_t = ei_t; const int* dst_t = ei_t + NE;
    const int* src_c = ei_c; const int* dst_c = ei_c + NE;
    int nepb = (NEP + 255) / 256, neb = (NE + 255) / 256;

    k_initmean<<<128, 256>>>(ea_t, ea_c);
    k_setup<<<1, 256>>>(We_t, ae_t, We_c, ae_c, lstm_bih, lstm_bhh);
    k_convall<<<(CW6 + 255) / 256, 256>>>(lstm_Wih, mha_in_w, mha_out_w, fus_w, out_w, x, W_t, W_c);

    // count/scan before xp (only need dst + zeroed cnt)
    k_count<<<dim3(neb, 2), 256>>>(dst_t, dst_c);
    k_scan<<<2, 1024>>>();

    // ---- xp = x @ W for both graphs (tensor cores, batched), a_s/a_d fused in epilogue ----
    {
        GA a0 = { xpadh, xpadl, wpadh, wpadl, xp0, nullptr, nullptr, nullptr,
                  asrc_t, adst_t, as0, ad0,
                  64, 64, NHC, 0, 0, 64, 0, 32, 1.f };
        GA a1 = { xpadh, xpadl, wpadh + (size_t)NHC * 64, wpadl + (size_t)NHC * 64, xp1,
                  nullptr, nullptr, nullptr,
                  asrc_c, adst_c, as1, ad1,
                  64, 64, NHC, 0, 0, 64, 0, 32, 1.f };
        mma_dual<<<dim3(32, 32, 2), 256, DYN>>>(a0, a1);
    }

    // ---- GAT edge pipeline (ex/den now fused into k_agg) ----
    k_scatalpha<<<dim3(nepb, 2), 256>>>(src_t, dst_t, ea_t, src_c, dst_c, ea_c);
    k_agg<<<dim3(NNODE, 2), 256>>>(src_t, src_c, b_t, b_c);

    // ---- qkv (z=0) + LSTM gates (z=1) in one launch ----
    {
        GA a0 = { hch, hcl, inwh, inwl, nullptr, qkvh, qkvl, mha_in_b,
                  nullptr, nullptr, nullptr, nullptr,
                  256, 256, 0, 768, 0, 256, 0, 12, 1.f };
        GA a1 = { hth, htl, wihh, wihl, big + OFF_G, nullptr, nullptr, big + OFF_BSUM,
                  nullptr, nullptr, nullptr, nullptr,
                  NHC, NHC, 1024, 0, 0, NHC, 0, 16, 1.f };
        mma_dual<<<dim3(16, 32, 2), 256, DYN>>>(a0, a1);
    }
    k_lstmvt<<<2 * NNODE, 256>>>(big + OFF_G, out_ht, qkvh, qkvl, vth, vtl);

    // ---- fused attention, split-KV x2 + merge ----
    k_flash<<<dim3(32, 4, 2), 256, DYN>>>(qkvh, qkvl, vth, vtl, po, pml);
    k_fmerge<<<NNODE, 256>>>(po, pml, attnh, attnl);

    // ---- proj (4096x256x256) ----
    {
        GA a = { attnh, attnl, mowh, mowl, out_hc, hcath, hcatl, mha_out_b,
                 nullptr, nullptr, nullptr, nullptr,
                 256, 256, 256, 512, 256, 256, 0, 4, 1.f };
        mma_single<<<dim3(4, 32), 256, DYN>>>(a);
    }
    // ---- fusion relu (4096x256x512) ----
    {
        GA a = { hcath, hcatl, fuwh, fuwl, nullptr, hfush, hfusl, fus_b,
                 nullptr, nullptr, nullptr, nullptr,
                 512, 512, 0, 256, 0, 512, 1, 4, 1.f };
        mma_single<<<dim3(4, 32), 256, DYN>>>(a);
    }
    // ---- out (4096x128x256) ----
    {
        GA a = { hfush, hfusl, owh, owl, out_main, nullptr, nullptr, out_b,
                 nullptr, nullptr, nullptr, nullptr,
                 256, 256, NOUT, 0, 0, 256, 0, 2, 1.f };
        mma_single<<<dim3(2, 32), 256, DYN>>>(a);
    }
}

// round 11
// speedup vs baseline: 2.5076x; 1.0278x over previous
#include <cuda_runtime.h>
#include <cuda_bf16.h>
#include <math.h>
#include <float.h>
#include <stdint.h>

#define NNODE 4096
#define NIN   28
#define NE    131072
#define NEP   (NE + NNODE)
#define NH    8
#define NC    256
#define NHC   2048
#define HID   256
#define NOUT  128

// ---------------- fp32 scratch ----------------
#define OFF_G    ((size_t)0)
#define OFF_BSUM (OFF_G + (size_t)NNODE * 1024)
#define BIG_SZ   (OFF_BSUM + 1024)
__device__ float g_big[BIG_SZ];

__device__ float g_xp[2][(size_t)NNODE * NHC];
__device__ float g_as[2][NNODE * NH];
__device__ float g_ad[2][NNODE * NH];
__device__ float g_w [2][(size_t)NEP * NH];
__device__ int   g_mx[2][NNODE * NH];
__device__ int   g_cnt[2][NNODE];
__device__ int   g_cur[2][NNODE];
__device__ int   g_start[2][NNODE];
__device__ int   g_sorted[2][NE];
__device__ float g_part[2][128];
__device__ float g_mean[2];
__device__ float g_ce[2][NH];

// flash split-K partials
__device__ float g_po[(size_t)2 * NNODE * 256];
__device__ float g_pml[(size_t)2 * NNODE * 8];

// ---------------- bf16 hi/lo tensors ----------------
__device__ __nv_bfloat16 g_hth[(size_t)NNODE * NHC], g_htl[(size_t)NNODE * NHC];
__device__ __nv_bfloat16 g_hch[(size_t)NNODE * 256], g_hcl[(size_t)NNODE * 256];
__device__ __nv_bfloat16 g_qkvh[(size_t)NNODE * 768], g_qkvl[(size_t)NNODE * 768];
__device__ __nv_bfloat16 g_vth[(size_t)4 * 64 * NNODE], g_vtl[(size_t)4 * 64 * NNODE];
__device__ __nv_bfloat16 g_attnh[(size_t)NNODE * 256], g_attnl[(size_t)NNODE * 256];
__device__ __nv_bfloat16 g_hcath[(size_t)NNODE * 512], g_hcatl[(size_t)NNODE * 512];
__device__ __nv_bfloat16 g_hfush[(size_t)NNODE * 256], g_hfusl[(size_t)NNODE * 256];
// weights
__device__ __nv_bfloat16 g_wihh[1024 * 2048], g_wihl[1024 * 2048];
__device__ __nv_bfloat16 g_inwh[768 * 256],   g_inwl[768 * 256];
__device__ __nv_bfloat16 g_mowh[256 * 256],   g_mowl[256 * 256];
__device__ __nv_bfloat16 g_fuwh[256 * 512],   g_fuwl[256 * 512];
__device__ __nv_bfloat16 g_owh[128 * 256],    g_owl[128 * 256];
// padded x / W for tensor-core xp GEMM
__device__ __nv_bfloat16 g_xpadh[(size_t)NNODE * 64], g_xpadl[(size_t)NNODE * 64];
__device__ __nv_bfloat16 g_wpadh[(size_t)2 * NHC * 64], g_wpadl[(size_t)2 * NHC * 64];

// ---------------- helpers ----------------
__device__ __forceinline__ int   f2ord(float f){ int i = __float_as_int(f); return i >= 0 ? i : i ^ 0x7fffffff; }
__device__ __forceinline__ float ord2f(int k){ return __int_as_float(k >= 0 ? k : k ^ 0x7fffffff); }
__device__ __forceinline__ float sigmf(float x){ return 1.f / (1.f + expf(-x)); }
__device__ __forceinline__ void f2hl(float v, __nv_bfloat16* H, __nv_bfloat16* L, size_t i){
    __nv_bfloat16 h = __float2bfloat16(v);
    H[i] = h; L[i] = __float2bfloat16(v - __bfloat162float(h));
}
__device__ __forceinline__ uint32_t smem_u32(const void* p){
    uint32_t a;
    asm("{ .reg .u64 t; cvta.to.shared.u64 t, %1; cvt.u32.u64 %0, t; }" : "=r"(a) : "l"(p));
    return a;
}
__device__ __forceinline__ void ldm_x4(uint32_t* r, uint32_t addr){
    asm volatile("ldmatrix.sync.aligned.m8n8.x4.shared.b16 {%0,%1,%2,%3}, [%4];"
        : "=r"(r[0]), "=r"(r[1]), "=r"(r[2]), "=r"(r[3]) : "r"(addr));
}
__device__ __forceinline__ void ldm_x2(uint32_t* r, uint32_t addr){
    asm volatile("ldmatrix.sync.aligned.m8n8.x2.shared.b16 {%0,%1}, [%2];"
        : "=r"(r[0]), "=r"(r[1]) : "r"(addr));
}
__device__ __forceinline__ void mma_bf16(float* c, const uint32_t* a, const uint32_t* b){
    asm volatile("mma.sync.aligned.m16n8k16.row.col.f32.bf16.bf16.f32 "
        "{%0,%1,%2,%3}, {%4,%5,%6,%7}, {%8,%9}, {%0,%1,%2,%3};"
        : "+f"(c[0]), "+f"(c[1]), "+f"(c[2]), "+f"(c[3])
        : "r"(a[0]), "r"(a[1]), "r"(a[2]), "r"(a[3]), "r"(b[0]), "r"(b[1]));
}
__device__ __forceinline__ void cpa16(uint32_t saddr, const void* g){
    asm volatile("cp.async.ca.shared.global [%0], [%1], 16;" :: "r"(saddr), "l"(g));
}
__device__ __forceinline__ void cpa_commit(){ asm volatile("cp.async.commit_group;" ::: "memory"); }
__device__ __forceinline__ void splitpack(float a, float b, uint32_t& hi, uint32_t& lo){
    __nv_bfloat16 ha = __float2bfloat16(a), hb = __float2bfloat16(b);
    __nv_bfloat16 la = __float2bfloat16(a - __bfloat162float(ha));
    __nv_bfloat16 lb = __float2bfloat16(b - __bfloat162float(hb));
    hi = ((uint32_t)__bfloat16_as_ushort(hb) << 16) | (uint32_t)__bfloat16_as_ushort(ha);
    lo = ((uint32_t)__bfloat16_as_ushort(lb) << 16) | (uint32_t)__bfloat16_as_ushort(la);
}

// ================= setup =================
__global__ void k_initmean(const float* __restrict__ ea_t, const float* __restrict__ ea_c){
    int idx = blockIdx.x * 256 + threadIdx.x, stride = gridDim.x * 256;
    int mi = f2ord(-FLT_MAX);
    for (int i = idx; i < NNODE * NH; i += stride){
        g_mx[0][i] = mi; g_mx[1][i] = mi;
        g_as[0][i] = 0.f; g_as[1][i] = 0.f;
        g_ad[0][i] = 0.f; g_ad[1][i] = 0.f;
    }
    for (int i = idx; i < NNODE; i += stride){
        g_cnt[0][i] = 0; g_cnt[1][i] = 0;
        g_cur[0][i] = 0; g_cur[1][i] = 0;
    }
    __shared__ float s0[256], s1[256];
    float a = 0.f, b = 0.f;
    for (int i = blockIdx.x * 256 + threadIdx.x; i < NE; i += 128 * 256){ a += ea_t[i]; b += ea_c[i]; }
    s0[threadIdx.x] = a; s1[threadIdx.x] = b; __syncthreads();
    for (int s = 128; s; s >>= 1){
        if (threadIdx.x < s){ s0[threadIdx.x] += s0[threadIdx.x+s]; s1[threadIdx.x] += s1[threadIdx.x+s]; }
        __syncthreads();
    }
    if (!threadIdx.x){ g_part[0][blockIdx.x] = s0[0]; g_part[1][blockIdx.x] = s1[0]; }
}

__global__ void k_setup(const float* __restrict__ We_t, const float* __restrict__ ae_t,
                        const float* __restrict__ We_c, const float* __restrict__ ae_c,
                        const float* __restrict__ bih,  const float* __restrict__ bhh){
    __shared__ float sh[256];
    int tid = threadIdx.x;
    for (int g = 0; g < 2; g++){
        sh[tid] = (tid < 128) ? g_part[g][tid] : 0.f;
        __syncthreads();
        for (int s = 128; s; s >>= 1){ if (tid < s) sh[tid] += sh[tid+s]; __syncthreads(); }
        if (!tid) g_mean[g] = sh[0] / (float)NE;
        __syncthreads();
    }
    int wid = tid >> 5, lane = tid & 31;
    for (int c = wid; c < 16; c += 8){
        int g = c >> 3, h = c & 7;
        const float* We = g ? We_c : We_t;
        const float* ae = g ? ae_c : ae_t;
        float s = 0.f;
        for (int i = lane; i < NC; i += 32) s = fmaf(We[h*NC + i], ae[h*NC + i], s);
        for (int o = 16; o; o >>= 1) s += __shfl_down_sync(0xffffffffu, s, o);
        if (!lane) g_ce[g][h] = s;
    }
    for (int j = tid; j < 1024; j += 256) g_big[OFF_BSUM + j] = bih[j] + bhh[j];
}

#define CW0 2097152
#define CW1 (CW0 + 196608)
#define CW2 (CW1 + 65536)
#define CW3 (CW2 + 131072)
#define CW4 (CW3 + 32768)
#define CW5 (CW4 + NNODE * 64)
#define CW6 (CW5 + 2 * NHC * 64)
__global__ void k_convall(const float* __restrict__ w0, const float* __restrict__ w1,
                          const float* __restrict__ w2, const float* __restrict__ w3,
                          const float* __restrict__ w4, const float* __restrict__ x,
                          const float* __restrict__ W_t, const float* __restrict__ W_c){
    int i = blockIdx.x * 256 + threadIdx.x;
    if (i < CW0)      f2hl(w0[i], g_wihh, g_wihl, i);
    else if (i < CW1) f2hl(w1[i - CW0], g_inwh, g_inwl, i - CW0);
    else if (i < CW2) f2hl(w2[i - CW1], g_mowh, g_mowl, i - CW1);
    else if (i < CW3) f2hl(w3[i - CW2], g_fuwh, g_fuwl, i - CW2);
    else if (i < CW4) f2hl(w4[i - CW3], g_owh, g_owl, i - CW3);
    else if (i < CW5){
        int j = i - CW4; int n = j >> 6, k = j & 63;
        float v = (k < NIN) ? x[n * NIN + k] : 0.f;
        f2hl(v, g_xpadh, g_xpadl, j);
    } else if (i < CW6){
        int j = i - CW5; int g = j >> 17; int r = j & 131071;
        int n = r >> 6, k = r & 63;
        const float* W = g ? W_c : W_t;
        float v = (k < NIN) ? W[k * NHC + n] : 0.f;
        f2hl(v, g_wpadh, g_wpadl, j);
    }
}

// ================= GAT edge pipeline =================
__global__ void k_count(const int* __restrict__ dst_t, const int* __restrict__ dst_c){
    int g = blockIdx.y;
    const int* dst = g ? dst_c : dst_t;
    int e = blockIdx.x * 256 + threadIdx.x;
    if (e < NE) atomicAdd(&g_cnt[g][dst[e]], 1);
}

__global__ void k_scan(){
    int g = blockIdx.x, tid = threadIdx.x;
    __shared__ int sh[1024];
    int base = tid * 4;
    int c0 = g_cnt[g][base], c1 = g_cnt[g][base+1], c2 = g_cnt[g][base+2], c3 = g_cnt[g][base+3];
    int s = c0 + c1 + c2 + c3;
    sh[tid] = s; __syncthreads();
    for (int off = 1; off < 1024; off <<= 1){
        int v = (tid >= off) ? sh[tid - off] : 0;
        __syncthreads();
        sh[tid] += v;
        __syncthreads();
    }
    int excl = sh[tid] - s;
    g_start[g][base]   = excl;
    g_start[g][base+1] = excl + c0;
    g_start[g][base+2] = excl + c0 + c1;
    g_start[g][base+3] = excl + c0 + c1 + c2;
}

__global__ void k_scatalpha(const int* __restrict__ src_t, const int* __restrict__ dst_t, const float* __restrict__ ea_t,
                            const int* __restrict__ src_c, const int* __restrict__ dst_c, const float* __restrict__ ea_c){
    int g = blockIdx.y;
    const int* src = g ? src_c : src_t;
    const int* dst = g ? dst_c : dst_t;
    const float* ea = g ? ea_c : ea_t;
    int e = blockIdx.x * 256 + threadIdx.x;
    if (e >= NEP) return;
    int s, d; float av;
    if (e < NE){
        s = src[e]; d = dst[e]; av = ea[e];
        int pos = g_start[g][d] + atomicAdd(&g_cur[g][d], 1);
        g_sorted[g][pos] = e;
    } else { s = d = e - NE; av = g_mean[g]; }
#pragma unroll
    for (int h = 0; h < NH; h++){
        float al = g_as[g][s*NH + h] + g_ad[g][d*NH + h] + av * g_ce[g][h];
        al = al > 0.f ? al : 0.2f * al;
        g_w[g][(size_t)e * NH + h] = al;
        atomicMax(&g_mx[g][d*NH + h], f2ord(al));
    }
}

// fused: exp + denominator + weighted aggregation
__global__ void __launch_bounds__(256) k_agg(const int* __restrict__ src_t, const int* __restrict__ src_c,
                                             const float* __restrict__ b_t, const float* __restrict__ b_c){
    int g = blockIdx.y;
    const int* src = g ? src_c : src_t;
    const float* bias = g ? b_c : b_t;
    int n = blockIdx.x, t = threadIdx.x;
    const float* xp = g_xp[g];
    const float* w  = g_w[g];

    __shared__ float smx[NH];
    __shared__ int   ssrc[32];
    __shared__ float sw[32][NH];
    if (t < NH) smx[t] = ord2f(g_mx[g][n*NH + t]);
    __syncthreads();

    float acc[NH], den[NH];
    {
        size_t e = (size_t)(NE + n) * NH;
        const float* xr = xp + (size_t)n * NHC + t;
#pragma unroll
        for (int h = 0; h < NH; h++){
            float exs = expf(w[e + h] - smx[h]);
            acc[h] = exs * xr[h * NC];
            den[h] = exs;
        }
    }
    int st = g_start[g][n], c = g_cnt[g][n];
    for (int i0 = 0; i0 < c; i0 += 32){
        int m = min(32, c - i0);
        __syncthreads();
        if (t < m) ssrc[t] = src[g_sorted[g][st + i0 + t]];
        {
            int j = t >> 3, h = t & 7;
            if (j < m) sw[j][h] = expf(w[(size_t)g_sorted[g][st + i0 + j] * NH + h] - smx[h]);
        }
        __syncthreads();
        int jj = 0;
        for (; jj + 4 <= m; jj += 4){
            const float* x0 = xp + (size_t)ssrc[jj+0] * NHC + t;
            const float* x1 = xp + (size_t)ssrc[jj+1] * NHC + t;
            const float* x2 = xp + (size_t)ssrc[jj+2] * NHC + t;
            const float* x3 = xp + (size_t)ssrc[jj+3] * NHC + t;
            float v0[NH], v1[NH], v2[NH], v3[NH];
#pragma unroll
            for (int h = 0; h < NH; h++){ v0[h] = x0[h*NC]; v1[h] = x1[h*NC]; v2[h] = x2[h*NC]; v3[h] = x3[h*NC]; }
#pragma unroll
            for (int h = 0; h < NH; h++){
                float w0 = sw[jj+0][h], w1 = sw[jj+1][h], w2 = sw[jj+2][h], w3 = sw[jj+3][h];
                acc[h] = fmaf(w0, v0[h], acc[h]);
                acc[h] = fmaf(w1, v1[h], acc[h]);
                acc[h] = fmaf(w2, v2[h], acc[h]);
                acc[h] = fmaf(w3, v3[h], acc[h]);
                den[h] += (w0 + w1) + (w2 + w3);
            }
        }
        for (; jj < m; jj++){
            const float* xr = xp + (size_t)ssrc[jj] * NHC + t;
#pragma unroll
            for (int h = 0; h < NH; h++){
                float ww = sw[jj][h];
                acc[h] = fmaf(ww, xr[h * NC], acc[h]);
                den[h] += ww;
            }
        }
    }
    if (g == 0){
#pragma unroll
        for (int h = 0; h < NH; h++){
            float v = acc[h] / (den[h] + 1e-16f) + bias[h * NC + t];
            f2hl(v, g_hth, g_htl, (size_t)n * NHC + h * NC + t);
        }
    } else {
        float s = 0.f;
#pragma unroll
        for (int h = 0; h < NH; h++) s += acc[h] / (den[h] + 1e-16f);
        f2hl(s * 0.125f + bias[t], g_hch, g_hcl, (size_t)n * NC + t);
    }
}

// ================= HMMA bf16x3 GEMM core =================
struct GA {
    const __nv_bfloat16 *Ah, *Al, *Bh, *Bl;
    float* C;
    __nv_bfloat16 *Ch, *Cl;
    const float* bias;
    const float *pas, *pad;
    float *oas, *oad;
    int lda, ldb, ldc, ldc2, c2off, K, act, gx;
    float alpha;
};

__device__ __forceinline__ void gemm_core(const GA a, int row0, int col0){
    extern __shared__ char sm[];
    int tid = threadIdx.x, lane = tid & 31, wid = tid >> 5;
    int wm = wid & 3, wn = wid >> 2;
    const __nv_bfloat16* Ah = a.Ah + (size_t)row0 * a.lda;
    const __nv_bfloat16* Al = a.Al + (size_t)row0 * a.lda;
    const __nv_bfloat16* Bh = a.Bh + (size_t)col0 * a.ldb;
    const __nv_bfloat16* Bl = a.Bl + (size_t)col0 * a.ldb;

    uint32_t sbase = smem_u32(sm);
    int nkb = a.K >> 6;

    auto issue = [&](int kb, int st){
        uint32_t su = sbase + st * 49152;
        int k0 = kb << 6;
#pragma unroll
        for (int it = 0; it < 4; it++){
            int i = tid + it * 256;
            int row = i >> 3, seg = i & 7;
            size_t goff = (size_t)row * a.lda + k0 + seg * 8;
            uint32_t so = row * 128 + ((seg ^ (row & 7)) << 4);
            cpa16(su + so,         Ah + goff);
            cpa16(su + 16384 + so, Al + goff);
        }
#pragma unroll
        for (int it = 0; it < 2; it++){
            int i = tid + it * 256;
            int row = i >> 3, seg = i & 7;
            size_t goff = (size_t)row * a.ldb + k0 + seg * 8;
            uint32_t so = row * 128 + ((seg ^ (row & 7)) << 4);
            cpa16(su + 32768 + so, Bh + goff);
            cpa16(su + 40960 + so, Bl + goff);
        }
        cpa_commit();
    };

    issue(0, 0);
    if (nkb > 1) issue(1, 1);

    float acc[2][4][4] = {};
    for (int kb = 0; kb < nkb; kb++){
        if (kb + 1 < nkb) asm volatile("cp.async.wait_group 1;" ::: "memory");
        else              asm volatile("cp.async.wait_group 0;" ::: "memory");
        __syncthreads();
        uint32_t sb2 = sbase + (kb & 1) * 49152;
#pragma unroll
        for (int ks = 0; ks < 4; ks++){
            uint32_t a_h[2][4], a_l[2][4], b_h[4][2], b_l[4][2];
#pragma unroll
            for (int mt = 0; mt < 2; mt++){
                int r = wm * 32 + mt * 16 + (lane & 15);
                int seg = ks * 2 + (lane >> 4);
                uint32_t ad = sb2 + r * 128 + ((seg ^ (r & 7)) << 4);
                ldm_x4(a_h[mt], ad);
                ldm_x4(a_l[mt], ad + 16384);
            }
#pragma unroll
            for (int nt = 0; nt < 4; nt++){
                int r = wn * 32 + nt * 8 + (lane & 7);
                int seg = ks * 2 + ((lane >> 3) & 1);
                uint32_t bd = sb2 + 32768 + r * 128 + ((seg ^ (r & 7)) << 4);
                ldm_x2(b_h[nt], bd);
                ldm_x2(b_l[nt], bd + 8192);
            }
#pragma unroll
            for (int mt = 0; mt < 2; mt++)
#pragma unroll
                for (int nt = 0; nt < 4; nt++){
                    mma_bf16(acc[mt][nt], a_h[mt], b_h[nt]);
                    mma_bf16(acc[mt][nt], a_h[mt], b_l[nt]);
                    mma_bf16(acc[mt][nt], a_l[mt], b_h[nt]);
                }
        }
        __syncthreads();
        if (kb + 2 < nkb) issue(kb + 2, kb & 1);
    }

    float s1[4] = {}, s2[4] = {};
    int h = col0 >> 8;
#pragma unroll
    for (int mt = 0; mt < 2; mt++){
#pragma unroll
        for (int nt = 0; nt < 4; nt++){
            int r0 = row0 + wm * 32 + mt * 16 + (lane >> 2);
            int c0 = col0 + wn * 32 + nt * 8 + ((lane & 3) << 1);
#pragma unroll
            for (int q = 0; q < 4; q++){
                int r = r0 + (q >> 1) * 8;
                int cc = c0 + (q & 1);
                float v = acc[mt][nt][q] * a.alpha;
                if (a.bias) v += a.bias[cc];
                if (a.act == 1) v = fmaxf(v, 0.f);
                if (a.C) a.C[(size_t)r * a.ldc + cc] = v;
                if (a.Ch) f2hl(v, a.Ch, a.Cl, (size_t)r * a.ldc2 + a.c2off + cc);
                if (a.pas){
                    int ridx = mt * 2 + (q >> 1);
                    int ci = h * 256 + (cc & 255);
                    s1[ridx] = fmaf(v, a.pas[ci], s1[ridx]);
                    s2[ridx] = fmaf(v, a.pad[ci], s2[ridx]);
                }
            }
        }
    }
    if (a.pas){
#pragma unroll
        for (int i = 0; i < 4; i++){
            s1[i] += __shfl_xor_sync(~0u, s1[i], 1); s1[i] += __shfl_xor_sync(~0u, s1[i], 2);
            s2[i] += __shfl_xor_sync(~0u, s2[i], 1); s2[i] += __shfl_xor_sync(~0u, s2[i], 2);
        }
        if ((lane & 3) == 0){
#pragma unroll
            for (int i = 0; i < 4; i++){
                int mt = i >> 1, rr = i & 1;
                int r = row0 + wm * 32 + mt * 16 + (lane >> 2) + rr * 8;
                atomicAdd(&a.oas[r * NH + h], s1[i]);
                atomicAdd(&a.oad[r * NH + h], s2[i]);
            }
        }
    }
}

__global__ void __launch_bounds__(256) mma_single(GA a){
    if ((int)blockIdx.x >= a.gx) return;
    gemm_core(a, blockIdx.y * 128, blockIdx.x * 64);
}
__global__ void __launch_bounds__(256) mma_dual(GA a0, GA a1){
    GA a = blockIdx.z ? a1 : a0;
    if ((int)blockIdx.x >= a.gx) return;
    gemm_core(a, blockIdx.y * 128, blockIdx.x * 64);
}

// ================= flash attention body (split-KV) =================
__device__ void flash_body(
    const __nv_bfloat16* __restrict__ qkvh, const __nv_bfloat16* __restrict__ qkvl,
    const __nv_bfloat16* __restrict__ vth, const __nv_bfloat16* __restrict__ vtl,
    float* __restrict__ pO, float* __restrict__ pML,
    int row0, int head, int z)
{
    extern __shared__ char sm[];
    int tid = threadIdx.x, lane = tid & 31, wid = tid >> 5;
    int kv0 = z * 2048;
    uint32_t sb = smem_u32(sm);

    const __nv_bfloat16* Qh = qkvh + (size_t)row0 * 768 + head * 64;
    const __nv_bfloat16* Ql = qkvl + (size_t)row0 * 768 + head * 64;
    const __nv_bfloat16* Kh = qkvh + 256 + head * 64;
    const __nv_bfloat16* Kl = qkvl + 256 + head * 64;
    const __nv_bfloat16* Vh = vth + (size_t)head * 64 * 4096;
    const __nv_bfloat16* Vl = vtl + (size_t)head * 64 * 4096;

#pragma unroll
    for (int it = 0; it < 4; it++){
        int i = tid + it * 256;
        int r = i >> 3, seg = i & 7;
        uint32_t so = r * 128 + ((seg ^ (r & 7)) << 4);
        cpa16(sb + so,         Qh + (size_t)r * 768 + seg * 8);
        cpa16(sb + 16384 + so, Ql + (size_t)r * 768 + seg * 8);
    }
#pragma unroll
    for (int it = 0; it < 2; it++){
        int i = tid + it * 256;
        int r = i >> 3, seg = i & 7;
        uint32_t so = r * 128 + ((seg ^ (r & 7)) << 4);
        cpa16(sb + 32768 + so,         Kh + (size_t)(kv0 + r) * 768 + seg * 8);
        cpa16(sb + 32768 + 8192 + so,  Kl + (size_t)(kv0 + r) * 768 + seg * 8);
        cpa16(sb + 32768 + 16384 + so, Vh + (size_t)r * 4096 + kv0 + seg * 8);
        cpa16(sb + 32768 + 24576 + so, Vl + (size_t)r * 4096 + kv0 + seg * 8);
    }
    cpa_commit();
    asm volatile("cp.async.wait_group 0;" ::: "memory");
    __syncthreads();

    uint32_t qf_h[4][4], qf_l[4][4];
#pragma unroll
    for (int ks = 0; ks < 4; ks++){
        int r = wid * 16 + (lane & 15);
        int seg = ks * 2 + (lane >> 4);
        uint32_t ad = sb + r * 128 + ((seg ^ (r & 7)) << 4);
        ldm_x4(qf_h[ks], ad);
        ldm_x4(qf_l[ks], ad + 16384);
    }

    float m0 = -1e30f, m1 = -1e30f, l0 = 0.f, l1 = 0.f;
    float acc_o[8][4] = {};
    int buf = 0;

    for (int kt = 0; kt < 32; kt++){
        if (kt < 31){
            uint32_t bo = sb + 32768 + (buf ^ 1) * 32768;
            int key0 = kv0 + (kt + 1) * 64;
#pragma unroll
            for (int it = 0; it < 2; it++){
                int i = tid + it * 256;
                int r = i >> 3, seg = i & 7;
                uint32_t so = r * 128 + ((seg ^ (r & 7)) << 4);
                cpa16(bo + so,         Kh + (size_t)(key0 + r) * 768 + seg * 8);
                cpa16(bo + 8192 + so,  Kl + (size_t)(key0 + r) * 768 + seg * 8);
                cpa16(bo + 16384 + so, Vh + (size_t)r * 4096 + key0 + seg * 8);
                cpa16(bo + 24576 + so, Vl + (size_t)r * 4096 + key0 + seg * 8);
            }
            cpa_commit();
            asm volatile("cp.async.wait_group 1;" ::: "memory");
        } else {
            asm volatile("cp.async.wait_group 0;" ::: "memory");
        }
        __syncthreads();

        uint32_t kb = sb + 32768 + buf * 32768;

        float acc_s[8][4] = {};
#pragma unroll
        for (int ks = 0; ks < 4; ks++){
            uint32_t bh[8][2], bl[8][2];
#pragma unroll
            for (int nt = 0; nt < 8; nt++){
                int r = nt * 8 + (lane & 7);
                int seg = ks * 2 + ((lane >> 3) & 1);
                uint32_t bd = kb + r * 128 + ((seg ^ (r & 7)) << 4);
                ldm_x2(bh[nt], bd);
                ldm_x2(bl[nt], bd + 8192);
            }
#pragma unroll
            for (int nt = 0; nt < 8; nt++){
                mma_bf16(acc_s[nt], qf_h[ks], bh[nt]);
                mma_bf16(acc_s[nt], qf_h[ks], bl[nt]);
                mma_bf16(acc_s[nt], qf_l[ks], bh[nt]);
            }
        }
#pragma unroll
        for (int nt = 0; nt < 8; nt++){
            acc_s[nt][0] *= 0.125f; acc_s[nt][1] *= 0.125f;
            acc_s[nt][2] *= 0.125f; acc_s[nt][3] *= 0.125f;
        }

        float tm0 = -1e30f, tm1 = -1e30f;
#pragma unroll
        for (int nt = 0; nt < 8; nt++){
            tm0 = fmaxf(tm0, fmaxf(acc_s[nt][0], acc_s[nt][1]));
            tm1 = fmaxf(tm1, fmaxf(acc_s[nt][2], acc_s[nt][3]));
        }
        tm0 = fmaxf(tm0, __shfl_xor_sync(~0u, tm0, 1)); tm0 = fmaxf(tm0, __shfl_xor_sync(~0u, tm0, 2));
        tm1 = fmaxf(tm1, __shfl_xor_sync(~0u, tm1, 1)); tm1 = fmaxf(tm1, __shfl_xor_sync(~0u, tm1, 2));
        float mn0 = fmaxf(m0, tm0), mn1 = fmaxf(m1, tm1);
        float sc0 = __expf(m0 - mn0), sc1 = __expf(m1 - mn1);
        m0 = mn0; m1 = mn1;
        l0 *= sc0; l1 *= sc1;
#pragma unroll
        for (int nt = 0; nt < 8; nt++){
            acc_o[nt][0] *= sc0; acc_o[nt][1] *= sc0;
            acc_o[nt][2] *= sc1; acc_o[nt][3] *= sc1;
        }
        float rs0 = 0.f, rs1 = 0.f;
        uint32_t pa_h[4][4], pa_l[4][4];
#pragma unroll
        for (int nt = 0; nt < 8; nt++){
            float p0 = __expf(acc_s[nt][0] - mn0), p1 = __expf(acc_s[nt][1] - mn0);
            float p2 = __expf(acc_s[nt][2] - mn1), p3 = __expf(acc_s[nt][3] - mn1);
            rs0 += p0 + p1; rs1 += p2 + p3;
            int k2 = nt >> 1;
            if (!(nt & 1)){
                splitpack(p0, p1, pa_h[k2][0], pa_l[k2][0]);
                splitpack(p2, p3, pa_h[k2][1], pa_l[k2][1]);
            } else {
                splitpack(p0, p1, pa_h[k2][2], pa_l[k2][2]);
                splitpack(p2, p3, pa_h[k2][3], pa_l[k2][3]);
            }
        }
        rs0 += __shfl_xor_sync(~0u, rs0, 1); rs0 += __shfl_xor_sync(~0u, rs0, 2);
        rs1 += __shfl_xor_sync(~0u, rs1, 1); rs1 += __shfl_xor_sync(~0u, rs1, 2);
        l0 += rs0; l1 += rs1;

        uint32_t vb = kb + 16384;
#pragma unroll
        for (int k2 = 0; k2 < 4; k2++){
            uint32_t vh[8][2], vl[8][2];
#pragma unroll
            for (int nt = 0; nt < 8; nt++){
                int r = nt * 8 + (lane & 7);
                int seg = k2 * 2 + ((lane >> 3) & 1);
                uint32_t vd = vb + r * 128 + ((seg ^ (r & 7)) << 4);
                ldm_x2(vh[nt], vd);
                ldm_x2(vl[nt], vd + 8192);
            }
#pragma unroll
            for (int nt = 0; nt < 8; nt++){
                mma_bf16(acc_o[nt], pa_h[k2], vh[nt]);
                mma_bf16(acc_o[nt], pa_h[k2], vl[nt]);
                mma_bf16(acc_o[nt], pa_l[k2], vh[nt]);
            }
        }
        __syncthreads();
        buf ^= 1;
    }

    int r = row0 + wid * 16 + (lane >> 2);
    size_t ro0 = ((size_t)z * NNODE + r) * 256;
    size_t ro1 = ((size_t)z * NNODE + r + 8) * 256;
#pragma unroll
    for (int nt = 0; nt < 8; nt++){
        int cc = head * 64 + nt * 8 + ((lane & 3) << 1);
        pO[ro0 + cc]     = acc_o[nt][0];
        pO[ro0 + cc + 1] = acc_o[nt][1];
        pO[ro1 + cc]     = acc_o[nt][2];
        pO[ro1 + cc + 1] = acc_o[nt][3];
    }
    if ((lane & 3) == 0){
        pML[((size_t)z * NNODE + r) * 8 + head * 2]     = m0;
        pML[((size_t)z * NNODE + r) * 8 + head * 2 + 1] = l0;
        pML[((size_t)z * NNODE + r + 8) * 8 + head * 2]     = m1;
        pML[((size_t)z * NNODE + r + 8) * 8 + head * 2 + 1] = l1;
    }
}

// combo: blocks 0..255 = flash (32 rowtiles x 4 heads x 2 splits); 256..767 = LSTM-gates GEMM
__global__ void __launch_bounds__(256) k_combo(
    GA a,
    const __nv_bfloat16* __restrict__ qkvh, const __nv_bfloat16* __restrict__ qkvl,
    const __nv_bfloat16* __restrict__ vth, const __nv_bfloat16* __restrict__ vtl,
    float* __restrict__ pO, float* __restrict__ pML)
{
    int bx = blockIdx.x;
    if (bx < 256){
        int row0 = (bx & 31) * 128;
        int head = (bx >> 5) & 3;
        int z = bx >> 7;
        flash_body(qkvh, qkvl, vth, vtl, pO, pML, row0, head, z);
    } else {
        int idx = bx - 256;
        gemm_core(a, (idx >> 4) * 128, (idx & 15) * 64);
    }
}

// ================= pointwise =================
__global__ void k_vt(const __nv_bfloat16* __restrict__ qh, const __nv_bfloat16* __restrict__ ql,
                     __nv_bfloat16* __restrict__ vh, __nv_bfloat16* __restrict__ vl){
    int idx = blockIdx.x * 256 + threadIdx.x;
    int hd = idx >> 12, n = idx & 4095;
    size_t s = (size_t)n * 768 + 512 + hd;
    vh[idx] = qh[s]; vl[idx] = ql[s];
}

// fused: flash merge (blocks 0..4095) + lstm pointwise (blocks 4096..8191)
__global__ void k_mergelstm(const float* __restrict__ pO, const float* __restrict__ pML,
                            __nv_bfloat16* __restrict__ Oh, __nv_bfloat16* __restrict__ Ol,
                            const float* __restrict__ G, float* __restrict__ ht_out){
    int b = blockIdx.x;
    if (b < NNODE){
        int row = b, col = threadIdx.x;
        int head = col >> 6;
        float m0 = pML[(size_t)row * 8 + head * 2],            l0 = pML[(size_t)row * 8 + head * 2 + 1];
        float m1 = pML[((size_t)NNODE + row) * 8 + head * 2],  l1 = pML[((size_t)NNODE + row) * 8 + head * 2 + 1];
        float mx = fmaxf(m0, m1);
        float w0 = __expf(m0 - mx), w1 = __expf(m1 - mx);
        float num = pO[(size_t)row * 256 + col] * w0 + pO[((size_t)NNODE + row) * 256 + col] * w1;
        float den = l0 * w0 + l1 * w1;
        f2hl(num / den, Oh, Ol, (size_t)row * 256 + col);
    } else {
        int idx = (b - NNODE) * 256 + threadIdx.x;
        int n = idx >> 8, j = idx & 255;
        const float* gr = G + (size_t)n * 1024;
        float ig = gr[j], gg = gr[512 + j], og = gr[768 + j];
        float cc = sigmf(ig) * tanhf(gg);
        float hv = sigmf(og) * tanhf(cc);
        ht_out[idx] = hv;
        f2hl(hv, g_hcath, g_hcatl, (size_t)n * 512 + j);
    }
}

// ================= launch =================
#define SYMADDR(p, s) do { void* _t; cudaGetSymbolAddress(&_t, s); p = (decltype(p))_t; } while(0)

extern "C" void kernel_launch(void* const* d_in, const int* in_sizes, int n_in,
                              void* d_out, int out_size) {
    const float* x     = (const float*)d_in[0];
    const int*   ei_t  = (const int*)d_in[1];
    const int*   ei_c  = (const int*)d_in[2];
    const float* ea_t  = (const float*)d_in[3];
    const float* ea_c  = (const float*)d_in[4];
    const float* W_t   = (const float*)d_in[5];
    const float* asrc_t= (const float*)d_in[6];
    const float* adst_t= (const float*)d_in[7];
    const float* We_t  = (const float*)d_in[8];
    const float* ae_t  = (const float*)d_in[9];
    const float* b_t   = (const float*)d_in[10];
    const float* W_c   = (const float*)d_in[11];
    const float* asrc_c= (const float*)d_in[12];
    const float* adst_c= (const float*)d_in[13];
    const float* We_c  = (const float*)d_in[14];
    const float* ae_c  = (const float*)d_in[15];
    const float* b_c   = (const float*)d_in[16];
    const float* lstm_Wih = (const float*)d_in[17];
    const float* lstm_bih = (const float*)d_in[19];
    const float* lstm_bhh = (const float*)d_in[20];
    const float* mha_in_w  = (const float*)d_in[21];
    const float* mha_in_b  = (const float*)d_in[22];
    const float* mha_out_w = (const float*)d_in[23];
    const float* mha_out_b = (const float*)d_in[24];
    const float* fus_w = (const float*)d_in[25];
    const float* fus_b = (const float*)d_in[26];
    const float* out_w = (const float*)d_in[27];
    const float* out_b = (const float*)d_in[28];

    float* big; SYMADDR(big, g_big);
    float* po;  SYMADDR(po, g_po);
    float* pml; SYMADDR(pml, g_pml);
    float* xp0; SYMADDR(xp0, g_xp);
    float* xp1 = xp0 + (size_t)NNODE * NHC;
    float* as0; SYMADDR(as0, g_as);
    float* as1 = as0 + NNODE * NH;
    float* ad0; SYMADDR(ad0, g_ad);
    float* ad1 = ad0 + NNODE * NH;
    __nv_bfloat16 *hth, *htl, *hch, *hcl, *qkvh, *qkvl, *vth, *vtl;
    __nv_bfloat16 *attnh, *attnl, *hcath, *hcatl, *hfush, *hfusl;
    __nv_bfloat16 *wihh, *wihl, *inwh, *inwl, *mowh, *mowl, *fuwh, *fuwl, *owh, *owl;
    __nv_bfloat16 *xpadh, *xpadl, *wpadh, *wpadl;
    SYMADDR(hth, g_hth); SYMADDR(htl, g_htl); SYMADDR(hch, g_hch); SYMADDR(hcl, g_hcl);
    SYMADDR(qkvh, g_qkvh); SYMADDR(qkvl, g_qkvl); SYMADDR(vth, g_vth); SYMADDR(vtl, g_vtl);
    SYMADDR(attnh, g_attnh); SYMADDR(attnl, g_attnl);
    SYMADDR(hcath, g_hcath); SYMADDR(hcatl, g_hcatl);
    SYMADDR(hfush, g_hfush); SYMADDR(hfusl, g_hfusl);
    SYMADDR(wihh, g_wihh); SYMADDR(wihl, g_wihl);
    SYMADDR(inwh, g_inwh); SYMADDR(inwl, g_inwl);
    SYMADDR(mowh, g_mowh); SYMADDR(mowl, g_mowl);
    SYMADDR(fuwh, g_fuwh); SYMADDR(fuwl, g_fuwl);
    SYMADDR(owh, g_owh); SYMADDR(owl, g_owl);
    SYMADDR(xpadh, g_xpadh); SYMADDR(xpadl, g_xpadl);
    SYMADDR(wpadh, g_wpadh); SYMADDR(wpadl, g_wpadl);

    cudaFuncSetAttribute(k_combo, cudaFuncAttributeMaxDynamicSharedMemorySize, 98304);
    cudaFuncSetAttribute(mma_single, cudaFuncAttributeMaxDynamicSharedMemorySize, 98304);
    cudaFuncSetAttribute(mma_dual, cudaFuncAttributeMaxDynamicSharedMemorySize, 98304);
    const int DYN = 98304;

    float* out_main = (float*)d_out;
    float* out_ht   = out_main + (size_t)NNODE * NOUT;
    float* out_hc   = out_ht   + (size_t)NNODE * HID;

    const int* src_t = ei_t; const int* dst_t = ei_t + NE;
    const int* src_c = ei_c; const int* dst_c = ei_c + NE;
    int nepb = (NEP + 255) / 256, neb = (NE + 255) / 256;

    k_initmean<<<128, 256>>>(ea_t, ea_c);
    k_setup<<<1, 256>>>(We_t, ae_t, We_c, ae_c, lstm_bih, lstm_bhh);
    k_convall<<<(CW6 + 255) / 256, 256>>>(lstm_Wih, mha_in_w, mha_out_w, fus_w, out_w, x, W_t, W_c);

    k_count<<<dim3(neb, 2), 256>>>(dst_t, dst_c);
    k_scan<<<2, 1024>>>();

    // ---- xp GEMMs (tensor cores), a_s/a_d fused in epilogue ----
    {
        GA a0 = { xpadh, xpadl, wpadh, wpadl, xp0, nullptr, nullptr, nullptr,
                  asrc_t, adst_t, as0, ad0,
                  64, 64, NHC, 0, 0, 64, 0, 32, 1.f };
        GA a1 = { xpadh, xpadl, wpadh + (size_t)NHC * 64, wpadl + (size_t)NHC * 64, xp1,
                  nullptr, nullptr, nullptr,
                  asrc_c, adst_c, as1, ad1,
                  64, 64, NHC, 0, 0, 64, 0, 32, 1.f };
        mma_dual<<<dim3(32, 32, 2), 256, DYN>>>(a0, a1);
    }

    // ---- GAT edge pipeline ----
    k_scatalpha<<<dim3(nepb, 2), 256>>>(src_t, dst_t, ea_t, src_c, dst_c, ea_c);
    k_agg<<<dim3(NNODE, 2), 256>>>(src_t, src_c, b_t, b_c);

    // ---- qkv GEMM (4096x768x256) ----
    {
        GA a = { hch, hcl, inwh, inwl, nullptr, qkvh, qkvl, mha_in_b,
                 nullptr, nullptr, nullptr, nullptr,
                 256, 256, 0, 768, 0, 256, 0, 12, 1.f };
        mma_single<<<dim3(12, 32), 256, DYN>>>(a);
    }
    k_vt<<<(4*64*NNODE)/256, 256>>>(qkvh, qkvl, vth, vtl);

    // ---- combo: flash attention (256 CTAs) + LSTM gates GEMM (512 CTAs) overlapped ----
    {
        GA a = { hth, htl, wihh, wihl, big + OFF_G, nullptr, nullptr, big + OFF_BSUM,
                 nullptr, nullptr, nullptr, nullptr,
                 NHC, NHC, 1024, 0, 0, NHC, 0, 16, 1.f };
        k_combo<<<768, 256, DYN>>>(a, qkvh, qkvl, vth, vtl, po, pml);
    }

    // ---- merge flash partials + lstm pointwise (one launch) ----
    k_mergelstm<<<2 * NNODE, 256>>>(po, pml, attnh, attnl, big + OFF_G, out_ht);

    // ---- proj (4096x256x256) ----
    {
        GA a = { attnh, attnl, mowh, mowl, out_hc, hcath, hcatl, mha_out_b,
                 nullptr, nullptr, nullptr, nullptr,
                 256, 256, 256, 512, 256, 256, 0, 4, 1.f };
        mma_single<<<dim3(4, 32), 256, DYN>>>(a);
    }
    // ---- fusion relu (4096x256x512) ----
    {
        GA a = { hcath, hcatl, fuwh, fuwl, nullptr, hfush, hfusl, fus_b,
                 nullptr, nullptr, nullptr, nullptr,
                 512, 512, 0, 256, 0, 512, 1, 4, 1.f };
        mma_single<<<dim3(4, 32), 256, DYN>>>(a);
    }
    // ---- out (4096x128x256) ----
    {
        GA a = { hfush, hfusl, owh, owl, out_main, nullptr, nullptr, out_b,
                 nullptr, nullptr, nullptr, nullptr,
                 256, 256, NOUT, 0, 0, 256, 0, 2, 1.f };
        mma_single<<<dim3(2, 32), 256, DYN>>>(a);
    }
}